// round 6
// baseline (speedup 1.0000x reference)
#include <cuda_runtime.h>
#include <cuda_bf16.h>
#include <math.h>
#include <stdint.h>

// ---------------- problem constants ----------------
constexpr int B = 16, S = 512, D = 768, H = 12, FF = 3072, L = 4;
constexpr int DH = 64;
constexpr int NREL = 129;
constexpr float SCALE = 0.125f;
constexpr float LN_EPS = 1e-12f;

constexpr size_t BS   = (size_t)B * S;
constexpr size_t BSD  = BS * D;
constexpr size_t BHS  = (size_t)B * H * S;
constexpr size_t BHSS = BHS * S;

// ---------------- device scratch ----------------
__device__ float g_x[BSD];
__device__ float g_q[BSD];
__device__ float g_scores[BHSS];
__device__ float g_qtab[BHS * NREL];
__device__ float g_ptab[BHS * NREL];
__device__ float g_ctx[BSD];
__device__ float g_tmp[BSD];
__device__ float g_attn[BSD];
__device__ float g_table[NREL * DH];

constexpr size_t WSZ = (size_t)L * D * D;
constexpr size_t WFF = (size_t)L * FF * D;
__device__ __align__(256) __nv_bfloat16 g_wqh[WSZ], g_wql[WSZ];
__device__ __align__(256) __nv_bfloat16 g_wkh[WSZ], g_wkl[WSZ];
__device__ __align__(256) __nv_bfloat16 g_wvh[WSZ], g_wvl[WSZ];
__device__ __align__(256) __nv_bfloat16 g_woh[WSZ], g_wol[WSZ];
__device__ __align__(256) __nv_bfloat16 g_wih[WFF], g_wil[WFF];
__device__ __align__(256) __nv_bfloat16 g_wdh[WFF], g_wdl[WFF];
__device__ __align__(256) __nv_bfloat16 g_xh[BSD], g_xl[BSD];
__device__ __align__(256) __nv_bfloat16 g_qh[BSD], g_ql[BSD];
__device__ __align__(256) __nv_bfloat16 g_kh[BSD], g_kl[BSD];
__device__ __align__(256) __nv_bfloat16 g_vh[BSD], g_vl[BSD];
__device__ __align__(256) __nv_bfloat16 g_ah[BSD], g_al[BSD];
__device__ __align__(256) __nv_bfloat16 g_ffh[BS * FF], g_ffl[BS * FF];
__device__ __align__(256) __nv_bfloat16 g_ph[BHSS], g_pl[BHSS];

// ---------------- helpers ----------------
__device__ __forceinline__ float block_reduce_sum(float v, float* red) {
    int t = threadIdx.x;
    red[t] = v; __syncthreads();
    for (int o = 128; o > 0; o >>= 1) {
        if (t < o) red[t] += red[t + o];
        __syncthreads();
    }
    float r = red[0]; __syncthreads();
    return r;
}

__device__ __forceinline__ void split1(float v, __nv_bfloat16& h, __nv_bfloat16& l) {
    h = __float2bfloat16_rn(v);
    l = __float2bfloat16_rn(v - __bfloat162float(h));
}

__global__ void build_table(const float* __restrict__ rel, float* __restrict__ table) {
    int i = blockIdx.x * 256 + threadIdx.x;
    if (i < NREL * DH) {
        int r = i / DH, d = i % DH;
        table[i] = rel[((size_t)128 * S + (64 + r)) * DH + d];
    }
}

__global__ __launch_bounds__(256) void split_bf16(
    const float* __restrict__ in, __nv_bfloat16* __restrict__ hi,
    __nv_bfloat16* __restrict__ lo, int n4)
{
    int i = blockIdx.x * 256 + threadIdx.x;
    if (i >= n4) return;
    float4 v = ((const float4*)in)[i];
    __nv_bfloat16 h0, h1, h2, h3, l0, l1, l2, l3;
    split1(v.x, h0, l0); split1(v.y, h1, l1);
    split1(v.z, h2, l2); split1(v.w, h3, l3);
    __nv_bfloat162* hp = (__nv_bfloat162*)hi;
    __nv_bfloat162* lp = (__nv_bfloat162*)lo;
    hp[i * 2 + 0] = __nv_bfloat162(h0, h1);
    hp[i * 2 + 1] = __nv_bfloat162(h2, h3);
    lp[i * 2 + 0] = __nv_bfloat162(l0, l1);
    lp[i * 2 + 1] = __nv_bfloat162(l2, l3);
}

// ---------------- mma primitives ----------------
__device__ __forceinline__ void mma16816(float* d, const uint32_t* a, const uint32_t* b) {
    asm volatile(
        "mma.sync.aligned.m16n8k16.row.col.f32.bf16.bf16.f32 "
        "{%0,%1,%2,%3}, {%4,%5,%6,%7}, {%8,%9}, {%0,%1,%2,%3};\n"
        : "+f"(d[0]), "+f"(d[1]), "+f"(d[2]), "+f"(d[3])
        : "r"(a[0]), "r"(a[1]), "r"(a[2]), "r"(a[3]), "r"(b[0]), "r"(b[1]));
}
__device__ __forceinline__ void ldsm4(uint32_t* r, uint32_t addr) {
    asm volatile("ldmatrix.sync.aligned.m8n8.x4.shared.b16 {%0,%1,%2,%3}, [%4];\n"
        : "=r"(r[0]), "=r"(r[1]), "=r"(r[2]), "=r"(r[3]) : "r"(addr));
}
__device__ __forceinline__ void ldsm4t(uint32_t* r, uint32_t addr) {
    asm volatile("ldmatrix.sync.aligned.m8n8.x4.trans.shared.b16 {%0,%1,%2,%3}, [%4];\n"
        : "=r"(r[0]), "=r"(r[1]), "=r"(r[2]), "=r"(r[3]) : "r"(addr));
}
__device__ __forceinline__ void cp16(uint32_t dst, const void* src) {
    asm volatile("cp.async.cg.shared.global [%0], [%1], 16;\n" :: "r"(dst), "l"(src));
}
__device__ __forceinline__ void cp_commit() { asm volatile("cp.async.commit_group;\n"); }
__device__ __forceinline__ void cp_wait1() { asm volatile("cp.async.wait_group 1;\n" ::: "memory"); }
__device__ __forceinline__ uint32_t smem_u32(const void* p) {
    return (uint32_t)__cvta_generic_to_shared(p);
}

// ======================================================================
// Pipelined split-bf16 MMA GEMM NT, k-tile 32, 3 stages, 1 sync/k-tile.
// C = (Ah+Al)(Wh+Wl)^T, 128x128 block, 8 warps (2m x 4n).
// Stage layout: 4 arrays (Ah,Al,Wh,Wl), each 128 rows x stride-40 bf16.
// ======================================================================
constexpr int GSTR  = 40;                    // padded bf16 stride per row (32 data + 8 pad)
constexpr int ARRB2 = 128 * GSTR * 2;        // 10240 B per array
constexpr int STGB2 = 4 * ARRB2;             // 40960 B per stage
constexpr int NSTG2 = 3;
constexpr int PIPE2_SMEM = NSTG2 * STGB2;    // 122880 B

struct GemmTargets {
    const __nv_bfloat16* wh[3];
    const __nv_bfloat16* wl[3];
    const float* bias[3];
    const float* res[3];
    float* c[3];
    __nv_bfloat16* ch[3];
    __nv_bfloat16* cl[3];
};

__global__ __launch_bounds__(256) void gemm_mma_pipe(
    const __nv_bfloat16* __restrict__ Ah, const __nv_bfloat16* __restrict__ Al,
    GemmTargets tg, int M, int N, int K, int act)
{
    extern __shared__ __align__(16) char dsm[];
    const uint32_t sbase = smem_u32(dsm);
    const int z = blockIdx.z;
    const __nv_bfloat16* Wh = tg.wh[z];
    const __nv_bfloat16* Wl = tg.wl[z];

    const int bm = blockIdx.y * 128, bn = blockIdx.x * 128;
    const int t = threadIdx.x, lane = t & 31, w = t >> 5;
    const int wm = (w & 1) * 64, wn = (w >> 1) * 32;

    float acc[4][4][4];
    #pragma unroll
    for (int i = 0; i < 4; i++)
        #pragma unroll
        for (int j = 0; j < 4; j++)
            #pragma unroll
            for (int r = 0; r < 4; r++) acc[i][j][r] = 0.f;

    uint32_t aoff[4], boff[2];
    #pragma unroll
    for (int mi = 0; mi < 4; mi++)
        aoff[mi] = (uint32_t)(((wm + mi * 16 + (lane & 15)) * GSTR + ((lane >> 4) << 3)) * 2);
    #pragma unroll
    for (int ni2 = 0; ni2 < 2; ni2++)
        boff[ni2] = (uint32_t)(((wn + ni2 * 16 + (lane & 7) + ((lane >> 4) << 3)) * GSTR
                               + (((lane >> 3) & 1) << 3)) * 2);

    const int nk = K / 32;

    // load geometry: 512 16B-segments per array per stage; thread does 2/array
    const int seg0 = t, seg1 = t + 256;
    const int r0 = seg0 >> 2, c0 = seg0 & 3;
    const int r1 = seg1 >> 2, c1 = seg1 & 3;

    auto issue = [&](int c) {
        if (c < nk) {
            const uint32_t base = sbase + (c % NSTG2) * STGB2;
            const size_t k0 = (size_t)c * 32;
            size_t a0 = (size_t)(bm + r0) * K + k0 + c0 * 8;
            size_t a1 = (size_t)(bm + r1) * K + k0 + c1 * 8;
            size_t b0 = (size_t)(bn + r0) * K + k0 + c0 * 8;
            size_t b1 = (size_t)(bn + r1) * K + k0 + c1 * 8;
            uint32_t d0 = (uint32_t)(r0 * (GSTR * 2) + c0 * 16);
            uint32_t d1 = (uint32_t)(r1 * (GSTR * 2) + c1 * 16);
            cp16(base + 0 * ARRB2 + d0, Ah + a0);
            cp16(base + 0 * ARRB2 + d1, Ah + a1);
            cp16(base + 1 * ARRB2 + d0, Al + a0);
            cp16(base + 1 * ARRB2 + d1, Al + a1);
            cp16(base + 2 * ARRB2 + d0, Wh + b0);
            cp16(base + 2 * ARRB2 + d1, Wh + b1);
            cp16(base + 3 * ARRB2 + d0, Wl + b0);
            cp16(base + 3 * ARRB2 + d1, Wl + b1);
        }
        cp_commit();
    };

    issue(0);
    issue(1);

    for (int kt = 0; kt < nk; kt++) {
        cp_wait1();
        __syncthreads();
        issue(kt + 2);

        const uint32_t sb = sbase + (kt % NSTG2) * STGB2;
        #pragma unroll
        for (int kk2 = 0; kk2 < 2; kk2++) {
            const uint32_t ko = kk2 * 32;     // 16 bf16 = 32 bytes
            uint32_t ah[4][4], al[4][4], bh[4][2], bl[4][2];
            #pragma unroll
            for (int mi = 0; mi < 4; mi++) {
                ldsm4(ah[mi], sb + 0 * ARRB2 + aoff[mi] + ko);
                ldsm4(al[mi], sb + 1 * ARRB2 + aoff[mi] + ko);
            }
            #pragma unroll
            for (int ni2 = 0; ni2 < 2; ni2++) {
                uint32_t t4[4];
                ldsm4(t4, sb + 2 * ARRB2 + boff[ni2] + ko);
                bh[ni2 * 2][0] = t4[0]; bh[ni2 * 2][1] = t4[1];
                bh[ni2 * 2 + 1][0] = t4[2]; bh[ni2 * 2 + 1][1] = t4[3];
                ldsm4(t4, sb + 3 * ARRB2 + boff[ni2] + ko);
                bl[ni2 * 2][0] = t4[0]; bl[ni2 * 2][1] = t4[1];
                bl[ni2 * 2 + 1][0] = t4[2]; bl[ni2 * 2 + 1][1] = t4[3];
            }
            #pragma unroll
            for (int mi = 0; mi < 4; mi++)
                #pragma unroll
                for (int ni = 0; ni < 4; ni++) {
                    mma16816(acc[mi][ni], ah[mi], bh[ni]);
                    mma16816(acc[mi][ni], ah[mi], bl[ni]);
                    mma16816(acc[mi][ni], al[mi], bh[ni]);
                }
        }
        __syncthreads();
    }

    // epilogue
    const float* bias = tg.bias[z];
    const float* res  = tg.res[z];
    float* Cp = tg.c[z];
    __nv_bfloat16* Ch = tg.ch[z];
    __nv_bfloat16* Cl = tg.cl[z];

    #pragma unroll
    for (int mi = 0; mi < 4; mi++) {
        int m0 = bm + wm + mi * 16 + (lane >> 2);
        #pragma unroll
        for (int ni = 0; ni < 4; ni++) {
            int n = bn + wn + ni * 8 + (lane & 3) * 2;
            float2 v0 = make_float2(acc[mi][ni][0], acc[mi][ni][1]);
            float2 v1 = make_float2(acc[mi][ni][2], acc[mi][ni][3]);
            if (bias) {
                float2 bv = *(const float2*)&bias[n];
                v0.x += bv.x; v0.y += bv.y; v1.x += bv.x; v1.y += bv.y;
            }
            if (res) {
                float2 rr0 = *(const float2*)&res[(size_t)m0 * N + n];
                float2 rr1 = *(const float2*)&res[(size_t)(m0 + 8) * N + n];
                v0.x += rr0.x; v0.y += rr0.y; v1.x += rr1.x; v1.y += rr1.y;
            }
            if (act == 1) {
                v0.x = 0.5f * v0.x * (1.f + erff(v0.x * 0.70710678118654752f));
                v0.y = 0.5f * v0.y * (1.f + erff(v0.y * 0.70710678118654752f));
                v1.x = 0.5f * v1.x * (1.f + erff(v1.x * 0.70710678118654752f));
                v1.y = 0.5f * v1.y * (1.f + erff(v1.y * 0.70710678118654752f));
            }
            if (Cp) {
                *(float2*)&Cp[(size_t)m0 * N + n] = v0;
                *(float2*)&Cp[(size_t)(m0 + 8) * N + n] = v1;
            }
            if (Ch) {
                __nv_bfloat16 h0, l0, h1, l1;
                split1(v0.x, h0, l0); split1(v0.y, h1, l1);
                *(__nv_bfloat162*)&Ch[(size_t)m0 * N + n] = __nv_bfloat162(h0, h1);
                *(__nv_bfloat162*)&Cl[(size_t)m0 * N + n] = __nv_bfloat162(l0, l1);
                split1(v1.x, h0, l0); split1(v1.y, h1, l1);
                *(__nv_bfloat162*)&Ch[(size_t)(m0 + 8) * N + n] = __nv_bfloat162(h0, h1);
                *(__nv_bfloat162*)&Cl[(size_t)(m0 + 8) * N + n] = __nv_bfloat162(l0, l1);
            }
        }
    }
}

// ======================================================================
// Scores MMA: per (b,h) 128x128 q,k tile; K=64
// ======================================================================
constexpr int QSTR = 40;
__global__ __launch_bounds__(256) void scores_mma(
    const __nv_bfloat16* __restrict__ Qh, const __nv_bfloat16* __restrict__ Ql,
    const __nv_bfloat16* __restrict__ Kh, const __nv_bfloat16* __restrict__ Kl,
    const float* __restrict__ qtab, const int* __restrict__ mask,
    float* __restrict__ scores)
{
    __shared__ __nv_bfloat16 sQh[128 * QSTR], sQl[128 * QSTR];
    __shared__ __nv_bfloat16 sKh[128 * QSTR], sKl[128 * QSTR];
    const int bh = blockIdx.z, b = bh / H, h = bh % H;
    const int q0 = blockIdx.y * 128, k0b = blockIdx.x * 128;
    const int t = threadIdx.x, lane = t & 31, w = t >> 5;
    const int wm = (w & 1) * 64, wn = (w >> 1) * 32;

    const uint32_t bQh = smem_u32(sQh), bQl = smem_u32(sQl);
    const uint32_t bKh = smem_u32(sKh), bKl = smem_u32(sKl);

    float acc[4][4][4];
    #pragma unroll
    for (int i = 0; i < 4; i++)
        #pragma unroll
        for (int j = 0; j < 4; j++)
            #pragma unroll
            for (int r = 0; r < 4; r++) acc[i][j][r] = 0.f;

    uint32_t aoff[4], boff[2];
    #pragma unroll
    for (int mi = 0; mi < 4; mi++)
        aoff[mi] = (uint32_t)(((wm + mi * 16 + (lane & 15)) * QSTR + ((lane >> 4) << 3)) * 2);
    #pragma unroll
    for (int ni2 = 0; ni2 < 2; ni2++)
        boff[ni2] = (uint32_t)(((wn + ni2 * 16 + (lane & 7) + ((lane >> 4) << 3)) * QSTR
                               + (((lane >> 3) & 1) << 3)) * 2);

    for (int kt = 0; kt < 2; kt++) {
        #pragma unroll
        for (int i = 0; i < 2; i++) {
            int idx = t * 2 + i;
            int row = idx >> 2, cseg = (idx & 3) * 8;
            size_t qsrc = ((size_t)(b * S) + q0 + row) * D + h * DH + kt * 32 + cseg;
            size_t ksrc = ((size_t)(b * S) + k0b + row) * D + h * DH + kt * 32 + cseg;
            *(uint4*)&sQh[row * QSTR + cseg] = *(const uint4*)&Qh[qsrc];
            *(uint4*)&sQl[row * QSTR + cseg] = *(const uint4*)&Ql[qsrc];
            *(uint4*)&sKh[row * QSTR + cseg] = *(const uint4*)&Kh[ksrc];
            *(uint4*)&sKl[row * QSTR + cseg] = *(const uint4*)&Kl[ksrc];
        }
        __syncthreads();
        #pragma unroll
        for (int kk2 = 0; kk2 < 2; kk2++) {
            uint32_t koffb = kk2 * 32;
            uint32_t ah[4][4], al[4][4], bhf[4][2], blf[4][2];
            #pragma unroll
            for (int mi = 0; mi < 4; mi++) {
                ldsm4(ah[mi], bQh + aoff[mi] + koffb);
                ldsm4(al[mi], bQl + aoff[mi] + koffb);
            }
            #pragma unroll
            for (int ni2 = 0; ni2 < 2; ni2++) {
                uint32_t t4[4];
                ldsm4(t4, bKh + boff[ni2] + koffb);
                bhf[ni2 * 2][0] = t4[0]; bhf[ni2 * 2][1] = t4[1];
                bhf[ni2 * 2 + 1][0] = t4[2]; bhf[ni2 * 2 + 1][1] = t4[3];
                ldsm4(t4, bKl + boff[ni2] + koffb);
                blf[ni2 * 2][0] = t4[0]; blf[ni2 * 2][1] = t4[1];
                blf[ni2 * 2 + 1][0] = t4[2]; blf[ni2 * 2 + 1][1] = t4[3];
            }
            #pragma unroll
            for (int mi = 0; mi < 4; mi++)
                #pragma unroll
                for (int ni = 0; ni < 4; ni++) {
                    mma16816(acc[mi][ni], ah[mi], bhf[ni]);
                    mma16816(acc[mi][ni], ah[mi], blf[ni]);
                    mma16816(acc[mi][ni], al[mi], bhf[ni]);
                }
        }
        __syncthreads();
    }

    #pragma unroll
    for (int mi = 0; mi < 4; mi++) {
        #pragma unroll
        for (int rr = 0; rr < 2; rr++) {
            int q = q0 + wm + mi * 16 + (lane >> 2) + rr * 8;
            const float* qtr = qtab + (((size_t)b * S + q) * H + h) * NREL;
            size_t rowb = ((size_t)bh * S + q) * S;
            #pragma unroll
            for (int ni = 0; ni < 4; ni++) {
                int k = k0b + wn + ni * 8 + (lane & 3) * 2;
                float vx = acc[mi][ni][rr * 2 + 0];
                float vy = acc[mi][ni][rr * 2 + 1];
                int r0 = k - q; r0 = r0 < -64 ? -64 : (r0 > 64 ? 64 : r0);
                int r1 = k + 1 - q; r1 = r1 < -64 ? -64 : (r1 > 64 ? 64 : r1);
                float mb0 = (1.f - (float)mask[b * S + k]) * -10000.f;
                float mb1 = (1.f - (float)mask[b * S + k + 1]) * -10000.f;
                float2 o;
                o.x = (vx + qtr[r0 + 64]) * SCALE + mb0;
                o.y = (vy + qtr[r1 + 64]) * SCALE + mb1;
                *(float2*)&scores[rowb + k] = o;
            }
        }
    }
}

// ======================================================================
// ctx += probs @ V (warp-mma). Tile 128q x 64d, k-tile 32.
// ======================================================================
constexpr int VSTR = 72;
__global__ __launch_bounds__(256) void ctx_pv_mma(
    const __nv_bfloat16* __restrict__ Ph, const __nv_bfloat16* __restrict__ Pl,
    const __nv_bfloat16* __restrict__ Vh, const __nv_bfloat16* __restrict__ Vl,
    float* __restrict__ ctx)
{
    __shared__ __nv_bfloat16 sPh[128 * QSTR], sPl[128 * QSTR];
    __shared__ __nv_bfloat16 sVh[32 * VSTR], sVl[32 * VSTR];
    const int bh = blockIdx.z, b = bh / H, h = bh % H;
    const int q0 = blockIdx.x * 128;
    const int t = threadIdx.x, lane = t & 31, w = t >> 5;
    const int wm = (w & 3) * 32, wn = (w >> 2) * 32;

    const uint32_t bPh = smem_u32(sPh), bPl = smem_u32(sPl);
    const uint32_t bVh = smem_u32(sVh), bVl = smem_u32(sVl);

    float acc[2][4][4];
    #pragma unroll
    for (int i = 0; i < 2; i++)
        #pragma unroll
        for (int j = 0; j < 4; j++)
            #pragma unroll
            for (int r = 0; r < 4; r++) acc[i][j][r] = 0.f;

    uint32_t aoff[2];
    #pragma unroll
    for (int mi = 0; mi < 2; mi++)
        aoff[mi] = (uint32_t)(((wm + mi * 16 + (lane & 15)) * QSTR + ((lane >> 4) << 3)) * 2);

    for (int kt = 0; kt < S / 32; kt++) {
        #pragma unroll
        for (int i = 0; i < 2; i++) {
            int idx = t * 2 + i;
            int row = idx >> 2, cseg = (idx & 3) * 8;
            size_t psrc = ((size_t)bh * S + q0 + row) * S + kt * 32 + cseg;
            *(uint4*)&sPh[row * QSTR + cseg] = *(const uint4*)&Ph[psrc];
            *(uint4*)&sPl[row * QSTR + cseg] = *(const uint4*)&Pl[psrc];
        }
        {
            int row = t >> 3, cseg = (t & 7) * 8;
            size_t vsrc = ((size_t)(b * S) + kt * 32 + row) * D + h * DH + cseg;
            *(uint4*)&sVh[row * VSTR + cseg] = *(const uint4*)&Vh[vsrc];
            *(uint4*)&sVl[row * VSTR + cseg] = *(const uint4*)&Vl[vsrc];
        }
        __syncthreads();
        #pragma unroll
        for (int kk2 = 0; kk2 < 2; kk2++) {
            uint32_t koffb = kk2 * 32;
            uint32_t ah[2][4], al[2][4], bhf[4][2], blf[4][2];
            #pragma unroll
            for (int mi = 0; mi < 2; mi++) {
                ldsm4(ah[mi], bPh + aoff[mi] + koffb);
                ldsm4(al[mi], bPl + aoff[mi] + koffb);
            }
            #pragma unroll
            for (int ni2 = 0; ni2 < 2; ni2++) {
                uint32_t vaddr = (uint32_t)(((kk2 * 16 + (lane & 15)) * VSTR
                                 + wn + ni2 * 16 + (lane >> 4) * 8) * 2);
                uint32_t t4[4];
                ldsm4t(t4, bVh + vaddr);
                bhf[ni2 * 2][0] = t4[0]; bhf[ni2 * 2][1] = t4[1];
                bhf[ni2 * 2 + 1][0] = t4[2]; bhf[ni2 * 2 + 1][1] = t4[3];
                ldsm4t(t4, bVl + vaddr);
                blf[ni2 * 2][0] = t4[0]; blf[ni2 * 2][1] = t4[1];
                blf[ni2 * 2 + 1][0] = t4[2]; blf[ni2 * 2 + 1][1] = t4[3];
            }
            #pragma unroll
            for (int mi = 0; mi < 2; mi++)
                #pragma unroll
                for (int ni = 0; ni < 4; ni++) {
                    mma16816(acc[mi][ni], ah[mi], bhf[ni]);
                    mma16816(acc[mi][ni], ah[mi], blf[ni]);
                    mma16816(acc[mi][ni], al[mi], bhf[ni]);
                }
        }
        __syncthreads();
    }

    #pragma unroll
    for (int mi = 0; mi < 2; mi++) {
        #pragma unroll
        for (int rr = 0; rr < 2; rr++) {
            int q = q0 + wm + mi * 16 + (lane >> 2) + rr * 8;
            size_t rb = ((size_t)(b * S) + q) * D + h * DH;
            #pragma unroll
            for (int ni = 0; ni < 4; ni++) {
                int d = wn + ni * 8 + (lane & 3) * 2;
                float2 cur = *(float2*)&ctx[rb + d];
                cur.x += acc[mi][ni][rr * 2 + 0];
                cur.y += acc[mi][ni][rr * 2 + 1];
                *(float2*)&ctx[rb + d] = cur;
            }
        }
    }
}

// ---------------- embedding + LN ----------------
__global__ __launch_bounds__(256) void embed_ln(
    const int* __restrict__ ids, const int* __restrict__ tti,
    const float* __restrict__ we, const float* __restrict__ te,
    const float* __restrict__ w, const float* __restrict__ bb,
    float* __restrict__ out, __nv_bfloat16* __restrict__ oh,
    __nv_bfloat16* __restrict__ ol)
{
    __shared__ float red[256];
    int m = blockIdx.x, t = threadIdx.x;
    int id = ids[m], t2 = tti[m];
    const float* wr = we + (size_t)id * D;
    const float* tr = te + (size_t)t2 * D;
    float vals[3]; float s = 0.f;
    #pragma unroll
    for (int i = 0; i < 3; i++) { int d = t + i * 256; vals[i] = wr[d] + tr[d]; s += vals[i]; }
    float mean = block_reduce_sum(s, red) * (1.f / D);
    float vs = 0.f;
    #pragma unroll
    for (int i = 0; i < 3; i++) { float dd = vals[i] - mean; vs += dd * dd; }
    float var = block_reduce_sum(vs, red) * (1.f / D);
    float rstd = rsqrtf(var + LN_EPS);
    #pragma unroll
    for (int i = 0; i < 3; i++) {
        int d = t + i * 256;
        float v = (vals[i] - mean) * rstd * w[d] + bb[d];
        out[(size_t)m * D + d] = v;
        __nv_bfloat16 h, l; split1(v, h, l);
        oh[(size_t)m * D + d] = h;
        ol[(size_t)m * D + d] = l;
    }
}

__global__ __launch_bounds__(256) void ln_kernel(
    const float* __restrict__ x, const float* __restrict__ w,
    const float* __restrict__ bb, float* __restrict__ out,
    __nv_bfloat16* __restrict__ oh, __nv_bfloat16* __restrict__ ol)
{
    __shared__ float red[256];
    int m = blockIdx.x, t = threadIdx.x;
    const float* xr = x + (size_t)m * D;
    float vals[3]; float s = 0.f;
    #pragma unroll
    for (int i = 0; i < 3; i++) { vals[i] = xr[t + i * 256]; s += vals[i]; }
    float mean = block_reduce_sum(s, red) * (1.f / D);
    float vs = 0.f;
    #pragma unroll
    for (int i = 0; i < 3; i++) { float dd = vals[i] - mean; vs += dd * dd; }
    float var = block_reduce_sum(vs, red) * (1.f / D);
    float rstd = rsqrtf(var + LN_EPS);
    #pragma unroll
    for (int i = 0; i < 3; i++) {
        int d = t + i * 256;
        float v = (vals[i] - mean) * rstd * w[d] + bb[d];
        out[(size_t)m * D + d] = v;
        __nv_bfloat16 h, l; split1(v, h, l);
        oh[(size_t)m * D + d] = h;
        ol[(size_t)m * D + d] = l;
    }
}

// ---------------- small guarded SIMT GEMMs ----------------
__global__ __launch_bounds__(256) void gemm_nt(
    const float* __restrict__ A, const float* __restrict__ W,
    float* __restrict__ C, int M, int N, int K)
{
    __shared__ float As[16][65];
    __shared__ float Bs[16][65];
    const int bm = blockIdx.y * 64, bn = blockIdx.x * 64;
    const int t = threadIdx.x, tx = t & 15, ty = t >> 4;
    float acc[4][4] = {};
    for (int k0 = 0; k0 < K; k0 += 16) {
        #pragma unroll
        for (int l = 0; l < 4; l++) {
            int idx = t + l * 256;
            int r = idx >> 4, c = idx & 15;
            int m = bm + r, kk = k0 + c;
            As[c][r] = (m < M && kk < K) ? A[(size_t)m * K + kk] : 0.f;
        }
        #pragma unroll
        for (int l = 0; l < 4; l++) {
            int idx = t + l * 256;
            int r = idx >> 4, c = idx & 15;
            int n = bn + r, kk = k0 + c;
            Bs[c][r] = (n < N && kk < K) ? W[(size_t)n * K + kk] : 0.f;
        }
        __syncthreads();
        #pragma unroll
        for (int kk = 0; kk < 16; kk++) {
            float a[4], bv[4];
            #pragma unroll
            for (int i = 0; i < 4; i++) a[i] = As[kk][ty * 4 + i];
            #pragma unroll
            for (int j = 0; j < 4; j++) bv[j] = Bs[kk][tx * 4 + j];
            #pragma unroll
            for (int i = 0; i < 4; i++)
                #pragma unroll
                for (int j = 0; j < 4; j++) acc[i][j] += a[i] * bv[j];
        }
        __syncthreads();
    }
    #pragma unroll
    for (int i = 0; i < 4; i++) {
        int m = bm + ty * 4 + i;
        if (m >= M) continue;
        #pragma unroll
        for (int j = 0; j < 4; j++) {
            int n = bn + tx * 4 + j;
            if (n >= N) continue;
            C[(size_t)m * N + n] = acc[i][j];
        }
    }
}

__global__ __launch_bounds__(256) void gemm_nn_small(
    const float* __restrict__ A, const float* __restrict__ Bm,
    float* __restrict__ C, int M, int N, int K)
{
    __shared__ float As[16][65];
    __shared__ float Bs[16][65];
    const int bm = blockIdx.y * 64, bn = blockIdx.x * 64;
    const int t = threadIdx.x, tx = t & 15, ty = t >> 4;
    float acc[4][4] = {};
    for (int k0 = 0; k0 < K; k0 += 16) {
        #pragma unroll
        for (int l = 0; l < 4; l++) {
            int idx = t + l * 256;
            int r = idx >> 4, c = idx & 15;
            int m = bm + r, kk = k0 + c;
            As[c][r] = (m < M && kk < K) ? A[(size_t)m * K + kk] : 0.f;
        }
        #pragma unroll
        for (int l = 0; l < 4; l++) {
            int idx = t + l * 256;
            int r = idx >> 6, c = idx & 63;
            int kk = k0 + r, n = bn + c;
            Bs[r][c] = (kk < K && n < N) ? Bm[(size_t)kk * N + n] : 0.f;
        }
        __syncthreads();
        #pragma unroll
        for (int kk = 0; kk < 16; kk++) {
            float a[4], bv[4];
            #pragma unroll
            for (int i = 0; i < 4; i++) a[i] = As[kk][ty * 4 + i];
            #pragma unroll
            for (int j = 0; j < 4; j++) bv[j] = Bs[kk][tx * 4 + j];
            #pragma unroll
            for (int i = 0; i < 4; i++)
                #pragma unroll
                for (int j = 0; j < 4; j++) acc[i][j] += a[i] * bv[j];
        }
        __syncthreads();
    }
    #pragma unroll
    for (int i = 0; i < 4; i++) {
        int m = bm + ty * 4 + i;
        if (m >= M) continue;
        #pragma unroll
        for (int j = 0; j < 4; j++) {
            int n = bn + tx * 4 + j;
            if (n >= N) continue;
            C[(size_t)m * N + n] = acc[i][j];
        }
    }
}

// ---------------- softmax -> bf16 hi/lo probs + ptab ----------------
__global__ __launch_bounds__(256) void softmax_kernel(
    const float* __restrict__ scores,
    __nv_bfloat16* __restrict__ ph, __nv_bfloat16* __restrict__ pl,
    float* __restrict__ ptab)
{
    __shared__ float red[256];
    __shared__ float pr[512];
    const int row = blockIdx.x;
    const int q = row % S, bh = row / S;
    const int b = bh / H, h = bh % H;
    const float* sr = scores + (size_t)row * S;
    const int t = threadIdx.x;
    float v0 = sr[t], v1 = sr[t + 256];

    float m = fmaxf(v0, v1);
    red[t] = m; __syncthreads();
    for (int o = 128; o > 0; o >>= 1) { if (t < o) red[t] = fmaxf(red[t], red[t + o]); __syncthreads(); }
    m = red[0]; __syncthreads();

    float e0 = expf(v0 - m), e1 = expf(v1 - m);
    float s = block_reduce_sum(e0 + e1, red);
    float inv = 1.f / s;
    float p0 = e0 * inv, p1 = e1 * inv;
    pr[t] = p0; pr[t + 256] = p1;

    size_t rb = (size_t)row * S;
    __nv_bfloat16 h0, l0, h1, l1;
    split1(p0, h0, l0); split1(p1, h1, l1);
    ph[rb + t] = h0; ph[rb + t + 256] = h1;
    pl[rb + t] = l0; pl[rb + t + 256] = l1;

    float left = 0.f, right = 0.f;
    if (t <= q - 64)       left += p0;
    if (t + 256 <= q - 64) left += p1;
    if (t >= q + 64)       right += p0;
    if (t + 256 >= q + 64) right += p1;
    left  = block_reduce_sum(left,  red);
    right = block_reduce_sum(right, red);

    size_t pbase = (((size_t)b * S + q) * H + h) * NREL;
    if (t == 0) { ptab[pbase] = left; ptab[pbase + 128] = right; }
    if (t >= 1 && t <= 127) {
        int k = q + t - 64;
        ptab[pbase + t] = (k >= 0 && k < S) ? pr[k] : 0.f;
    }
}

// ---------------- launch ----------------
extern "C" void kernel_launch(void* const* d_in, const int* in_sizes, int n_in,
                              void* d_out, int out_size)
{
    const int*   ids     = (const int*)d_in[0];
    const int*   amask   = (const int*)d_in[1];
    const int*   tti     = (const int*)d_in[2];
    const float* wemb    = (const float*)d_in[3];
    const float* temb    = (const float*)d_in[4];
    const float* elnw    = (const float*)d_in[5];
    const float* elnb    = (const float*)d_in[6];
    const float* qw      = (const float*)d_in[7];
    const float* qb      = (const float*)d_in[8];
    const float* kw      = (const float*)d_in[9];
    const float* kb      = (const float*)d_in[10];
    const float* vw      = (const float*)d_in[11];
    const float* vb      = (const float*)d_in[12];
    const float* rel     = (const float*)d_in[13];
    const float* ow      = (const float*)d_in[14];
    const float* ob      = (const float*)d_in[15];
    const float* alnw    = (const float*)d_in[16];
    const float* alnb    = (const float*)d_in[17];
    const float* iw      = (const float*)d_in[18];
    const float* ib      = (const float*)d_in[19];
    const float* dw      = (const float*)d_in[20];
    const float* db      = (const float*)d_in[21];
    const float* olnw    = (const float*)d_in[22];
    const float* olnb    = (const float*)d_in[23];
    float* out = (float*)d_out;

    float *x, *q, *sc, *qt, *pt, *ctx, *tmp, *attn, *tab;
    cudaGetSymbolAddress((void**)&x,    g_x);
    cudaGetSymbolAddress((void**)&q,    g_q);
    cudaGetSymbolAddress((void**)&sc,   g_scores);
    cudaGetSymbolAddress((void**)&qt,   g_qtab);
    cudaGetSymbolAddress((void**)&pt,   g_ptab);
    cudaGetSymbolAddress((void**)&ctx,  g_ctx);
    cudaGetSymbolAddress((void**)&tmp,  g_tmp);
    cudaGetSymbolAddress((void**)&attn, g_attn);
    cudaGetSymbolAddress((void**)&tab,  g_table);

    __nv_bfloat16 *wqh, *wql, *wkh, *wkl, *wvh, *wvl, *woh, *wol;
    __nv_bfloat16 *wih, *wil, *wdh, *wdl;
    __nv_bfloat16 *xh, *xl, *qh, *ql, *kh, *kl, *vh, *vl, *ah, *al, *ffh, *ffl, *ph, *pl;
    cudaGetSymbolAddress((void**)&wqh, g_wqh); cudaGetSymbolAddress((void**)&wql, g_wql);
    cudaGetSymbolAddress((void**)&wkh, g_wkh); cudaGetSymbolAddress((void**)&wkl, g_wkl);
    cudaGetSymbolAddress((void**)&wvh, g_wvh); cudaGetSymbolAddress((void**)&wvl, g_wvl);
    cudaGetSymbolAddress((void**)&woh, g_woh); cudaGetSymbolAddress((void**)&wol, g_wol);
    cudaGetSymbolAddress((void**)&wih, g_wih); cudaGetSymbolAddress((void**)&wil, g_wil);
    cudaGetSymbolAddress((void**)&wdh, g_wdh); cudaGetSymbolAddress((void**)&wdl, g_wdl);
    cudaGetSymbolAddress((void**)&xh,  g_xh);  cudaGetSymbolAddress((void**)&xl,  g_xl);
    cudaGetSymbolAddress((void**)&qh,  g_qh);  cudaGetSymbolAddress((void**)&ql,  g_ql);
    cudaGetSymbolAddress((void**)&kh,  g_kh);  cudaGetSymbolAddress((void**)&kl,  g_kl);
    cudaGetSymbolAddress((void**)&vh,  g_vh);  cudaGetSymbolAddress((void**)&vl,  g_vl);
    cudaGetSymbolAddress((void**)&ah,  g_ah);  cudaGetSymbolAddress((void**)&al,  g_al);
    cudaGetSymbolAddress((void**)&ffh, g_ffh); cudaGetSymbolAddress((void**)&ffl, g_ffl);
    cudaGetSymbolAddress((void**)&ph,  g_ph);  cudaGetSymbolAddress((void**)&pl,  g_pl);

    cudaFuncSetAttribute(gemm_mma_pipe, cudaFuncAttributeMaxDynamicSharedMemorySize, PIPE2_SMEM);

    build_table<<<(NREL * DH + 255) / 256, 256>>>(rel, tab);
    embed_ln<<<(int)BS, 256>>>(ids, tti, wemb, temb, elnw, elnb, x, xh, xl);

    {
        int n4 = (int)(WSZ / 4), g = (n4 + 255) / 256;
        split_bf16<<<g, 256>>>(qw, wqh, wql, n4);
        split_bf16<<<g, 256>>>(kw, wkh, wkl, n4);
        split_bf16<<<g, 256>>>(vw, wvh, wvl, n4);
        split_bf16<<<g, 256>>>(ow, woh, wol, n4);
        int n4f = (int)(WFF / 4), gf = (n4f + 255) / 256;
        split_bf16<<<gf, 256>>>(iw, wih, wil, n4f);
        split_bf16<<<gf, 256>>>(dw, wdh, wdl, n4f);
    }

    const int nD4 = (int)(BSD / 4), gD = (nD4 + 255) / 256;

    const dim3 gQKV(D / 128, (int)(BS / 128), 3);
    const dim3 gP(D / 128, (int)(BS / 128), 1);
    const dim3 gF1(FF / 128, (int)(BS / 128), 1);
    const dim3 gQT((NREL + 63) / 64, (int)(BS * H / 64));
    const dim3 gCR(1, (int)(BS * H / 64));
    const dim3 gSC(S / 128, S / 128, B * H);
    const dim3 gPV(S / 128, 1, B * H);

    for (int l = 0; l < L; l++) {
        const size_t wo = (size_t)l * D * D;
        const size_t fo = (size_t)l * FF * D;

        // QKV fused via blockIdx.z
        GemmTargets tq = {};
        tq.wh[0] = wqh + wo; tq.wl[0] = wql + wo; tq.bias[0] = qb + l * D;
        tq.res[0] = nullptr; tq.c[0] = q; tq.ch[0] = qh; tq.cl[0] = ql;
        tq.wh[1] = wkh + wo; tq.wl[1] = wkl + wo; tq.bias[1] = kb + l * D;
        tq.res[1] = nullptr; tq.c[1] = nullptr; tq.ch[1] = kh; tq.cl[1] = kl;
        tq.wh[2] = wvh + wo; tq.wl[2] = wvl + wo; tq.bias[2] = vb + l * D;
        tq.res[2] = nullptr; tq.c[2] = nullptr; tq.ch[2] = vh; tq.cl[2] = vl;
        gemm_mma_pipe<<<gQKV, 256, PIPE2_SMEM>>>(xh, xl, tq, (int)BS, D, D, 0);

        gemm_nt<<<gQT, 256>>>(q, tab, qt, (int)(BS * H), NREL, DH);

        scores_mma<<<gSC, 256>>>(qh, ql, kh, kl, qt, amask, sc);
        softmax_kernel<<<(int)BHS, 256>>>(sc, ph, pl, pt);

        gemm_nn_small<<<gCR, 256>>>(pt, tab, ctx, (int)(BS * H), DH, NREL);
        ctx_pv_mma<<<gPV, 256>>>(ph, pl, vh, vl, ctx);

        split_bf16<<<gD, 256>>>(ctx, ah, al, nD4);
        GemmTargets to = {};
        to.wh[0] = woh + wo; to.wl[0] = wol + wo; to.bias[0] = ob + l * D;
        to.res[0] = x; to.c[0] = tmp; to.ch[0] = nullptr; to.cl[0] = nullptr;
        gemm_mma_pipe<<<gP, 256, PIPE2_SMEM>>>(ah, al, to, (int)BS, D, D, 0);
        ln_kernel<<<(int)BS, 256>>>(tmp, alnw + l * D, alnb + l * D, attn, ah, al);

        GemmTargets tf = {};
        tf.wh[0] = wih + fo; tf.wl[0] = wil + fo; tf.bias[0] = ib + l * FF;
        tf.res[0] = nullptr; tf.c[0] = nullptr; tf.ch[0] = ffh; tf.cl[0] = ffl;
        gemm_mma_pipe<<<gF1, 256, PIPE2_SMEM>>>(ah, al, tf, (int)BS, FF, D, 1);

        GemmTargets td = {};
        td.wh[0] = wdh + fo; td.wl[0] = wdl + fo; td.bias[0] = db + l * D;
        td.res[0] = attn; td.c[0] = tmp; td.ch[0] = nullptr; td.cl[0] = nullptr;
        gemm_mma_pipe<<<gP, 256, PIPE2_SMEM>>>(ffh, ffl, td, (int)BS, D, FF, 0);
        ln_kernel<<<(int)BS, 256>>>(tmp, olnw + l * D, olnb + l * D,
                                    (l == L - 1) ? out : x, xh, xl);
    }
}

// round 7
// speedup vs baseline: 1.1646x; 1.1646x over previous
#include <cuda_runtime.h>
#include <cuda_bf16.h>
#include <math.h>
#include <stdint.h>

// ---------------- problem constants ----------------
constexpr int B = 16, S = 512, D = 768, H = 12, FF = 3072, L = 4;
constexpr int DH = 64;
constexpr int NREL = 129;
constexpr int NRELP = 144;        // padded rel dim for bf16 ptab
constexpr float SCALE = 0.125f;
constexpr float LN_EPS = 1e-12f;

constexpr size_t BS   = (size_t)B * S;
constexpr size_t BSD  = BS * D;
constexpr size_t BHS  = (size_t)B * H * S;
constexpr size_t BHSS = BHS * S;

// ---------------- device scratch ----------------
__device__ float g_x[BSD];
__device__ float g_scores[BHSS];
__device__ float g_qtab[BHS * NREL];
__device__ float g_ctx[BSD];
__device__ float g_tmp[BSD];
__device__ float g_attn[BSD];

constexpr size_t WSZ = (size_t)L * D * D;
constexpr size_t WFF = (size_t)L * FF * D;
__device__ __align__(256) __nv_bfloat16 g_wqh[WSZ], g_wql[WSZ];
__device__ __align__(256) __nv_bfloat16 g_wkh[WSZ], g_wkl[WSZ];
__device__ __align__(256) __nv_bfloat16 g_wvh[WSZ], g_wvl[WSZ];
__device__ __align__(256) __nv_bfloat16 g_woh[WSZ], g_wol[WSZ];
__device__ __align__(256) __nv_bfloat16 g_wih[WFF], g_wil[WFF];
__device__ __align__(256) __nv_bfloat16 g_wdh[WFF], g_wdl[WFF];
__device__ __align__(256) __nv_bfloat16 g_xh[BSD], g_xl[BSD];
__device__ __align__(256) __nv_bfloat16 g_qh[BSD], g_ql[BSD];
__device__ __align__(256) __nv_bfloat16 g_kh[BSD], g_kl[BSD];
__device__ __align__(256) __nv_bfloat16 g_vh[BSD], g_vl[BSD];
__device__ __align__(256) __nv_bfloat16 g_ah[BSD], g_al[BSD];
__device__ __align__(256) __nv_bfloat16 g_ffh[BS * FF], g_ffl[BS * FF];
__device__ __align__(256) __nv_bfloat16 g_ph[BHSS], g_pl[BHSS];
__device__ __align__(256) __nv_bfloat16 g_pth[BHS * NRELP], g_ptl[BHS * NRELP];
__device__ __align__(256) __nv_bfloat16 g_tabh[160 * 64], g_tabl[160 * 64];    // [j,d] padded rows
__device__ __align__(256) __nv_bfloat16 g_tTh[64 * NRELP], g_tTl[64 * NRELP];  // [d,j] padded cols

// ---------------- helpers ----------------
__device__ __forceinline__ float block_reduce_sum(float v, float* red) {
    int t = threadIdx.x;
    red[t] = v; __syncthreads();
    for (int o = 128; o > 0; o >>= 1) {
        if (t < o) red[t] += red[t + o];
        __syncthreads();
    }
    float r = red[0]; __syncthreads();
    return r;
}

__device__ __forceinline__ void split1(float v, __nv_bfloat16& h, __nv_bfloat16& l) {
    h = __float2bfloat16_rn(v);
    l = __float2bfloat16_rn(v - __bfloat162float(h));
}

__global__ void build_tables(const float* __restrict__ rel,
                             __nv_bfloat16* __restrict__ tabh, __nv_bfloat16* __restrict__ tabl,
                             __nv_bfloat16* __restrict__ tTh, __nv_bfloat16* __restrict__ tTl)
{
    int i = blockIdx.x * 256 + threadIdx.x;
    if (i >= 160 * 64) return;
    int j = i / 64, d = i % 64;
    float v = (j < NREL) ? rel[((size_t)128 * S + (64 + j)) * DH + d] : 0.f;
    __nv_bfloat16 h, l; split1(v, h, l);
    tabh[j * 64 + d] = h; tabl[j * 64 + d] = l;
    if (j < NRELP) { tTh[d * NRELP + j] = h; tTl[d * NRELP + j] = l; }
}

__global__ __launch_bounds__(256) void split_bf16(
    const float* __restrict__ in, __nv_bfloat16* __restrict__ hi,
    __nv_bfloat16* __restrict__ lo, int n4)
{
    int i = blockIdx.x * 256 + threadIdx.x;
    if (i >= n4) return;
    float4 v = ((const float4*)in)[i];
    __nv_bfloat16 h0, h1, h2, h3, l0, l1, l2, l3;
    split1(v.x, h0, l0); split1(v.y, h1, l1);
    split1(v.z, h2, l2); split1(v.w, h3, l3);
    __nv_bfloat162* hp = (__nv_bfloat162*)hi;
    __nv_bfloat162* lp = (__nv_bfloat162*)lo;
    hp[i * 2 + 0] = __nv_bfloat162(h0, h1);
    hp[i * 2 + 1] = __nv_bfloat162(h2, h3);
    lp[i * 2 + 0] = __nv_bfloat162(l0, l1);
    lp[i * 2 + 1] = __nv_bfloat162(l2, l3);
}

// ---------------- mma primitives ----------------
__device__ __forceinline__ void mma16816(float* d, const uint32_t* a, const uint32_t* b) {
    asm volatile(
        "mma.sync.aligned.m16n8k16.row.col.f32.bf16.bf16.f32 "
        "{%0,%1,%2,%3}, {%4,%5,%6,%7}, {%8,%9}, {%0,%1,%2,%3};\n"
        : "+f"(d[0]), "+f"(d[1]), "+f"(d[2]), "+f"(d[3])
        : "r"(a[0]), "r"(a[1]), "r"(a[2]), "r"(a[3]), "r"(b[0]), "r"(b[1]));
}
__device__ __forceinline__ void ldsm4(uint32_t* r, uint32_t addr) {
    asm volatile("ldmatrix.sync.aligned.m8n8.x4.shared.b16 {%0,%1,%2,%3}, [%4];\n"
        : "=r"(r[0]), "=r"(r[1]), "=r"(r[2]), "=r"(r[3]) : "r"(addr));
}
__device__ __forceinline__ void ldsm4t(uint32_t* r, uint32_t addr) {
    asm volatile("ldmatrix.sync.aligned.m8n8.x4.trans.shared.b16 {%0,%1,%2,%3}, [%4];\n"
        : "=r"(r[0]), "=r"(r[1]), "=r"(r[2]), "=r"(r[3]) : "r"(addr));
}
__device__ __forceinline__ void cp16(uint32_t dst, const void* src) {
    asm volatile("cp.async.cg.shared.global [%0], [%1], 16;\n" :: "r"(dst), "l"(src));
}
__device__ __forceinline__ void cp_commit() { asm volatile("cp.async.commit_group;\n"); }
__device__ __forceinline__ void cp_wait1() { asm volatile("cp.async.wait_group 1;\n" ::: "memory"); }
__device__ __forceinline__ uint32_t smem_u32(const void* p) {
    return (uint32_t)__cvta_generic_to_shared(p);
}

// ======================================================================
// R4 pipelined split-bf16 MMA GEMM NT (k16, 3 stages, 73.7KB, 2 CTA/SM)
// ======================================================================
constexpr int ASTR = 24;
constexpr int STG_ARR = 128 * ASTR * 2;   // 6144
constexpr int STG = 4 * STG_ARR;          // 24576
constexpr int NSTAGE = 3;
constexpr int PIPE_SMEM = NSTAGE * STG;   // 73728

struct GemmTargets {
    const __nv_bfloat16* wh[3];
    const __nv_bfloat16* wl[3];
    const float* bias[3];
    float* c[3];
    __nv_bfloat16* ch[3];
    __nv_bfloat16* cl[3];
};

__global__ __launch_bounds__(256) void gemm_mma_pipe(
    const __nv_bfloat16* __restrict__ Ah, const __nv_bfloat16* __restrict__ Al,
    GemmTargets tg, int M, int N, int K, int act)
{
    extern __shared__ __align__(16) char dsm[];
    const uint32_t sbase = smem_u32(dsm);
    const int z = blockIdx.z;
    const __nv_bfloat16* Wh = tg.wh[z];
    const __nv_bfloat16* Wl = tg.wl[z];

    const int bm = blockIdx.y * 128, bn = blockIdx.x * 128;
    const int t = threadIdx.x, lane = t & 31, w = t >> 5;
    const int wm = (w & 1) * 64, wn = (w >> 1) * 32;

    const int grow = t >> 1, gcol = (t & 1) * 8;
    const __nv_bfloat16* pAh = Ah + (size_t)(bm + grow) * K + gcol;
    const __nv_bfloat16* pAl = Al + (size_t)(bm + grow) * K + gcol;
    const __nv_bfloat16* pWh = Wh + (size_t)(bn + grow) * K + gcol;
    const __nv_bfloat16* pWl = Wl + (size_t)(bn + grow) * K + gcol;
    const uint32_t dstoff = (uint32_t)((grow * ASTR + gcol) * 2);

    float acc[4][4][4];
    #pragma unroll
    for (int i = 0; i < 4; i++)
        #pragma unroll
        for (int j = 0; j < 4; j++)
            #pragma unroll
            for (int r = 0; r < 4; r++) acc[i][j][r] = 0.f;

    uint32_t aoff[4], boff[2];
    #pragma unroll
    for (int mi = 0; mi < 4; mi++)
        aoff[mi] = (uint32_t)(((wm + mi * 16 + (lane & 15)) * ASTR + ((lane >> 4) << 3)) * 2);
    #pragma unroll
    for (int ni2 = 0; ni2 < 2; ni2++)
        boff[ni2] = (uint32_t)(((wn + ni2 * 16 + (lane & 7) + ((lane >> 4) << 3)) * ASTR
                               + (((lane >> 3) & 1) << 3)) * 2);

    const int nk = K / 16;
    auto issue = [&](int kt, int slot) {
        if (kt < nk) {
            uint32_t base = sbase + slot * STG + dstoff;
            size_t go = (size_t)kt * 16;
            cp16(base,               pAh + go);
            cp16(base + STG_ARR,     pAl + go);
            cp16(base + 2 * STG_ARR, pWh + go);
            cp16(base + 3 * STG_ARR, pWl + go);
        }
        cp_commit();
    };
    issue(0, 0);
    issue(1, 1);

    for (int kt = 0; kt < nk; kt++) {
        cp_wait1();
        __syncthreads();
        issue(kt + 2, (kt + 2) % NSTAGE);

        const uint32_t sb = sbase + (kt % NSTAGE) * STG;
        uint32_t ah[4][4], al[4][4], bh[4][2], bl[4][2];
        #pragma unroll
        for (int mi = 0; mi < 4; mi++) {
            ldsm4(ah[mi], sb + aoff[mi]);
            ldsm4(al[mi], sb + STG_ARR + aoff[mi]);
        }
        #pragma unroll
        for (int ni2 = 0; ni2 < 2; ni2++) {
            uint32_t t4[4];
            ldsm4(t4, sb + 2 * STG_ARR + boff[ni2]);
            bh[ni2 * 2][0] = t4[0]; bh[ni2 * 2][1] = t4[1];
            bh[ni2 * 2 + 1][0] = t4[2]; bh[ni2 * 2 + 1][1] = t4[3];
            ldsm4(t4, sb + 3 * STG_ARR + boff[ni2]);
            bl[ni2 * 2][0] = t4[0]; bl[ni2 * 2][1] = t4[1];
            bl[ni2 * 2 + 1][0] = t4[2]; bl[ni2 * 2 + 1][1] = t4[3];
        }
        #pragma unroll
        for (int mi = 0; mi < 4; mi++)
            #pragma unroll
            for (int ni = 0; ni < 4; ni++) {
                mma16816(acc[mi][ni], ah[mi], bh[ni]);
                mma16816(acc[mi][ni], ah[mi], bl[ni]);
                mma16816(acc[mi][ni], al[mi], bh[ni]);
            }
        __syncthreads();
    }

    const float* bias = tg.bias[z];
    float* Cp = tg.c[z];
    __nv_bfloat16* Ch = tg.ch[z];
    __nv_bfloat16* Cl = tg.cl[z];

    #pragma unroll
    for (int mi = 0; mi < 4; mi++) {
        int m0 = bm + wm + mi * 16 + (lane >> 2);
        #pragma unroll
        for (int ni = 0; ni < 4; ni++) {
            int n = bn + wn + ni * 8 + (lane & 3) * 2;
            float2 v0 = make_float2(acc[mi][ni][0], acc[mi][ni][1]);
            float2 v1 = make_float2(acc[mi][ni][2], acc[mi][ni][3]);
            if (bias) {
                float2 bv = *(const float2*)&bias[n];
                v0.x += bv.x; v0.y += bv.y; v1.x += bv.x; v1.y += bv.y;
            }
            if (act == 1) {
                v0.x = 0.5f * v0.x * (1.f + erff(v0.x * 0.70710678118654752f));
                v0.y = 0.5f * v0.y * (1.f + erff(v0.y * 0.70710678118654752f));
                v1.x = 0.5f * v1.x * (1.f + erff(v1.x * 0.70710678118654752f));
                v1.y = 0.5f * v1.y * (1.f + erff(v1.y * 0.70710678118654752f));
            }
            if (Cp) {
                *(float2*)&Cp[(size_t)m0 * N + n] = v0;
                *(float2*)&Cp[(size_t)(m0 + 8) * N + n] = v1;
            }
            if (Ch) {
                __nv_bfloat16 h0, l0, h1, l1;
                split1(v0.x, h0, l0); split1(v0.y, h1, l1);
                *(__nv_bfloat162*)&Ch[(size_t)m0 * N + n] = __nv_bfloat162(h0, h1);
                *(__nv_bfloat162*)&Cl[(size_t)m0 * N + n] = __nv_bfloat162(l0, l1);
                split1(v1.x, h0, l0); split1(v1.y, h1, l1);
                *(__nv_bfloat162*)&Ch[(size_t)(m0 + 8) * N + n] = __nv_bfloat162(h0, h1);
                *(__nv_bfloat162*)&Cl[(size_t)(m0 + 8) * N + n] = __nv_bfloat162(l0, l1);
            }
        }
    }
}

__global__ __launch_bounds__(256) void gemm_mma_pipe_res(
    const __nv_bfloat16* __restrict__ Ah, const __nv_bfloat16* __restrict__ Al,
    const __nv_bfloat16* __restrict__ Wh, const __nv_bfloat16* __restrict__ Wl,
    const float* __restrict__ bias, const float* __restrict__ res,
    float* __restrict__ Cp, int M, int N, int K)
{
    extern __shared__ __align__(16) char dsm[];
    const uint32_t sbase = smem_u32(dsm);
    const int bm = blockIdx.y * 128, bn = blockIdx.x * 128;
    const int t = threadIdx.x, lane = t & 31, w = t >> 5;
    const int wm = (w & 1) * 64, wn = (w >> 1) * 32;

    const int grow = t >> 1, gcol = (t & 1) * 8;
    const __nv_bfloat16* pAh = Ah + (size_t)(bm + grow) * K + gcol;
    const __nv_bfloat16* pAl = Al + (size_t)(bm + grow) * K + gcol;
    const __nv_bfloat16* pWh = Wh + (size_t)(bn + grow) * K + gcol;
    const __nv_bfloat16* pWl = Wl + (size_t)(bn + grow) * K + gcol;
    const uint32_t dstoff = (uint32_t)((grow * ASTR + gcol) * 2);

    float acc[4][4][4];
    #pragma unroll
    for (int i = 0; i < 4; i++)
        #pragma unroll
        for (int j = 0; j < 4; j++)
            #pragma unroll
            for (int r = 0; r < 4; r++) acc[i][j][r] = 0.f;

    uint32_t aoff[4], boff[2];
    #pragma unroll
    for (int mi = 0; mi < 4; mi++)
        aoff[mi] = (uint32_t)(((wm + mi * 16 + (lane & 15)) * ASTR + ((lane >> 4) << 3)) * 2);
    #pragma unroll
    for (int ni2 = 0; ni2 < 2; ni2++)
        boff[ni2] = (uint32_t)(((wn + ni2 * 16 + (lane & 7) + ((lane >> 4) << 3)) * ASTR
                               + (((lane >> 3) & 1) << 3)) * 2);

    const int nk = K / 16;
    auto issue = [&](int kt, int slot) {
        if (kt < nk) {
            uint32_t base = sbase + slot * STG + dstoff;
            size_t go = (size_t)kt * 16;
            cp16(base,               pAh + go);
            cp16(base + STG_ARR,     pAl + go);
            cp16(base + 2 * STG_ARR, pWh + go);
            cp16(base + 3 * STG_ARR, pWl + go);
        }
        cp_commit();
    };
    issue(0, 0);
    issue(1, 1);

    for (int kt = 0; kt < nk; kt++) {
        cp_wait1();
        __syncthreads();
        issue(kt + 2, (kt + 2) % NSTAGE);

        const uint32_t sb = sbase + (kt % NSTAGE) * STG;
        uint32_t ah[4][4], al[4][4], bh[4][2], bl[4][2];
        #pragma unroll
        for (int mi = 0; mi < 4; mi++) {
            ldsm4(ah[mi], sb + aoff[mi]);
            ldsm4(al[mi], sb + STG_ARR + aoff[mi]);
        }
        #pragma unroll
        for (int ni2 = 0; ni2 < 2; ni2++) {
            uint32_t t4[4];
            ldsm4(t4, sb + 2 * STG_ARR + boff[ni2]);
            bh[ni2 * 2][0] = t4[0]; bh[ni2 * 2][1] = t4[1];
            bh[ni2 * 2 + 1][0] = t4[2]; bh[ni2 * 2 + 1][1] = t4[3];
            ldsm4(t4, sb + 3 * STG_ARR + boff[ni2]);
            bl[ni2 * 2][0] = t4[0]; bl[ni2 * 2][1] = t4[1];
            bl[ni2 * 2 + 1][0] = t4[2]; bl[ni2 * 2 + 1][1] = t4[3];
        }
        #pragma unroll
        for (int mi = 0; mi < 4; mi++)
            #pragma unroll
            for (int ni = 0; ni < 4; ni++) {
                mma16816(acc[mi][ni], ah[mi], bh[ni]);
                mma16816(acc[mi][ni], ah[mi], bl[ni]);
                mma16816(acc[mi][ni], al[mi], bh[ni]);
            }
        __syncthreads();
    }

    #pragma unroll
    for (int mi = 0; mi < 4; mi++) {
        int m0 = bm + wm + mi * 16 + (lane >> 2);
        #pragma unroll
        for (int ni = 0; ni < 4; ni++) {
            int n = bn + wn + ni * 8 + (lane & 3) * 2;
            float2 v0 = make_float2(acc[mi][ni][0], acc[mi][ni][1]);
            float2 v1 = make_float2(acc[mi][ni][2], acc[mi][ni][3]);
            float2 bv = *(const float2*)&bias[n];
            v0.x += bv.x; v0.y += bv.y; v1.x += bv.x; v1.y += bv.y;
            float2 r0 = *(const float2*)&res[(size_t)m0 * N + n];
            float2 r1 = *(const float2*)&res[(size_t)(m0 + 8) * N + n];
            v0.x += r0.x; v0.y += r0.y; v1.x += r1.x; v1.y += r1.y;
            *(float2*)&Cp[(size_t)m0 * N + n] = v0;
            *(float2*)&Cp[(size_t)(m0 + 8) * N + n] = v1;
        }
    }
}

// ======================================================================
// qtab via warp-MMA: qtab[m, j] = Q[m,:]·table[j,:], m = token*H+h.
// A = qh/ql [98304 x 64], B = tab padded [160 x 64]. Tile 128 x 160.
// 8 warps: 4m x 2n (warp tile 32 x 80).
// ======================================================================
constexpr int QT_STR = 72;
constexpr int QT_A = 128 * QT_STR * 2;   // 18432 B per A array
constexpr int QT_B = 160 * QT_STR * 2;   // 23040 B per B array
constexpr int QT_SMEM = 2 * QT_A + 2 * QT_B;  // 82944

__global__ __launch_bounds__(256) void qtab_mma(
    const __nv_bfloat16* __restrict__ Qh, const __nv_bfloat16* __restrict__ Ql,
    const __nv_bfloat16* __restrict__ Th, const __nv_bfloat16* __restrict__ Tl,
    float* __restrict__ qt)
{
    extern __shared__ __align__(16) char dsm[];
    __nv_bfloat16* sAh = (__nv_bfloat16*)dsm;
    __nv_bfloat16* sAl = (__nv_bfloat16*)(dsm + QT_A);
    __nv_bfloat16* sBh = (__nv_bfloat16*)(dsm + 2 * QT_A);
    __nv_bfloat16* sBl = (__nv_bfloat16*)(dsm + 2 * QT_A + QT_B);
    const uint32_t bAh = smem_u32(sAh), bAl = smem_u32(sAl);
    const uint32_t bBh = smem_u32(sBh), bBl = smem_u32(sBl);

    const int bm = blockIdx.x * 128;
    const int t = threadIdx.x, lane = t & 31, w = t >> 5;
    const int wm = (w & 3) * 32, wn = (w >> 2) * 80;

    // load A tile: 128 rows x 64 cols (8 segs of 16B per row) -> 1024 segs
    #pragma unroll
    for (int i = 0; i < 4; i++) {
        int s = t + i * 256;
        int row = s >> 3, c8 = s & 7;
        size_t src = (size_t)(bm + row) * 64 + c8 * 8;
        *(uint4*)&sAh[row * QT_STR + c8 * 8] = *(const uint4*)&Qh[src];
        *(uint4*)&sAl[row * QT_STR + c8 * 8] = *(const uint4*)&Ql[src];
    }
    // load B: 160 x 64 -> 1280 segs
    #pragma unroll
    for (int i = 0; i < 5; i++) {
        int s = t + i * 256;
        int row = s >> 3, c8 = s & 7;
        *(uint4*)&sBh[row * QT_STR + c8 * 8] = *(const uint4*)&Th[row * 64 + c8 * 8];
        *(uint4*)&sBl[row * QT_STR + c8 * 8] = *(const uint4*)&Tl[row * 64 + c8 * 8];
    }
    __syncthreads();

    float acc[2][10][4];
    #pragma unroll
    for (int i = 0; i < 2; i++)
        #pragma unroll
        for (int j = 0; j < 10; j++)
            #pragma unroll
            for (int r = 0; r < 4; r++) acc[i][j][r] = 0.f;

    uint32_t aoff[2], boff[5];
    #pragma unroll
    for (int mi = 0; mi < 2; mi++)
        aoff[mi] = (uint32_t)(((wm + mi * 16 + (lane & 15)) * QT_STR + ((lane >> 4) << 3)) * 2);
    #pragma unroll
    for (int ni2 = 0; ni2 < 5; ni2++)
        boff[ni2] = (uint32_t)(((wn + ni2 * 16 + (lane & 7) + ((lane >> 4) << 3)) * QT_STR
                               + (((lane >> 3) & 1) << 3)) * 2);

    #pragma unroll
    for (int kc = 0; kc < 4; kc++) {
        uint32_t ko = kc * 32;
        uint32_t ah[2][4], al[2][4];
        #pragma unroll
        for (int mi = 0; mi < 2; mi++) {
            ldsm4(ah[mi], bAh + aoff[mi] + ko);
            ldsm4(al[mi], bAl + aoff[mi] + ko);
        }
        #pragma unroll
        for (int ni2 = 0; ni2 < 5; ni2++) {
            uint32_t th4[4], tl4[4];
            ldsm4(th4, bBh + boff[ni2] + ko);
            ldsm4(tl4, bBl + boff[ni2] + ko);
            uint32_t bh0[2] = {th4[0], th4[1]}, bh1[2] = {th4[2], th4[3]};
            uint32_t bl0[2] = {tl4[0], tl4[1]}, bl1[2] = {tl4[2], tl4[3]};
            #pragma unroll
            for (int mi = 0; mi < 2; mi++) {
                mma16816(acc[mi][ni2 * 2], ah[mi], bh0);
                mma16816(acc[mi][ni2 * 2], ah[mi], bl0);
                mma16816(acc[mi][ni2 * 2], al[mi], bh0);
                mma16816(acc[mi][ni2 * 2 + 1], ah[mi], bh1);
                mma16816(acc[mi][ni2 * 2 + 1], ah[mi], bl1);
                mma16816(acc[mi][ni2 * 2 + 1], al[mi], bh1);
            }
        }
    }

    #pragma unroll
    for (int mi = 0; mi < 2; mi++)
        #pragma unroll
        for (int rr = 0; rr < 2; rr++) {
            int m0 = bm + wm + mi * 16 + (lane >> 2) + rr * 8;
            #pragma unroll
            for (int ni = 0; ni < 10; ni++) {
                int n = wn + ni * 8 + (lane & 3) * 2;
                if (n < NREL)     qt[(size_t)m0 * NREL + n]     = acc[mi][ni][rr * 2 + 0];
                if (n + 1 < NREL) qt[(size_t)m0 * NREL + n + 1] = acc[mi][ni][rr * 2 + 1];
            }
        }
}

// ======================================================================
// ctx_rel via warp-MMA: ctx[m, d] = ptab[m,:]·tabT[d,:], K = 144 (3 chunks of 48)
// Tile 128 x 64. 8 warps: 4m x 2n (32 x 32).
// ======================================================================
constexpr int CR_ASTR = 56;
constexpr int CR_BSTR = 152;
constexpr int CR_A = 128 * CR_ASTR * 2;   // 14336
constexpr int CR_B = 64 * CR_BSTR * 2;    // 19456
constexpr int CR_SMEM = 2 * CR_A + 2 * CR_B;  // 67584

__global__ __launch_bounds__(256) void ctx_rel_mma(
    const __nv_bfloat16* __restrict__ Ph, const __nv_bfloat16* __restrict__ Pl,
    const __nv_bfloat16* __restrict__ Th, const __nv_bfloat16* __restrict__ Tl,
    float* __restrict__ ctx)
{
    extern __shared__ __align__(16) char dsm[];
    __nv_bfloat16* sAh = (__nv_bfloat16*)dsm;
    __nv_bfloat16* sAl = (__nv_bfloat16*)(dsm + CR_A);
    __nv_bfloat16* sBh = (__nv_bfloat16*)(dsm + 2 * CR_A);
    __nv_bfloat16* sBl = (__nv_bfloat16*)(dsm + 2 * CR_A + CR_B);
    const uint32_t bAh = smem_u32(sAh), bAl = smem_u32(sAl);
    const uint32_t bBh = smem_u32(sBh), bBl = smem_u32(sBl);

    const int bm = blockIdx.x * 128;
    const int t = threadIdx.x, lane = t & 31, w = t >> 5;
    const int wm = (w & 3) * 32, wn = (w >> 2) * 32;

    // load B fully: 64 rows x 144 cols = 18 segs/row -> 1152 segs
    for (int s = t; s < 1152; s += 256) {
        int row = s / 18, c8 = s % 18;
        *(uint4*)&sBh[row * CR_BSTR + c8 * 8] = *(const uint4*)&Th[row * NRELP + c8 * 8];
        *(uint4*)&sBl[row * CR_BSTR + c8 * 8] = *(const uint4*)&Tl[row * NRELP + c8 * 8];
    }

    float acc[2][4][4];
    #pragma unroll
    for (int i = 0; i < 2; i++)
        #pragma unroll
        for (int j = 0; j < 4; j++)
            #pragma unroll
            for (int r = 0; r < 4; r++) acc[i][j][r] = 0.f;

    uint32_t aoff[2], boff[2];
    #pragma unroll
    for (int mi = 0; mi < 2; mi++)
        aoff[mi] = (uint32_t)(((wm + mi * 16 + (lane & 15)) * CR_ASTR + ((lane >> 4) << 3)) * 2);
    #pragma unroll
    for (int ni2 = 0; ni2 < 2; ni2++)
        boff[ni2] = (uint32_t)(((wn + ni2 * 16 + (lane & 7) + ((lane >> 4) << 3)) * CR_BSTR
                               + (((lane >> 3) & 1) << 3)) * 2);

    for (int c = 0; c < 3; c++) {
        __syncthreads();
        // load A chunk: 128 rows x 48 cols = 6 segs/row -> 768 segs
        #pragma unroll
        for (int i = 0; i < 3; i++) {
            int s = t + i * 256;
            int row = s / 6, c8 = s % 6;
            size_t src = (size_t)(bm + row) * NRELP + c * 48 + c8 * 8;
            *(uint4*)&sAh[row * CR_ASTR + c8 * 8] = *(const uint4*)&Ph[src];
            *(uint4*)&sAl[row * CR_ASTR + c8 * 8] = *(const uint4*)&Pl[src];
        }
        __syncthreads();
        #pragma unroll
        for (int kc = 0; kc < 3; kc++) {
            uint32_t kaoff = kc * 32;
            uint32_t kboff = (uint32_t)(c * 96 + kc * 32);
            uint32_t ah[2][4], al[2][4];
            #pragma unroll
            for (int mi = 0; mi < 2; mi++) {
                ldsm4(ah[mi], bAh + aoff[mi] + kaoff);
                ldsm4(al[mi], bAl + aoff[mi] + kaoff);
            }
            #pragma unroll
            for (int ni2 = 0; ni2 < 2; ni2++) {
                uint32_t th4[4], tl4[4];
                ldsm4(th4, bBh + boff[ni2] + kboff);
                ldsm4(tl4, bBl + boff[ni2] + kboff);
                uint32_t bh0[2] = {th4[0], th4[1]}, bh1[2] = {th4[2], th4[3]};
                uint32_t bl0[2] = {tl4[0], tl4[1]}, bl1[2] = {tl4[2], tl4[3]};
                #pragma unroll
                for (int mi = 0; mi < 2; mi++) {
                    mma16816(acc[mi][ni2 * 2], ah[mi], bh0);
                    mma16816(acc[mi][ni2 * 2], ah[mi], bl0);
                    mma16816(acc[mi][ni2 * 2], al[mi], bh0);
                    mma16816(acc[mi][ni2 * 2 + 1], ah[mi], bh1);
                    mma16816(acc[mi][ni2 * 2 + 1], ah[mi], bl1);
                    mma16816(acc[mi][ni2 * 2 + 1], al[mi], bh1);
                }
            }
        }
    }

    #pragma unroll
    for (int mi = 0; mi < 2; mi++)
        #pragma unroll
        for (int rr = 0; rr < 2; rr++) {
            int m0 = bm + wm + mi * 16 + (lane >> 2) + rr * 8;
            #pragma unroll
            for (int ni = 0; ni < 4; ni++) {
                int n = wn + ni * 8 + (lane & 3) * 2;
                float2 v = make_float2(acc[mi][ni][rr * 2 + 0], acc[mi][ni][rr * 2 + 1]);
                *(float2*)&ctx[(size_t)m0 * 64 + n] = v;
            }
        }
}

// ======================================================================
// Scores MMA: per (b,h) 128x128 q,k tile; K=64
// ======================================================================
constexpr int QSTR = 40;
__global__ __launch_bounds__(256) void scores_mma(
    const __nv_bfloat16* __restrict__ Qh, const __nv_bfloat16* __restrict__ Ql,
    const __nv_bfloat16* __restrict__ Kh, const __nv_bfloat16* __restrict__ Kl,
    const float* __restrict__ qtab, const int* __restrict__ mask,
    float* __restrict__ scores)
{
    __shared__ __nv_bfloat16 sQh[128 * QSTR], sQl[128 * QSTR];
    __shared__ __nv_bfloat16 sKh[128 * QSTR], sKl[128 * QSTR];
    const int bh = blockIdx.z, b = bh / H, h = bh % H;
    const int q0 = blockIdx.y * 128, k0b = blockIdx.x * 128;
    const int t = threadIdx.x, lane = t & 31, w = t >> 5;
    const int wm = (w & 1) * 64, wn = (w >> 1) * 32;

    const uint32_t bQh = smem_u32(sQh), bQl = smem_u32(sQl);
    const uint32_t bKh = smem_u32(sKh), bKl = smem_u32(sKl);

    float acc[4][4][4];
    #pragma unroll
    for (int i = 0; i < 4; i++)
        #pragma unroll
        for (int j = 0; j < 4; j++)
            #pragma unroll
            for (int r = 0; r < 4; r++) acc[i][j][r] = 0.f;

    uint32_t aoff[4], boff[2];
    #pragma unroll
    for (int mi = 0; mi < 4; mi++)
        aoff[mi] = (uint32_t)(((wm + mi * 16 + (lane & 15)) * QSTR + ((lane >> 4) << 3)) * 2);
    #pragma unroll
    for (int ni2 = 0; ni2 < 2; ni2++)
        boff[ni2] = (uint32_t)(((wn + ni2 * 16 + (lane & 7) + ((lane >> 4) << 3)) * QSTR
                               + (((lane >> 3) & 1) << 3)) * 2);

    for (int kt = 0; kt < 2; kt++) {
        #pragma unroll
        for (int i = 0; i < 2; i++) {
            int idx = t * 2 + i;
            int row = idx >> 2, cseg = (idx & 3) * 8;
            size_t qsrc = ((size_t)(b * S) + q0 + row) * D + h * DH + kt * 32 + cseg;
            size_t ksrc = ((size_t)(b * S) + k0b + row) * D + h * DH + kt * 32 + cseg;
            *(uint4*)&sQh[row * QSTR + cseg] = *(const uint4*)&Qh[qsrc];
            *(uint4*)&sQl[row * QSTR + cseg] = *(const uint4*)&Ql[qsrc];
            *(uint4*)&sKh[row * QSTR + cseg] = *(const uint4*)&Kh[ksrc];
            *(uint4*)&sKl[row * QSTR + cseg] = *(const uint4*)&Kl[ksrc];
        }
        __syncthreads();
        #pragma unroll
        for (int kk2 = 0; kk2 < 2; kk2++) {
            uint32_t koffb = kk2 * 32;
            uint32_t ah[4][4], al[4][4], bhf[4][2], blf[4][2];
            #pragma unroll
            for (int mi = 0; mi < 4; mi++) {
                ldsm4(ah[mi], bQh + aoff[mi] + koffb);
                ldsm4(al[mi], bQl + aoff[mi] + koffb);
            }
            #pragma unroll
            for (int ni2 = 0; ni2 < 2; ni2++) {
                uint32_t t4[4];
                ldsm4(t4, bKh + boff[ni2] + koffb);
                bhf[ni2 * 2][0] = t4[0]; bhf[ni2 * 2][1] = t4[1];
                bhf[ni2 * 2 + 1][0] = t4[2]; bhf[ni2 * 2 + 1][1] = t4[3];
                ldsm4(t4, bKl + boff[ni2] + koffb);
                blf[ni2 * 2][0] = t4[0]; blf[ni2 * 2][1] = t4[1];
                blf[ni2 * 2 + 1][0] = t4[2]; blf[ni2 * 2 + 1][1] = t4[3];
            }
            #pragma unroll
            for (int mi = 0; mi < 4; mi++)
                #pragma unroll
                for (int ni = 0; ni < 4; ni++) {
                    mma16816(acc[mi][ni], ah[mi], bhf[ni]);
                    mma16816(acc[mi][ni], ah[mi], blf[ni]);
                    mma16816(acc[mi][ni], al[mi], bhf[ni]);
                }
        }
        __syncthreads();
    }

    #pragma unroll
    for (int mi = 0; mi < 4; mi++) {
        #pragma unroll
        for (int rr = 0; rr < 2; rr++) {
            int q = q0 + wm + mi * 16 + (lane >> 2) + rr * 8;
            const float* qtr = qtab + (((size_t)b * S + q) * H + h) * NREL;
            size_t rowb = ((size_t)bh * S + q) * S;
            #pragma unroll
            for (int ni = 0; ni < 4; ni++) {
                int k = k0b + wn + ni * 8 + (lane & 3) * 2;
                float vx = acc[mi][ni][rr * 2 + 0];
                float vy = acc[mi][ni][rr * 2 + 1];
                int r0 = k - q; r0 = r0 < -64 ? -64 : (r0 > 64 ? 64 : r0);
                int r1 = k + 1 - q; r1 = r1 < -64 ? -64 : (r1 > 64 ? 64 : r1);
                float mb0 = (1.f - (float)mask[b * S + k]) * -10000.f;
                float mb1 = (1.f - (float)mask[b * S + k + 1]) * -10000.f;
                float2 o;
                o.x = (vx + qtr[r0 + 64]) * SCALE + mb0;
                o.y = (vy + qtr[r1 + 64]) * SCALE + mb1;
                *(float2*)&scores[rowb + k] = o;
            }
        }
    }
}

// ======================================================================
// ctx_pv: ctx_out(hi/lo bf16) = probs@V + ctx_rel(fp32 in). Tile 128q x 64d.
// ======================================================================
constexpr int VSTR = 72;
__global__ __launch_bounds__(256) void ctx_pv_mma(
    const __nv_bfloat16* __restrict__ Ph, const __nv_bfloat16* __restrict__ Pl,
    const __nv_bfloat16* __restrict__ Vh, const __nv_bfloat16* __restrict__ Vl,
    const float* __restrict__ ctxin,
    __nv_bfloat16* __restrict__ outh, __nv_bfloat16* __restrict__ outl)
{
    __shared__ __nv_bfloat16 sPh[128 * QSTR], sPl[128 * QSTR];
    __shared__ __nv_bfloat16 sVh[32 * VSTR], sVl[32 * VSTR];
    const int bh = blockIdx.z, b = bh / H, h = bh % H;
    const int q0 = blockIdx.x * 128;
    const int t = threadIdx.x, lane = t & 31, w = t >> 5;
    const int wm = (w & 3) * 32, wn = (w >> 2) * 32;

    const uint32_t bPh = smem_u32(sPh), bPl = smem_u32(sPl);
    const uint32_t bVh = smem_u32(sVh), bVl = smem_u32(sVl);

    float acc[2][4][4];
    #pragma unroll
    for (int i = 0; i < 2; i++)
        #pragma unroll
        for (int j = 0; j < 4; j++)
            #pragma unroll
            for (int r = 0; r < 4; r++) acc[i][j][r] = 0.f;

    uint32_t aoff[2];
    #pragma unroll
    for (int mi = 0; mi < 2; mi++)
        aoff[mi] = (uint32_t)(((wm + mi * 16 + (lane & 15)) * QSTR + ((lane >> 4) << 3)) * 2);

    for (int kt = 0; kt < S / 32; kt++) {
        #pragma unroll
        for (int i = 0; i < 2; i++) {
            int idx = t * 2 + i;
            int row = idx >> 2, cseg = (idx & 3) * 8;
            size_t psrc = ((size_t)bh * S + q0 + row) * S + kt * 32 + cseg;
            *(uint4*)&sPh[row * QSTR + cseg] = *(const uint4*)&Ph[psrc];
            *(uint4*)&sPl[row * QSTR + cseg] = *(const uint4*)&Pl[psrc];
        }
        {
            int row = t >> 3, cseg = (t & 7) * 8;
            size_t vsrc = ((size_t)(b * S) + kt * 32 + row) * D + h * DH + cseg;
            *(uint4*)&sVh[row * VSTR + cseg] = *(const uint4*)&Vh[vsrc];
            *(uint4*)&sVl[row * VSTR + cseg] = *(const uint4*)&Vl[vsrc];
        }
        __syncthreads();
        #pragma unroll
        for (int kk2 = 0; kk2 < 2; kk2++) {
            uint32_t koffb = kk2 * 32;
            uint32_t ah[2][4], al[2][4], bhf[4][2], blf[4][2];
            #pragma unroll
            for (int mi = 0; mi < 2; mi++) {
                ldsm4(ah[mi], bPh + aoff[mi] + koffb);
                ldsm4(al[mi], bPl + aoff[mi] + koffb);
            }
            #pragma unroll
            for (int ni2 = 0; ni2 < 2; ni2++) {
                uint32_t vaddr = (uint32_t)(((kk2 * 16 + (lane & 15)) * VSTR
                                 + wn + ni2 * 16 + (lane >> 4) * 8) * 2);
                uint32_t t4[4];
                ldsm4t(t4, bVh + vaddr);
                bhf[ni2 * 2][0] = t4[0]; bhf[ni2 * 2][1] = t4[1];
                bhf[ni2 * 2 + 1][0] = t4[2]; bhf[ni2 * 2 + 1][1] = t4[3];
                ldsm4t(t4, bVl + vaddr);
                blf[ni2 * 2][0] = t4[0]; blf[ni2 * 2][1] = t4[1];
                blf[ni2 * 2 + 1][0] = t4[2]; blf[ni2 * 2 + 1][1] = t4[3];
            }
            #pragma unroll
            for (int mi = 0; mi < 2; mi++)
                #pragma unroll
                for (int ni = 0; ni < 4; ni++) {
                    mma16816(acc[mi][ni], ah[mi], bhf[ni]);
                    mma16816(acc[mi][ni], ah[mi], blf[ni]);
                    mma16816(acc[mi][ni], al[mi], bhf[ni]);
                }
        }
        __syncthreads();
    }

    #pragma unroll
    for (int mi = 0; mi < 2; mi++) {
        #pragma unroll
        for (int rr = 0; rr < 2; rr++) {
            int q = q0 + wm + mi * 16 + (lane >> 2) + rr * 8;
            size_t rb = ((size_t)(b * S) + q) * D + h * DH;
            #pragma unroll
            for (int ni = 0; ni < 4; ni++) {
                int d = wn + ni * 8 + (lane & 3) * 2;
                float2 cur = *(const float2*)&ctxin[rb + d];
                cur.x += acc[mi][ni][rr * 2 + 0];
                cur.y += acc[mi][ni][rr * 2 + 1];
                __nv_bfloat16 h0, l0, h1, l1;
                split1(cur.x, h0, l0); split1(cur.y, h1, l1);
                *(__nv_bfloat162*)&outh[rb + d] = __nv_bfloat162(h0, h1);
                *(__nv_bfloat162*)&outl[rb + d] = __nv_bfloat162(l0, l1);
            }
        }
    }
}

// ---------------- embedding + LN ----------------
__global__ __launch_bounds__(256) void embed_ln(
    const int* __restrict__ ids, const int* __restrict__ tti,
    const float* __restrict__ we, const float* __restrict__ te,
    const float* __restrict__ w, const float* __restrict__ bb,
    float* __restrict__ out, __nv_bfloat16* __restrict__ oh,
    __nv_bfloat16* __restrict__ ol)
{
    __shared__ float red[256];
    int m = blockIdx.x, t = threadIdx.x;
    int id = ids[m], t2 = tti[m];
    const float* wr = we + (size_t)id * D;
    const float* tr = te + (size_t)t2 * D;
    float vals[3]; float s = 0.f;
    #pragma unroll
    for (int i = 0; i < 3; i++) { int d = t + i * 256; vals[i] = wr[d] + tr[d]; s += vals[i]; }
    float mean = block_reduce_sum(s, red) * (1.f / D);
    float vs = 0.f;
    #pragma unroll
    for (int i = 0; i < 3; i++) { float dd = vals[i] - mean; vs += dd * dd; }
    float var = block_reduce_sum(vs, red) * (1.f / D);
    float rstd = rsqrtf(var + LN_EPS);
    #pragma unroll
    for (int i = 0; i < 3; i++) {
        int d = t + i * 256;
        float v = (vals[i] - mean) * rstd * w[d] + bb[d];
        out[(size_t)m * D + d] = v;
        __nv_bfloat16 h, l; split1(v, h, l);
        oh[(size_t)m * D + d] = h;
        ol[(size_t)m * D + d] = l;
    }
}

__global__ __launch_bounds__(256) void ln_kernel(
    const float* __restrict__ x, const float* __restrict__ w,
    const float* __restrict__ bb, float* __restrict__ out,
    __nv_bfloat16* __restrict__ oh, __nv_bfloat16* __restrict__ ol)
{
    __shared__ float red[256];
    int m = blockIdx.x, t = threadIdx.x;
    const float* xr = x + (size_t)m * D;
    float vals[3]; float s = 0.f;
    #pragma unroll
    for (int i = 0; i < 3; i++) { vals[i] = xr[t + i * 256]; s += vals[i]; }
    float mean = block_reduce_sum(s, red) * (1.f / D);
    float vs = 0.f;
    #pragma unroll
    for (int i = 0; i < 3; i++) { float dd = vals[i] - mean; vs += dd * dd; }
    float var = block_reduce_sum(vs, red) * (1.f / D);
    float rstd = rsqrtf(var + LN_EPS);
    #pragma unroll
    for (int i = 0; i < 3; i++) {
        int d = t + i * 256;
        float v = (vals[i] - mean) * rstd * w[d] + bb[d];
        out[(size_t)m * D + d] = v;
        __nv_bfloat16 h, l; split1(v, h, l);
        oh[(size_t)m * D + d] = h;
        ol[(size_t)m * D + d] = l;
    }
}

// ---------------- warp-per-row softmax -> bf16 probs + padded bf16 ptab ----------------
__global__ __launch_bounds__(256) void softmax_warp(
    const float* __restrict__ scores,
    __nv_bfloat16* __restrict__ ph, __nv_bfloat16* __restrict__ pl,
    __nv_bfloat16* __restrict__ pth, __nv_bfloat16* __restrict__ ptl)
{
    __shared__ float srow[8][512];
    const int w = threadIdx.x >> 5, lane = threadIdx.x & 31;
    const int row = blockIdx.x * 8 + w;      // (b*H+h)*S + q
    const int q = row % S, bh = row / S;
    const int b = bh / H, h = bh % H;
    const float* sr = scores + (size_t)row * S;

    float2 v[8];
    float m = -1e30f;
    #pragma unroll
    for (int i = 0; i < 8; i++) {
        v[i] = *(const float2*)&sr[lane * 2 + 64 * i];
        m = fmaxf(m, fmaxf(v[i].x, v[i].y));
    }
    #pragma unroll
    for (int o = 16; o > 0; o >>= 1) m = fmaxf(m, __shfl_xor_sync(0xffffffffu, m, o));

    float s = 0.f;
    #pragma unroll
    for (int i = 0; i < 8; i++) {
        v[i].x = expf(v[i].x - m); v[i].y = expf(v[i].y - m);
        s += v[i].x + v[i].y;
    }
    #pragma unroll
    for (int o = 16; o > 0; o >>= 1) s += __shfl_xor_sync(0xffffffffu, s, o);
    float inv = 1.f / s;

    size_t rb = (size_t)row * S;
    float left = 0.f, right = 0.f;
    #pragma unroll
    for (int i = 0; i < 8; i++) {
        int k = lane * 2 + 64 * i;
        float p0 = v[i].x * inv, p1 = v[i].y * inv;
        srow[w][k] = p0; srow[w][k + 1] = p1;
        __nv_bfloat16 h0, l0, h1, l1;
        split1(p0, h0, l0); split1(p1, h1, l1);
        *(__nv_bfloat162*)&ph[rb + k] = __nv_bfloat162(h0, h1);
        *(__nv_bfloat162*)&pl[rb + k] = __nv_bfloat162(l0, l1);
        if (k <= q - 64)     left += p0;
        if (k + 1 <= q - 64) left += p1;
        if (k >= q + 64)     right += p0;
        if (k + 1 >= q + 64) right += p1;
    }
    #pragma unroll
    for (int o = 16; o > 0; o >>= 1) {
        left  += __shfl_xor_sync(0xffffffffu, left, o);
        right += __shfl_xor_sync(0xffffffffu, right, o);
    }
    __syncwarp();

    size_t pbase = ((size_t)(b * S + q) * H + h) * NRELP;
    __nv_bfloat16 hh, ll;
    if (lane == 0) {
        split1(left, hh, ll);  pth[pbase] = hh;       ptl[pbase] = ll;
        split1(right, hh, ll); pth[pbase + 128] = hh; ptl[pbase + 128] = ll;
    }
    if (lane < 15) {           // zero pad j = 129..143
        pth[pbase + 129 + lane] = __float2bfloat16(0.f);
        ptl[pbase + 129 + lane] = __float2bfloat16(0.f);
    }
    #pragma unroll
    for (int jj = 0; jj < 4; jj++) {
        int j = 1 + lane + 32 * jj;
        if (j <= 127) {
            int k = q + j - 64;
            float p = (k >= 0 && k < S) ? srow[w][k] : 0.f;
            split1(p, hh, ll);
            pth[pbase + j] = hh; ptl[pbase + j] = ll;
        }
    }
}

// ---------------- launch ----------------
extern "C" void kernel_launch(void* const* d_in, const int* in_sizes, int n_in,
                              void* d_out, int out_size)
{
    const int*   ids     = (const int*)d_in[0];
    const int*   amask   = (const int*)d_in[1];
    const int*   tti     = (const int*)d_in[2];
    const float* wemb    = (const float*)d_in[3];
    const float* temb    = (const float*)d_in[4];
    const float* elnw    = (const float*)d_in[5];
    const float* elnb    = (const float*)d_in[6];
    const float* qw      = (const float*)d_in[7];
    const float* qb      = (const float*)d_in[8];
    const float* kw      = (const float*)d_in[9];
    const float* kb      = (const float*)d_in[10];
    const float* vw      = (const float*)d_in[11];
    const float* vb      = (const float*)d_in[12];
    const float* rel     = (const float*)d_in[13];
    const float* ow      = (const float*)d_in[14];
    const float* ob      = (const float*)d_in[15];
    const float* alnw    = (const float*)d_in[16];
    const float* alnb    = (const float*)d_in[17];
    const float* iw      = (const float*)d_in[18];
    const float* ib      = (const float*)d_in[19];
    const float* dw      = (const float*)d_in[20];
    const float* db      = (const float*)d_in[21];
    const float* olnw    = (const float*)d_in[22];
    const float* olnb    = (const float*)d_in[23];
    float* out = (float*)d_out;

    float *x, *sc, *qt, *ctx, *tmp, *attn;
    cudaGetSymbolAddress((void**)&x,    g_x);
    cudaGetSymbolAddress((void**)&sc,   g_scores);
    cudaGetSymbolAddress((void**)&qt,   g_qtab);
    cudaGetSymbolAddress((void**)&ctx,  g_ctx);
    cudaGetSymbolAddress((void**)&tmp,  g_tmp);
    cudaGetSymbolAddress((void**)&attn, g_attn);

    __nv_bfloat16 *wqh, *wql, *wkh, *wkl, *wvh, *wvl, *woh, *wol;
    __nv_bfloat16 *wih, *wil, *wdh, *wdl;
    __nv_bfloat16 *xh, *xl, *qh, *ql, *kh, *kl, *vh, *vl, *ah, *al, *ffh, *ffl, *ph, *pl;
    __nv_bfloat16 *pth, *ptl, *tabh, *tabl, *tTh, *tTl;
    cudaGetSymbolAddress((void**)&wqh, g_wqh); cudaGetSymbolAddress((void**)&wql, g_wql);
    cudaGetSymbolAddress((void**)&wkh, g_wkh); cudaGetSymbolAddress((void**)&wkl, g_wkl);
    cudaGetSymbolAddress((void**)&wvh, g_wvh); cudaGetSymbolAddress((void**)&wvl, g_wvl);
    cudaGetSymbolAddress((void**)&woh, g_woh); cudaGetSymbolAddress((void**)&wol, g_wol);
    cudaGetSymbolAddress((void**)&wih, g_wih); cudaGetSymbolAddress((void**)&wil, g_wil);
    cudaGetSymbolAddress((void**)&wdh, g_wdh); cudaGetSymbolAddress((void**)&wdl, g_wdl);
    cudaGetSymbolAddress((void**)&xh,  g_xh);  cudaGetSymbolAddress((void**)&xl,  g_xl);
    cudaGetSymbolAddress((void**)&qh,  g_qh);  cudaGetSymbolAddress((void**)&ql,  g_ql);
    cudaGetSymbolAddress((void**)&kh,  g_kh);  cudaGetSymbolAddress((void**)&kl,  g_kl);
    cudaGetSymbolAddress((void**)&vh,  g_vh);  cudaGetSymbolAddress((void**)&vl,  g_vl);
    cudaGetSymbolAddress((void**)&ah,  g_ah);  cudaGetSymbolAddress((void**)&al,  g_al);
    cudaGetSymbolAddress((void**)&ffh, g_ffh); cudaGetSymbolAddress((void**)&ffl, g_ffl);
    cudaGetSymbolAddress((void**)&ph,  g_ph);  cudaGetSymbolAddress((void**)&pl,  g_pl);
    cudaGetSymbolAddress((void**)&pth, g_pth); cudaGetSymbolAddress((void**)&ptl, g_ptl);
    cudaGetSymbolAddress((void**)&tabh, g_tabh); cudaGetSymbolAddress((void**)&tabl, g_tabl);
    cudaGetSymbolAddress((void**)&tTh, g_tTh); cudaGetSymbolAddress((void**)&tTl, g_tTl);

    cudaFuncSetAttribute(gemm_mma_pipe, cudaFuncAttributeMaxDynamicSharedMemorySize, PIPE_SMEM);
    cudaFuncSetAttribute(gemm_mma_pipe_res, cudaFuncAttributeMaxDynamicSharedMemorySize, PIPE_SMEM);
    cudaFuncSetAttribute(qtab_mma, cudaFuncAttributeMaxDynamicSharedMemorySize, QT_SMEM);
    cudaFuncSetAttribute(ctx_rel_mma, cudaFuncAttributeMaxDynamicSharedMemorySize, CR_SMEM);

    build_tables<<<(160 * 64 + 255) / 256, 256>>>(rel, tabh, tabl, tTh, tTl);
    embed_ln<<<(int)BS, 256>>>(ids, tti, wemb, temb, elnw, elnb, x, xh, xl);

    {
        int n4 = (int)(WSZ / 4), g = (n4 + 255) / 256;
        split_bf16<<<g, 256>>>(qw, wqh, wql, n4);
        split_bf16<<<g, 256>>>(kw, wkh, wkl, n4);
        split_bf16<<<g, 256>>>(vw, wvh, wvl, n4);
        split_bf16<<<g, 256>>>(ow, woh, wol, n4);
        int n4f = (int)(WFF / 4), gf = (n4f + 255) / 256;
        split_bf16<<<gf, 256>>>(iw, wih, wil, n4f);
        split_bf16<<<gf, 256>>>(dw, wdh, wdl, n4f);
    }

    const dim3 gQKV(D / 128, (int)(BS / 128), 3);
    const dim3 gP(D / 128, (int)(BS / 128), 1);
    const dim3 gF1(FF / 128, (int)(BS / 128), 1);
    const dim3 gSC(S / 128, S / 128, B * H);
    const dim3 gPV(S / 128, 1, B * H);
    const int gRow = (int)(BS * H / 128);      // 768

    for (int l = 0; l < L; l++) {
        const size_t wo = (size_t)l * D * D;
        const size_t fo = (size_t)l * FF * D;

        GemmTargets tq = {};
        tq.wh[0] = wqh + wo; tq.wl[0] = wql + wo; tq.bias[0] = qb + l * D;
        tq.c[0] = nullptr; tq.ch[0] = qh; tq.cl[0] = ql;
        tq.wh[1] = wkh + wo; tq.wl[1] = wkl + wo; tq.bias[1] = kb + l * D;
        tq.c[1] = nullptr; tq.ch[1] = kh; tq.cl[1] = kl;
        tq.wh[2] = wvh + wo; tq.wl[2] = wvl + wo; tq.bias[2] = vb + l * D;
        tq.c[2] = nullptr; tq.ch[2] = vh; tq.cl[2] = vl;
        gemm_mma_pipe<<<gQKV, 256, PIPE_SMEM>>>(xh, xl, tq, (int)BS, D, D, 0);

        qtab_mma<<<gRow, 256, QT_SMEM>>>(qh, ql, tabh, tabl, qt);

        scores_mma<<<gSC, 256>>>(qh, ql, kh, kl, qt, amask, sc);
        softmax_warp<<<(int)(BHS / 8), 256>>>(sc, ph, pl, pth, ptl);

        ctx_rel_mma<<<gRow, 256, CR_SMEM>>>(pth, ptl, tTh, tTl, ctx);
        ctx_pv_mma<<<gPV, 256>>>(ph, pl, vh, vl, ctx, ah, al);

        gemm_mma_pipe_res<<<gP, 256, PIPE_SMEM>>>(ah, al, woh + wo, wol + wo,
                                                  ob + l * D, x, tmp, (int)BS, D, D);
        ln_kernel<<<(int)BS, 256>>>(tmp, alnw + l * D, alnb + l * D, attn, ah, al);

        GemmTargets tf = {};
        tf.wh[0] = wih + fo; tf.wl[0] = wil + fo; tf.bias[0] = ib + l * FF;
        tf.c[0] = nullptr; tf.ch[0] = ffh; tf.cl[0] = ffl;
        gemm_mma_pipe<<<gF1, 256, PIPE_SMEM>>>(ah, al, tf, (int)BS, FF, D, 1);

        gemm_mma_pipe_res<<<gP, 256, PIPE_SMEM>>>(ffh, ffl, wdh + fo, wdl + fo,
                                                  db + l * D, attn, tmp, (int)BS, D, FF);
        ln_kernel<<<(int)BS, 256>>>(tmp, olnw + l * D, olnb + l * D,
                                    (l == L - 1) ? out : x, xh, xl);
    }
}

// round 8
// speedup vs baseline: 1.1950x; 1.0261x over previous
#include <cuda_runtime.h>
#include <cuda_bf16.h>
#include <math.h>
#include <stdint.h>

// ---------------- problem constants ----------------
constexpr int B = 16, S = 512, D = 768, H = 12, FF = 3072, L = 4;
constexpr int DH = 64;
constexpr int NREL = 129;
constexpr int NRELP = 144;        // padded rel dim for bf16 ptab
constexpr float SCALE = 0.125f;
constexpr float LN_EPS = 1e-12f;

constexpr size_t BS   = (size_t)B * S;
constexpr size_t BSD  = BS * D;
constexpr size_t BHS  = (size_t)B * H * S;
constexpr size_t BHSS = BHS * S;

// ---------------- device scratch ----------------
__device__ float g_x[BSD];
__device__ float g_scores[BHSS];
__device__ float g_qtab[BHS * NREL];
__device__ float g_ctx[BSD];
__device__ float g_tmp[BSD];
__device__ float g_attn[BSD];

constexpr size_t WSZ = (size_t)L * D * D;
constexpr size_t WFF = (size_t)L * FF * D;
__device__ __align__(256) __nv_bfloat16 g_wqh[WSZ], g_wql[WSZ];
__device__ __align__(256) __nv_bfloat16 g_wkh[WSZ], g_wkl[WSZ];
__device__ __align__(256) __nv_bfloat16 g_wvh[WSZ], g_wvl[WSZ];
__device__ __align__(256) __nv_bfloat16 g_woh[WSZ], g_wol[WSZ];
__device__ __align__(256) __nv_bfloat16 g_wih[WFF], g_wil[WFF];
__device__ __align__(256) __nv_bfloat16 g_wdh[WFF], g_wdl[WFF];
__device__ __align__(256) __nv_bfloat16 g_xh[BSD], g_xl[BSD];
__device__ __align__(256) __nv_bfloat16 g_qh[BSD], g_ql[BSD];
__device__ __align__(256) __nv_bfloat16 g_kh[BSD], g_kl[BSD];
__device__ __align__(256) __nv_bfloat16 g_vh[BSD], g_vl[BSD];
__device__ __align__(256) __nv_bfloat16 g_ah[BSD], g_al[BSD];
__device__ __align__(256) __nv_bfloat16 g_ffh[BS * FF], g_ffl[BS * FF];
__device__ __align__(256) __nv_bfloat16 g_ph[BHSS], g_pl[BHSS];
__device__ __align__(256) __nv_bfloat16 g_pth[BHS * NRELP], g_ptl[BHS * NRELP];
__device__ __align__(256) __nv_bfloat16 g_tabh[160 * 64], g_tabl[160 * 64];
__device__ __align__(256) __nv_bfloat16 g_tTh[64 * NRELP], g_tTl[64 * NRELP];

// ---------------- helpers ----------------
__device__ __forceinline__ float block_reduce_sum(float v, float* red) {
    int t = threadIdx.x;
    red[t] = v; __syncthreads();
    for (int o = 128; o > 0; o >>= 1) {
        if (t < o) red[t] += red[t + o];
        __syncthreads();
    }
    float r = red[0]; __syncthreads();
    return r;
}

__device__ __forceinline__ void split1(float v, __nv_bfloat16& h, __nv_bfloat16& l) {
    h = __float2bfloat16_rn(v);
    l = __float2bfloat16_rn(v - __bfloat162float(h));
}

__global__ void build_tables(const float* __restrict__ rel,
                             __nv_bfloat16* __restrict__ tabh, __nv_bfloat16* __restrict__ tabl,
                             __nv_bfloat16* __restrict__ tTh, __nv_bfloat16* __restrict__ tTl)
{
    int i = blockIdx.x * 256 + threadIdx.x;
    if (i >= 160 * 64) return;
    int j = i / 64, d = i % 64;
    float v = (j < NREL) ? rel[((size_t)128 * S + (64 + j)) * DH + d] : 0.f;
    __nv_bfloat16 h, l; split1(v, h, l);
    tabh[j * 64 + d] = h; tabl[j * 64 + d] = l;
    if (j < NRELP) { tTh[d * NRELP + j] = h; tTl[d * NRELP + j] = l; }
}

__global__ __launch_bounds__(256) void split_bf16(
    const float* __restrict__ in, __nv_bfloat16* __restrict__ hi,
    __nv_bfloat16* __restrict__ lo, int n4)
{
    int i = blockIdx.x * 256 + threadIdx.x;
    if (i >= n4) return;
    float4 v = ((const float4*)in)[i];
    __nv_bfloat16 h0, h1, h2, h3, l0, l1, l2, l3;
    split1(v.x, h0, l0); split1(v.y, h1, l1);
    split1(v.z, h2, l2); split1(v.w, h3, l3);
    __nv_bfloat162* hp = (__nv_bfloat162*)hi;
    __nv_bfloat162* lp = (__nv_bfloat162*)lo;
    hp[i * 2 + 0] = __nv_bfloat162(h0, h1);
    hp[i * 2 + 1] = __nv_bfloat162(h2, h3);
    lp[i * 2 + 0] = __nv_bfloat162(l0, l1);
    lp[i * 2 + 1] = __nv_bfloat162(l2, l3);
}

// ---------------- mma primitives ----------------
__device__ __forceinline__ void mma16816(float* d, const uint32_t* a, const uint32_t* b) {
    asm volatile(
        "mma.sync.aligned.m16n8k16.row.col.f32.bf16.bf16.f32 "
        "{%0,%1,%2,%3}, {%4,%5,%6,%7}, {%8,%9}, {%0,%1,%2,%3};\n"
        : "+f"(d[0]), "+f"(d[1]), "+f"(d[2]), "+f"(d[3])
        : "r"(a[0]), "r"(a[1]), "r"(a[2]), "r"(a[3]), "r"(b[0]), "r"(b[1]));
}
__device__ __forceinline__ void ldsm4(uint32_t* r, uint32_t addr) {
    asm volatile("ldmatrix.sync.aligned.m8n8.x4.shared.b16 {%0,%1,%2,%3}, [%4];\n"
        : "=r"(r[0]), "=r"(r[1]), "=r"(r[2]), "=r"(r[3]) : "r"(addr));
}
__device__ __forceinline__ void ldsm4t(uint32_t* r, uint32_t addr) {
    asm volatile("ldmatrix.sync.aligned.m8n8.x4.trans.shared.b16 {%0,%1,%2,%3}, [%4];\n"
        : "=r"(r[0]), "=r"(r[1]), "=r"(r[2]), "=r"(r[3]) : "r"(addr));
}
__device__ __forceinline__ void cp16(uint32_t dst, const void* src) {
    asm volatile("cp.async.cg.shared.global [%0], [%1], 16;\n" :: "r"(dst), "l"(src));
}
__device__ __forceinline__ void cp_commit() { asm volatile("cp.async.commit_group;\n"); }
__device__ __forceinline__ void cp_wait1() { asm volatile("cp.async.wait_group 1;\n" ::: "memory"); }
__device__ __forceinline__ void cp_wait0() { asm volatile("cp.async.wait_group 0;\n" ::: "memory"); }
__device__ __forceinline__ uint32_t smem_u32(const void* p) {
    return (uint32_t)__cvta_generic_to_shared(p);
}

// ======================================================================
// R4 pipelined split-bf16 MMA GEMM NT (k16, 3 stages, 73.7KB, 2 CTA/SM)
// ======================================================================
constexpr int ASTR = 24;
constexpr int STG_ARR = 128 * ASTR * 2;   // 6144
constexpr int STG = 4 * STG_ARR;          // 24576
constexpr int NSTAGE = 3;
constexpr int PIPE_SMEM = NSTAGE * STG;   // 73728

struct GemmTargets {
    const __nv_bfloat16* wh[3];
    const __nv_bfloat16* wl[3];
    const float* bias[3];
    float* c[3];
    __nv_bfloat16* ch[3];
    __nv_bfloat16* cl[3];
};

__global__ __launch_bounds__(256) void gemm_mma_pipe(
    const __nv_bfloat16* __restrict__ Ah, const __nv_bfloat16* __restrict__ Al,
    GemmTargets tg, int M, int N, int K, int act)
{
    extern __shared__ __align__(16) char dsm[];
    const uint32_t sbase = smem_u32(dsm);
    const int z = blockIdx.z;
    const __nv_bfloat16* Wh = tg.wh[z];
    const __nv_bfloat16* Wl = tg.wl[z];

    const int bm = blockIdx.y * 128, bn = blockIdx.x * 128;
    const int t = threadIdx.x, lane = t & 31, w = t >> 5;
    const int wm = (w & 1) * 64, wn = (w >> 1) * 32;

    const int grow = t >> 1, gcol = (t & 1) * 8;
    const __nv_bfloat16* pAh = Ah + (size_t)(bm + grow) * K + gcol;
    const __nv_bfloat16* pAl = Al + (size_t)(bm + grow) * K + gcol;
    const __nv_bfloat16* pWh = Wh + (size_t)(bn + grow) * K + gcol;
    const __nv_bfloat16* pWl = Wl + (size_t)(bn + grow) * K + gcol;
    const uint32_t dstoff = (uint32_t)((grow * ASTR + gcol) * 2);

    float acc[4][4][4];
    #pragma unroll
    for (int i = 0; i < 4; i++)
        #pragma unroll
        for (int j = 0; j < 4; j++)
            #pragma unroll
            for (int r = 0; r < 4; r++) acc[i][j][r] = 0.f;

    uint32_t aoff[4], boff[2];
    #pragma unroll
    for (int mi = 0; mi < 4; mi++)
        aoff[mi] = (uint32_t)(((wm + mi * 16 + (lane & 15)) * ASTR + ((lane >> 4) << 3)) * 2);
    #pragma unroll
    for (int ni2 = 0; ni2 < 2; ni2++)
        boff[ni2] = (uint32_t)(((wn + ni2 * 16 + (lane & 7) + ((lane >> 4) << 3)) * ASTR
                               + (((lane >> 3) & 1) << 3)) * 2);

    const int nk = K / 16;
    auto issue = [&](int kt, int slot) {
        if (kt < nk) {
            uint32_t base = sbase + slot * STG + dstoff;
            size_t go = (size_t)kt * 16;
            cp16(base,               pAh + go);
            cp16(base + STG_ARR,     pAl + go);
            cp16(base + 2 * STG_ARR, pWh + go);
            cp16(base + 3 * STG_ARR, pWl + go);
        }
        cp_commit();
    };
    issue(0, 0);
    issue(1, 1);

    for (int kt = 0; kt < nk; kt++) {
        cp_wait1();
        __syncthreads();
        issue(kt + 2, (kt + 2) % NSTAGE);

        const uint32_t sb = sbase + (kt % NSTAGE) * STG;
        uint32_t ah[4][4], al[4][4], bh[4][2], bl[4][2];
        #pragma unroll
        for (int mi = 0; mi < 4; mi++) {
            ldsm4(ah[mi], sb + aoff[mi]);
            ldsm4(al[mi], sb + STG_ARR + aoff[mi]);
        }
        #pragma unroll
        for (int ni2 = 0; ni2 < 2; ni2++) {
            uint32_t t4[4];
            ldsm4(t4, sb + 2 * STG_ARR + boff[ni2]);
            bh[ni2 * 2][0] = t4[0]; bh[ni2 * 2][1] = t4[1];
            bh[ni2 * 2 + 1][0] = t4[2]; bh[ni2 * 2 + 1][1] = t4[3];
            ldsm4(t4, sb + 3 * STG_ARR + boff[ni2]);
            bl[ni2 * 2][0] = t4[0]; bl[ni2 * 2][1] = t4[1];
            bl[ni2 * 2 + 1][0] = t4[2]; bl[ni2 * 2 + 1][1] = t4[3];
        }
        #pragma unroll
        for (int mi = 0; mi < 4; mi++)
            #pragma unroll
            for (int ni = 0; ni < 4; ni++) {
                mma16816(acc[mi][ni], ah[mi], bh[ni]);
                mma16816(acc[mi][ni], ah[mi], bl[ni]);
                mma16816(acc[mi][ni], al[mi], bh[ni]);
            }
        __syncthreads();
    }

    const float* bias = tg.bias[z];
    float* Cp = tg.c[z];
    __nv_bfloat16* Ch = tg.ch[z];
    __nv_bfloat16* Cl = tg.cl[z];

    #pragma unroll
    for (int mi = 0; mi < 4; mi++) {
        int m0 = bm + wm + mi * 16 + (lane >> 2);
        #pragma unroll
        for (int ni = 0; ni < 4; ni++) {
            int n = bn + wn + ni * 8 + (lane & 3) * 2;
            float2 v0 = make_float2(acc[mi][ni][0], acc[mi][ni][1]);
            float2 v1 = make_float2(acc[mi][ni][2], acc[mi][ni][3]);
            if (bias) {
                float2 bv = *(const float2*)&bias[n];
                v0.x += bv.x; v0.y += bv.y; v1.x += bv.x; v1.y += bv.y;
            }
            if (act == 1) {
                v0.x = 0.5f * v0.x * (1.f + erff(v0.x * 0.70710678118654752f));
                v0.y = 0.5f * v0.y * (1.f + erff(v0.y * 0.70710678118654752f));
                v1.x = 0.5f * v1.x * (1.f + erff(v1.x * 0.70710678118654752f));
                v1.y = 0.5f * v1.y * (1.f + erff(v1.y * 0.70710678118654752f));
            }
            if (Cp) {
                *(float2*)&Cp[(size_t)m0 * N + n] = v0;
                *(float2*)&Cp[(size_t)(m0 + 8) * N + n] = v1;
            }
            if (Ch) {
                __nv_bfloat16 h0, l0, h1, l1;
                split1(v0.x, h0, l0); split1(v0.y, h1, l1);
                *(__nv_bfloat162*)&Ch[(size_t)m0 * N + n] = __nv_bfloat162(h0, h1);
                *(__nv_bfloat162*)&Cl[(size_t)m0 * N + n] = __nv_bfloat162(l0, l1);
                split1(v1.x, h0, l0); split1(v1.y, h1, l1);
                *(__nv_bfloat162*)&Ch[(size_t)(m0 + 8) * N + n] = __nv_bfloat162(h0, h1);
                *(__nv_bfloat162*)&Cl[(size_t)(m0 + 8) * N + n] = __nv_bfloat162(l0, l1);
            }
        }
    }
}

__global__ __launch_bounds__(256) void gemm_mma_pipe_res(
    const __nv_bfloat16* __restrict__ Ah, const __nv_bfloat16* __restrict__ Al,
    const __nv_bfloat16* __restrict__ Wh, const __nv_bfloat16* __restrict__ Wl,
    const float* __restrict__ bias, const float* __restrict__ res,
    float* __restrict__ Cp, int M, int N, int K)
{
    extern __shared__ __align__(16) char dsm[];
    const uint32_t sbase = smem_u32(dsm);
    const int bm = blockIdx.y * 128, bn = blockIdx.x * 128;
    const int t = threadIdx.x, lane = t & 31, w = t >> 5;
    const int wm = (w & 1) * 64, wn = (w >> 1) * 32;

    const int grow = t >> 1, gcol = (t & 1) * 8;
    const __nv_bfloat16* pAh = Ah + (size_t)(bm + grow) * K + gcol;
    const __nv_bfloat16* pAl = Al + (size_t)(bm + grow) * K + gcol;
    const __nv_bfloat16* pWh = Wh + (size_t)(bn + grow) * K + gcol;
    const __nv_bfloat16* pWl = Wl + (size_t)(bn + grow) * K + gcol;
    const uint32_t dstoff = (uint32_t)((grow * ASTR + gcol) * 2);

    float acc[4][4][4];
    #pragma unroll
    for (int i = 0; i < 4; i++)
        #pragma unroll
        for (int j = 0; j < 4; j++)
            #pragma unroll
            for (int r = 0; r < 4; r++) acc[i][j][r] = 0.f;

    uint32_t aoff[4], boff[2];
    #pragma unroll
    for (int mi = 0; mi < 4; mi++)
        aoff[mi] = (uint32_t)(((wm + mi * 16 + (lane & 15)) * ASTR + ((lane >> 4) << 3)) * 2);
    #pragma unroll
    for (int ni2 = 0; ni2 < 2; ni2++)
        boff[ni2] = (uint32_t)(((wn + ni2 * 16 + (lane & 7) + ((lane >> 4) << 3)) * ASTR
                               + (((lane >> 3) & 1) << 3)) * 2);

    const int nk = K / 16;
    auto issue = [&](int kt, int slot) {
        if (kt < nk) {
            uint32_t base = sbase + slot * STG + dstoff;
            size_t go = (size_t)kt * 16;
            cp16(base,               pAh + go);
            cp16(base + STG_ARR,     pAl + go);
            cp16(base + 2 * STG_ARR, pWh + go);
            cp16(base + 3 * STG_ARR, pWl + go);
        }
        cp_commit();
    };
    issue(0, 0);
    issue(1, 1);

    for (int kt = 0; kt < nk; kt++) {
        cp_wait1();
        __syncthreads();
        issue(kt + 2, (kt + 2) % NSTAGE);

        const uint32_t sb = sbase + (kt % NSTAGE) * STG;
        uint32_t ah[4][4], al[4][4], bh[4][2], bl[4][2];
        #pragma unroll
        for (int mi = 0; mi < 4; mi++) {
            ldsm4(ah[mi], sb + aoff[mi]);
            ldsm4(al[mi], sb + STG_ARR + aoff[mi]);
        }
        #pragma unroll
        for (int ni2 = 0; ni2 < 2; ni2++) {
            uint32_t t4[4];
            ldsm4(t4, sb + 2 * STG_ARR + boff[ni2]);
            bh[ni2 * 2][0] = t4[0]; bh[ni2 * 2][1] = t4[1];
            bh[ni2 * 2 + 1][0] = t4[2]; bh[ni2 * 2 + 1][1] = t4[3];
            ldsm4(t4, sb + 3 * STG_ARR + boff[ni2]);
            bl[ni2 * 2][0] = t4[0]; bl[ni2 * 2][1] = t4[1];
            bl[ni2 * 2 + 1][0] = t4[2]; bl[ni2 * 2 + 1][1] = t4[3];
        }
        #pragma unroll
        for (int mi = 0; mi < 4; mi++)
            #pragma unroll
            for (int ni = 0; ni < 4; ni++) {
                mma16816(acc[mi][ni], ah[mi], bh[ni]);
                mma16816(acc[mi][ni], ah[mi], bl[ni]);
                mma16816(acc[mi][ni], al[mi], bh[ni]);
            }
        __syncthreads();
    }

    #pragma unroll
    for (int mi = 0; mi < 4; mi++) {
        int m0 = bm + wm + mi * 16 + (lane >> 2);
        #pragma unroll
        for (int ni = 0; ni < 4; ni++) {
            int n = bn + wn + ni * 8 + (lane & 3) * 2;
            float2 v0 = make_float2(acc[mi][ni][0], acc[mi][ni][1]);
            float2 v1 = make_float2(acc[mi][ni][2], acc[mi][ni][3]);
            float2 bv = *(const float2*)&bias[n];
            v0.x += bv.x; v0.y += bv.y; v1.x += bv.x; v1.y += bv.y;
            float2 r0 = *(const float2*)&res[(size_t)m0 * N + n];
            float2 r1 = *(const float2*)&res[(size_t)(m0 + 8) * N + n];
            v0.x += r0.x; v0.y += r0.y; v1.x += r1.x; v1.y += r1.y;
            *(float2*)&Cp[(size_t)m0 * N + n] = v0;
            *(float2*)&Cp[(size_t)(m0 + 8) * N + n] = v1;
        }
    }
}

// ======================================================================
// qtab via warp-MMA (unchanged from R7)
// ======================================================================
constexpr int QT_STR = 72;
constexpr int QT_A = 128 * QT_STR * 2;
constexpr int QT_B = 160 * QT_STR * 2;
constexpr int QT_SMEM = 2 * QT_A + 2 * QT_B;

__global__ __launch_bounds__(256) void qtab_mma(
    const __nv_bfloat16* __restrict__ Qh, const __nv_bfloat16* __restrict__ Ql,
    const __nv_bfloat16* __restrict__ Th, const __nv_bfloat16* __restrict__ Tl,
    float* __restrict__ qt)
{
    extern __shared__ __align__(16) char dsm[];
    __nv_bfloat16* sAh = (__nv_bfloat16*)dsm;
    __nv_bfloat16* sAl = (__nv_bfloat16*)(dsm + QT_A);
    __nv_bfloat16* sBh = (__nv_bfloat16*)(dsm + 2 * QT_A);
    __nv_bfloat16* sBl = (__nv_bfloat16*)(dsm + 2 * QT_A + QT_B);
    const uint32_t bAh = smem_u32(sAh), bAl = smem_u32(sAl);
    const uint32_t bBh = smem_u32(sBh), bBl = smem_u32(sBl);

    const int bm = blockIdx.x * 128;
    const int t = threadIdx.x, lane = t & 31, w = t >> 5;
    const int wm = (w & 3) * 32, wn = (w >> 2) * 80;

    #pragma unroll
    for (int i = 0; i < 4; i++) {
        int s = t + i * 256;
        int row = s >> 3, c8 = s & 7;
        size_t src = (size_t)(bm + row) * 64 + c8 * 8;
        *(uint4*)&sAh[row * QT_STR + c8 * 8] = *(const uint4*)&Qh[src];
        *(uint4*)&sAl[row * QT_STR + c8 * 8] = *(const uint4*)&Ql[src];
    }
    #pragma unroll
    for (int i = 0; i < 5; i++) {
        int s = t + i * 256;
        int row = s >> 3, c8 = s & 7;
        *(uint4*)&sBh[row * QT_STR + c8 * 8] = *(const uint4*)&Th[row * 64 + c8 * 8];
        *(uint4*)&sBl[row * QT_STR + c8 * 8] = *(const uint4*)&Tl[row * 64 + c8 * 8];
    }
    __syncthreads();

    float acc[2][10][4];
    #pragma unroll
    for (int i = 0; i < 2; i++)
        #pragma unroll
        for (int j = 0; j < 10; j++)
            #pragma unroll
            for (int r = 0; r < 4; r++) acc[i][j][r] = 0.f;

    uint32_t aoff[2], boff[5];
    #pragma unroll
    for (int mi = 0; mi < 2; mi++)
        aoff[mi] = (uint32_t)(((wm + mi * 16 + (lane & 15)) * QT_STR + ((lane >> 4) << 3)) * 2);
    #pragma unroll
    for (int ni2 = 0; ni2 < 5; ni2++)
        boff[ni2] = (uint32_t)(((wn + ni2 * 16 + (lane & 7) + ((lane >> 4) << 3)) * QT_STR
                               + (((lane >> 3) & 1) << 3)) * 2);

    #pragma unroll
    for (int kc = 0; kc < 4; kc++) {
        uint32_t ko = kc * 32;
        uint32_t ah[2][4], al[2][4];
        #pragma unroll
        for (int mi = 0; mi < 2; mi++) {
            ldsm4(ah[mi], bAh + aoff[mi] + ko);
            ldsm4(al[mi], bAl + aoff[mi] + ko);
        }
        #pragma unroll
        for (int ni2 = 0; ni2 < 5; ni2++) {
            uint32_t th4[4], tl4[4];
            ldsm4(th4, bBh + boff[ni2] + ko);
            ldsm4(tl4, bBl + boff[ni2] + ko);
            uint32_t bh0[2] = {th4[0], th4[1]}, bh1[2] = {th4[2], th4[3]};
            uint32_t bl0[2] = {tl4[0], tl4[1]}, bl1[2] = {tl4[2], tl4[3]};
            #pragma unroll
            for (int mi = 0; mi < 2; mi++) {
                mma16816(acc[mi][ni2 * 2], ah[mi], bh0);
                mma16816(acc[mi][ni2 * 2], ah[mi], bl0);
                mma16816(acc[mi][ni2 * 2], al[mi], bh0);
                mma16816(acc[mi][ni2 * 2 + 1], ah[mi], bh1);
                mma16816(acc[mi][ni2 * 2 + 1], ah[mi], bl1);
                mma16816(acc[mi][ni2 * 2 + 1], al[mi], bh1);
            }
        }
    }

    #pragma unroll
    for (int mi = 0; mi < 2; mi++)
        #pragma unroll
        for (int rr = 0; rr < 2; rr++) {
            int m0 = bm + wm + mi * 16 + (lane >> 2) + rr * 8;
            #pragma unroll
            for (int ni = 0; ni < 10; ni++) {
                int n = wn + ni * 8 + (lane & 3) * 2;
                if (n < NREL)     qt[(size_t)m0 * NREL + n]     = acc[mi][ni][rr * 2 + 0];
                if (n + 1 < NREL) qt[(size_t)m0 * NREL + n + 1] = acc[mi][ni][rr * 2 + 1];
            }
        }
}

// ======================================================================
// ctx_rel via warp-MMA (unchanged from R7)
// ======================================================================
constexpr int CR_ASTR = 56;
constexpr int CR_BSTR = 152;
constexpr int CR_A = 128 * CR_ASTR * 2;
constexpr int CR_B = 64 * CR_BSTR * 2;
constexpr int CR_SMEM = 2 * CR_A + 2 * CR_B;

__global__ __launch_bounds__(256) void ctx_rel_mma(
    const __nv_bfloat16* __restrict__ Ph, const __nv_bfloat16* __restrict__ Pl,
    const __nv_bfloat16* __restrict__ Th, const __nv_bfloat16* __restrict__ Tl,
    float* __restrict__ ctx)
{
    extern __shared__ __align__(16) char dsm[];
    __nv_bfloat16* sAh = (__nv_bfloat16*)dsm;
    __nv_bfloat16* sAl = (__nv_bfloat16*)(dsm + CR_A);
    __nv_bfloat16* sBh = (__nv_bfloat16*)(dsm + 2 * CR_A);
    __nv_bfloat16* sBl = (__nv_bfloat16*)(dsm + 2 * CR_A + CR_B);
    const uint32_t bAh = smem_u32(sAh), bAl = smem_u32(sAl);
    const uint32_t bBh = smem_u32(sBh), bBl = smem_u32(sBl);

    const int bm = blockIdx.x * 128;
    const int t = threadIdx.x, lane = t & 31, w = t >> 5;
    const int wm = (w & 3) * 32, wn = (w >> 2) * 32;

    for (int s = t; s < 1152; s += 256) {
        int row = s / 18, c8 = s % 18;
        *(uint4*)&sBh[row * CR_BSTR + c8 * 8] = *(const uint4*)&Th[row * NRELP + c8 * 8];
        *(uint4*)&sBl[row * CR_BSTR + c8 * 8] = *(const uint4*)&Tl[row * NRELP + c8 * 8];
    }

    float acc[2][4][4];
    #pragma unroll
    for (int i = 0; i < 2; i++)
        #pragma unroll
        for (int j = 0; j < 4; j++)
            #pragma unroll
            for (int r = 0; r < 4; r++) acc[i][j][r] = 0.f;

    uint32_t aoff[2], boff[2];
    #pragma unroll
    for (int mi = 0; mi < 2; mi++)
        aoff[mi] = (uint32_t)(((wm + mi * 16 + (lane & 15)) * CR_ASTR + ((lane >> 4) << 3)) * 2);
    #pragma unroll
    for (int ni2 = 0; ni2 < 2; ni2++)
        boff[ni2] = (uint32_t)(((wn + ni2 * 16 + (lane & 7) + ((lane >> 4) << 3)) * CR_BSTR
                               + (((lane >> 3) & 1) << 3)) * 2);

    for (int c = 0; c < 3; c++) {
        __syncthreads();
        #pragma unroll
        for (int i = 0; i < 3; i++) {
            int s = t + i * 256;
            int row = s / 6, c8 = s % 6;
            size_t src = (size_t)(bm + row) * NRELP + c * 48 + c8 * 8;
            *(uint4*)&sAh[row * CR_ASTR + c8 * 8] = *(const uint4*)&Ph[src];
            *(uint4*)&sAl[row * CR_ASTR + c8 * 8] = *(const uint4*)&Pl[src];
        }
        __syncthreads();
        #pragma unroll
        for (int kc = 0; kc < 3; kc++) {
            uint32_t kaoff = kc * 32;
            uint32_t kboff = (uint32_t)(c * 96 + kc * 32);
            uint32_t ah[2][4], al[2][4];
            #pragma unroll
            for (int mi = 0; mi < 2; mi++) {
                ldsm4(ah[mi], bAh + aoff[mi] + kaoff);
                ldsm4(al[mi], bAl + aoff[mi] + kaoff);
            }
            #pragma unroll
            for (int ni2 = 0; ni2 < 2; ni2++) {
                uint32_t th4[4], tl4[4];
                ldsm4(th4, bBh + boff[ni2] + kboff);
                ldsm4(tl4, bBl + boff[ni2] + kboff);
                uint32_t bh0[2] = {th4[0], th4[1]}, bh1[2] = {th4[2], th4[3]};
                uint32_t bl0[2] = {tl4[0], tl4[1]}, bl1[2] = {tl4[2], tl4[3]};
                #pragma unroll
                for (int mi = 0; mi < 2; mi++) {
                    mma16816(acc[mi][ni2 * 2], ah[mi], bh0);
                    mma16816(acc[mi][ni2 * 2], ah[mi], bl0);
                    mma16816(acc[mi][ni2 * 2], al[mi], bh0);
                    mma16816(acc[mi][ni2 * 2 + 1], ah[mi], bh1);
                    mma16816(acc[mi][ni2 * 2 + 1], ah[mi], bl1);
                    mma16816(acc[mi][ni2 * 2 + 1], al[mi], bh1);
                }
            }
        }
    }

    #pragma unroll
    for (int mi = 0; mi < 2; mi++)
        #pragma unroll
        for (int rr = 0; rr < 2; rr++) {
            int m0 = bm + wm + mi * 16 + (lane >> 2) + rr * 8;
            #pragma unroll
            for (int ni = 0; ni < 4; ni++) {
                int n = wn + ni * 8 + (lane & 3) * 2;
                float2 v = make_float2(acc[mi][ni][rr * 2 + 0], acc[mi][ni][rr * 2 + 1]);
                *(float2*)&ctx[(size_t)m0 * 64 + n] = v;
            }
        }
}

// ======================================================================
// Scores MMA with cp.async double buffer (2 stages, dynamic smem)
// Stage holds 32 k-cols of Qh/Ql/Kh/Kl at stride 40.
// ======================================================================
constexpr int QSTR = 40;
constexpr int SC_ARR = 128 * QSTR * 2;    // 10240 per array
constexpr int SC_STG = 4 * SC_ARR;        // 40960 per stage
constexpr int SC_SMEM = 2 * SC_STG;       // 81920

__global__ __launch_bounds__(256) void scores_mma(
    const __nv_bfloat16* __restrict__ Qh, const __nv_bfloat16* __restrict__ Ql,
    const __nv_bfloat16* __restrict__ Kh, const __nv_bfloat16* __restrict__ Kl,
    const float* __restrict__ qtab, const int* __restrict__ mask,
    float* __restrict__ scores)
{
    extern __shared__ __align__(16) char dsm[];
    const uint32_t sbase = smem_u32(dsm);
    const int bh = blockIdx.z, b = bh / H, h = bh % H;
    const int q0 = blockIdx.y * 128, k0b = blockIdx.x * 128;
    const int t = threadIdx.x, lane = t & 31, w = t >> 5;
    const int wm = (w & 1) * 64, wn = (w >> 1) * 32;

    float acc[4][4][4];
    #pragma unroll
    for (int i = 0; i < 4; i++)
        #pragma unroll
        for (int j = 0; j < 4; j++)
            #pragma unroll
            for (int r = 0; r < 4; r++) acc[i][j][r] = 0.f;

    uint32_t aoff[4], boff[2];
    #pragma unroll
    for (int mi = 0; mi < 4; mi++)
        aoff[mi] = (uint32_t)(((wm + mi * 16 + (lane & 15)) * QSTR + ((lane >> 4) << 3)) * 2);
    #pragma unroll
    for (int ni2 = 0; ni2 < 2; ni2++)
        boff[ni2] = (uint32_t)(((wn + ni2 * 16 + (lane & 7) + ((lane >> 4) << 3)) * QSTR
                               + (((lane >> 3) & 1) << 3)) * 2);

    // per-thread loads: 2 segs per array
    auto issue = [&](int kt) {
        uint32_t base = sbase + kt * SC_STG;
        #pragma unroll
        for (int i = 0; i < 2; i++) {
            int idx = t * 2 + i;
            int row = idx >> 2, cseg = (idx & 3) * 8;
            size_t qsrc = ((size_t)(b * S) + q0 + row) * D + h * DH + kt * 32 + cseg;
            size_t ksrc = ((size_t)(b * S) + k0b + row) * D + h * DH + kt * 32 + cseg;
            uint32_t d = base + (uint32_t)((row * QSTR + cseg) * 2);
            cp16(d,              Qh + qsrc);
            cp16(d + SC_ARR,     Ql + qsrc);
            cp16(d + 2 * SC_ARR, Kh + ksrc);
            cp16(d + 3 * SC_ARR, Kl + ksrc);
        }
        cp_commit();
    };
    issue(0);
    issue(1);

    for (int kt = 0; kt < 2; kt++) {
        if (kt == 0) cp_wait1(); else cp_wait0();
        __syncthreads();
        const uint32_t sb = sbase + kt * SC_STG;
        #pragma unroll
        for (int kk2 = 0; kk2 < 2; kk2++) {
            uint32_t koffb = kk2 * 32;
            uint32_t ah[4][4], al[4][4], bhf[4][2], blf[4][2];
            #pragma unroll
            for (int mi = 0; mi < 4; mi++) {
                ldsm4(ah[mi], sb + aoff[mi] + koffb);
                ldsm4(al[mi], sb + SC_ARR + aoff[mi] + koffb);
            }
            #pragma unroll
            for (int ni2 = 0; ni2 < 2; ni2++) {
                uint32_t t4[4];
                ldsm4(t4, sb + 2 * SC_ARR + boff[ni2] + koffb);
                bhf[ni2 * 2][0] = t4[0]; bhf[ni2 * 2][1] = t4[1];
                bhf[ni2 * 2 + 1][0] = t4[2]; bhf[ni2 * 2 + 1][1] = t4[3];
                ldsm4(t4, sb + 3 * SC_ARR + boff[ni2] + koffb);
                blf[ni2 * 2][0] = t4[0]; blf[ni2 * 2][1] = t4[1];
                blf[ni2 * 2 + 1][0] = t4[2]; blf[ni2 * 2 + 1][1] = t4[3];
            }
            #pragma unroll
            for (int mi = 0; mi < 4; mi++)
                #pragma unroll
                for (int ni = 0; ni < 4; ni++) {
                    mma16816(acc[mi][ni], ah[mi], bhf[ni]);
                    mma16816(acc[mi][ni], ah[mi], blf[ni]);
                    mma16816(acc[mi][ni], al[mi], bhf[ni]);
                }
        }
    }

    #pragma unroll
    for (int mi = 0; mi < 4; mi++) {
        #pragma unroll
        for (int rr = 0; rr < 2; rr++) {
            int q = q0 + wm + mi * 16 + (lane >> 2) + rr * 8;
            const float* qtr = qtab + (((size_t)b * S + q) * H + h) * NREL;
            size_t rowb = ((size_t)bh * S + q) * S;
            #pragma unroll
            for (int ni = 0; ni < 4; ni++) {
                int k = k0b + wn + ni * 8 + (lane & 3) * 2;
                float vx = acc[mi][ni][rr * 2 + 0];
                float vy = acc[mi][ni][rr * 2 + 1];
                int r0 = k - q; r0 = r0 < -64 ? -64 : (r0 > 64 ? 64 : r0);
                int r1 = k + 1 - q; r1 = r1 < -64 ? -64 : (r1 > 64 ? 64 : r1);
                float mb0 = (1.f - (float)mask[b * S + k]) * -10000.f;
                float mb1 = (1.f - (float)mask[b * S + k + 1]) * -10000.f;
                float2 o;
                o.x = (vx + qtr[r0 + 64]) * SCALE + mb0;
                o.y = (vy + qtr[r1 + 64]) * SCALE + mb1;
                *(float2*)&scores[rowb + k] = o;
            }
        }
    }
}

// ======================================================================
// ctx_pv with cp.async 3-stage pipeline (dynamic smem).
// ctx_out(hi/lo bf16) = probs@V + ctx_rel(fp32). Tile 128q x 64d, k-tile 32.
// ======================================================================
constexpr int VSTR = 72;
constexpr int PV_P = 128 * QSTR * 2;      // 10240 per P array
constexpr int PV_V = 32 * VSTR * 2;       // 4608 per V array
constexpr int PV_STG = 2 * PV_P + 2 * PV_V;  // 29696 per stage
constexpr int PV_NSTG = 3;
constexpr int PV_SMEM = PV_NSTG * PV_STG;    // 89088

__global__ __launch_bounds__(256) void ctx_pv_mma(
    const __nv_bfloat16* __restrict__ Ph, const __nv_bfloat16* __restrict__ Pl,
    const __nv_bfloat16* __restrict__ Vh, const __nv_bfloat16* __restrict__ Vl,
    const float* __restrict__ ctxin,
    __nv_bfloat16* __restrict__ outh, __nv_bfloat16* __restrict__ outl)
{
    extern __shared__ __align__(16) char dsm[];
    const uint32_t sbase = smem_u32(dsm);
    const int bh = blockIdx.z, b = bh / H, h = bh % H;
    const int q0 = blockIdx.x * 128;
    const int t = threadIdx.x, lane = t & 31, w = t >> 5;
    const int wm = (w & 3) * 32, wn = (w >> 2) * 32;

    float acc[2][4][4];
    #pragma unroll
    for (int i = 0; i < 2; i++)
        #pragma unroll
        for (int j = 0; j < 4; j++)
            #pragma unroll
            for (int r = 0; r < 4; r++) acc[i][j][r] = 0.f;

    uint32_t aoff[2];
    #pragma unroll
    for (int mi = 0; mi < 2; mi++)
        aoff[mi] = (uint32_t)(((wm + mi * 16 + (lane & 15)) * QSTR + ((lane >> 4) << 3)) * 2);

    const int nk = S / 32;   // 16

    auto issue = [&](int kt, int slot) {
        if (kt < nk) {
            uint32_t base = sbase + slot * PV_STG;
            #pragma unroll
            for (int i = 0; i < 2; i++) {
                int idx = t * 2 + i;
                int row = idx >> 2, cseg = (idx & 3) * 8;
                size_t psrc = ((size_t)bh * S + q0 + row) * S + kt * 32 + cseg;
                uint32_t d = base + (uint32_t)((row * QSTR + cseg) * 2);
                cp16(d,        Ph + psrc);
                cp16(d + PV_P, Pl + psrc);
            }
            {
                int row = t >> 3, cseg = (t & 7) * 8;
                size_t vsrc = ((size_t)(b * S) + kt * 32 + row) * D + h * DH + cseg;
                uint32_t d = base + 2 * PV_P + (uint32_t)((row * VSTR + cseg) * 2);
                cp16(d,        Vh + vsrc);
                cp16(d + PV_V, Vl + vsrc);
            }
        }
        cp_commit();
    };
    issue(0, 0);
    issue(1, 1);

    for (int kt = 0; kt < nk; kt++) {
        cp_wait1();
        __syncthreads();
        issue(kt + 2, (kt + 2) % PV_NSTG);

        const uint32_t sb = sbase + (kt % PV_NSTG) * PV_STG;
        #pragma unroll
        for (int kk2 = 0; kk2 < 2; kk2++) {
            uint32_t koffb = kk2 * 32;
            uint32_t ah[2][4], al[2][4], bhf[4][2], blf[4][2];
            #pragma unroll
            for (int mi = 0; mi < 2; mi++) {
                ldsm4(ah[mi], sb + aoff[mi] + koffb);
                ldsm4(al[mi], sb + PV_P + aoff[mi] + koffb);
            }
            #pragma unroll
            for (int ni2 = 0; ni2 < 2; ni2++) {
                uint32_t vaddr = (uint32_t)(((kk2 * 16 + (lane & 15)) * VSTR
                                 + wn + ni2 * 16 + (lane >> 4) * 8) * 2);
                uint32_t t4[4];
                ldsm4t(t4, sb + 2 * PV_P + vaddr);
                bhf[ni2 * 2][0] = t4[0]; bhf[ni2 * 2][1] = t4[1];
                bhf[ni2 * 2 + 1][0] = t4[2]; bhf[ni2 * 2 + 1][1] = t4[3];
                ldsm4t(t4, sb + 2 * PV_P + PV_V + vaddr);
                blf[ni2 * 2][0] = t4[0]; blf[ni2 * 2][1] = t4[1];
                blf[ni2 * 2 + 1][0] = t4[2]; blf[ni2 * 2 + 1][1] = t4[3];
            }
            #pragma unroll
            for (int mi = 0; mi < 2; mi++)
                #pragma unroll
                for (int ni = 0; ni < 4; ni++) {
                    mma16816(acc[mi][ni], ah[mi], bhf[ni]);
                    mma16816(acc[mi][ni], ah[mi], blf[ni]);
                    mma16816(acc[mi][ni], al[mi], bhf[ni]);
                }
        }
        __syncthreads();
    }

    #pragma unroll
    for (int mi = 0; mi < 2; mi++) {
        #pragma unroll
        for (int rr = 0; rr < 2; rr++) {
            int q = q0 + wm + mi * 16 + (lane >> 2) + rr * 8;
            size_t rb = ((size_t)(b * S) + q) * D + h * DH;
            #pragma unroll
            for (int ni = 0; ni < 4; ni++) {
                int d = wn + ni * 8 + (lane & 3) * 2;
                float2 cur = *(const float2*)&ctxin[rb + d];
                cur.x += acc[mi][ni][rr * 2 + 0];
                cur.y += acc[mi][ni][rr * 2 + 1];
                __nv_bfloat16 h0, l0, h1, l1;
                split1(cur.x, h0, l0); split1(cur.y, h1, l1);
                *(__nv_bfloat162*)&outh[rb + d] = __nv_bfloat162(h0, h1);
                *(__nv_bfloat162*)&outl[rb + d] = __nv_bfloat162(l0, l1);
            }
        }
    }
}

// ---------------- embedding + LN ----------------
__global__ __launch_bounds__(256) void embed_ln(
    const int* __restrict__ ids, const int* __restrict__ tti,
    const float* __restrict__ we, const float* __restrict__ te,
    const float* __restrict__ w, const float* __restrict__ bb,
    float* __restrict__ out, __nv_bfloat16* __restrict__ oh,
    __nv_bfloat16* __restrict__ ol)
{
    __shared__ float red[256];
    int m = blockIdx.x, t = threadIdx.x;
    int id = ids[m], t2 = tti[m];
    const float* wr = we + (size_t)id * D;
    const float* tr = te + (size_t)t2 * D;
    float vals[3]; float s = 0.f;
    #pragma unroll
    for (int i = 0; i < 3; i++) { int d = t + i * 256; vals[i] = wr[d] + tr[d]; s += vals[i]; }
    float mean = block_reduce_sum(s, red) * (1.f / D);
    float vs = 0.f;
    #pragma unroll
    for (int i = 0; i < 3; i++) { float dd = vals[i] - mean; vs += dd * dd; }
    float var = block_reduce_sum(vs, red) * (1.f / D);
    float rstd = rsqrtf(var + LN_EPS);
    #pragma unroll
    for (int i = 0; i < 3; i++) {
        int d = t + i * 256;
        float v = (vals[i] - mean) * rstd * w[d] + bb[d];
        out[(size_t)m * D + d] = v;
        __nv_bfloat16 h, l; split1(v, h, l);
        oh[(size_t)m * D + d] = h;
        ol[(size_t)m * D + d] = l;
    }
}

__global__ __launch_bounds__(256) void ln_kernel(
    const float* __restrict__ x, const float* __restrict__ w,
    const float* __restrict__ bb, float* __restrict__ out,
    __nv_bfloat16* __restrict__ oh, __nv_bfloat16* __restrict__ ol)
{
    __shared__ float red[256];
    int m = blockIdx.x, t = threadIdx.x;
    const float* xr = x + (size_t)m * D;
    float vals[3]; float s = 0.f;
    #pragma unroll
    for (int i = 0; i < 3; i++) { vals[i] = xr[t + i * 256]; s += vals[i]; }
    float mean = block_reduce_sum(s, red) * (1.f / D);
    float vs = 0.f;
    #pragma unroll
    for (int i = 0; i < 3; i++) { float dd = vals[i] - mean; vs += dd * dd; }
    float var = block_reduce_sum(vs, red) * (1.f / D);
    float rstd = rsqrtf(var + LN_EPS);
    #pragma unroll
    for (int i = 0; i < 3; i++) {
        int d = t + i * 256;
        float v = (vals[i] - mean) * rstd * w[d] + bb[d];
        out[(size_t)m * D + d] = v;
        __nv_bfloat16 h, l; split1(v, h, l);
        oh[(size_t)m * D + d] = h;
        ol[(size_t)m * D + d] = l;
    }
}

// ---------------- warp-per-row softmax (unchanged from R7) ----------------
__global__ __launch_bounds__(256) void softmax_warp(
    const float* __restrict__ scores,
    __nv_bfloat16* __restrict__ ph, __nv_bfloat16* __restrict__ pl,
    __nv_bfloat16* __restrict__ pth, __nv_bfloat16* __restrict__ ptl)
{
    __shared__ float srow[8][512];
    const int w = threadIdx.x >> 5, lane = threadIdx.x & 31;
    const int row = blockIdx.x * 8 + w;
    const int q = row % S, bh = row / S;
    const int b = bh / H, h = bh % H;
    const float* sr = scores + (size_t)row * S;

    float2 v[8];
    float m = -1e30f;
    #pragma unroll
    for (int i = 0; i < 8; i++) {
        v[i] = *(const float2*)&sr[lane * 2 + 64 * i];
        m = fmaxf(m, fmaxf(v[i].x, v[i].y));
    }
    #pragma unroll
    for (int o = 16; o > 0; o >>= 1) m = fmaxf(m, __shfl_xor_sync(0xffffffffu, m, o));

    float s = 0.f;
    #pragma unroll
    for (int i = 0; i < 8; i++) {
        v[i].x = expf(v[i].x - m); v[i].y = expf(v[i].y - m);
        s += v[i].x + v[i].y;
    }
    #pragma unroll
    for (int o = 16; o > 0; o >>= 1) s += __shfl_xor_sync(0xffffffffu, s, o);
    float inv = 1.f / s;

    size_t rb = (size_t)row * S;
    float left = 0.f, right = 0.f;
    #pragma unroll
    for (int i = 0; i < 8; i++) {
        int k = lane * 2 + 64 * i;
        float p0 = v[i].x * inv, p1 = v[i].y * inv;
        srow[w][k] = p0; srow[w][k + 1] = p1;
        __nv_bfloat16 h0, l0, h1, l1;
        split1(p0, h0, l0); split1(p1, h1, l1);
        *(__nv_bfloat162*)&ph[rb + k] = __nv_bfloat162(h0, h1);
        *(__nv_bfloat162*)&pl[rb + k] = __nv_bfloat162(l0, l1);
        if (k <= q - 64)     left += p0;
        if (k + 1 <= q - 64) left += p1;
        if (k >= q + 64)     right += p0;
        if (k + 1 >= q + 64) right += p1;
    }
    #pragma unroll
    for (int o = 16; o > 0; o >>= 1) {
        left  += __shfl_xor_sync(0xffffffffu, left, o);
        right += __shfl_xor_sync(0xffffffffu, right, o);
    }
    __syncwarp();

    size_t pbase = ((size_t)(b * S + q) * H + h) * NRELP;
    __nv_bfloat16 hh, ll;
    if (lane == 0) {
        split1(left, hh, ll);  pth[pbase] = hh;       ptl[pbase] = ll;
        split1(right, hh, ll); pth[pbase + 128] = hh; ptl[pbase + 128] = ll;
    }
    if (lane < 15) {
        pth[pbase + 129 + lane] = __float2bfloat16(0.f);
        ptl[pbase + 129 + lane] = __float2bfloat16(0.f);
    }
    #pragma unroll
    for (int jj = 0; jj < 4; jj++) {
        int j = 1 + lane + 32 * jj;
        if (j <= 127) {
            int k = q + j - 64;
            float p = (k >= 0 && k < S) ? srow[w][k] : 0.f;
            split1(p, hh, ll);
            pth[pbase + j] = hh; ptl[pbase + j] = ll;
        }
    }
}

// ---------------- launch ----------------
extern "C" void kernel_launch(void* const* d_in, const int* in_sizes, int n_in,
                              void* d_out, int out_size)
{
    const int*   ids     = (const int*)d_in[0];
    const int*   amask   = (const int*)d_in[1];
    const int*   tti     = (const int*)d_in[2];
    const float* wemb    = (const float*)d_in[3];
    const float* temb    = (const float*)d_in[4];
    const float* elnw    = (const float*)d_in[5];
    const float* elnb    = (const float*)d_in[6];
    const float* qw      = (const float*)d_in[7];
    const float* qb      = (const float*)d_in[8];
    const float* kw      = (const float*)d_in[9];
    const float* kb      = (const float*)d_in[10];
    const float* vw      = (const float*)d_in[11];
    const float* vb      = (const float*)d_in[12];
    const float* rel     = (const float*)d_in[13];
    const float* ow      = (const float*)d_in[14];
    const float* ob      = (const float*)d_in[15];
    const float* alnw    = (const float*)d_in[16];
    const float* alnb    = (const float*)d_in[17];
    const float* iw      = (const float*)d_in[18];
    const float* ib      = (const float*)d_in[19];
    const float* dw      = (const float*)d_in[20];
    const float* db      = (const float*)d_in[21];
    const float* olnw    = (const float*)d_in[22];
    const float* olnb    = (const float*)d_in[23];
    float* out = (float*)d_out;

    float *x, *sc, *qt, *ctx, *tmp, *attn;
    cudaGetSymbolAddress((void**)&x,    g_x);
    cudaGetSymbolAddress((void**)&sc,   g_scores);
    cudaGetSymbolAddress((void**)&qt,   g_qtab);
    cudaGetSymbolAddress((void**)&ctx,  g_ctx);
    cudaGetSymbolAddress((void**)&tmp,  g_tmp);
    cudaGetSymbolAddress((void**)&attn, g_attn);

    __nv_bfloat16 *wqh, *wql, *wkh, *wkl, *wvh, *wvl, *woh, *wol;
    __nv_bfloat16 *wih, *wil, *wdh, *wdl;
    __nv_bfloat16 *xh, *xl, *qh, *ql, *kh, *kl, *vh, *vl, *ah, *al, *ffh, *ffl, *ph, *pl;
    __nv_bfloat16 *pth, *ptl, *tabh, *tabl, *tTh, *tTl;
    cudaGetSymbolAddress((void**)&wqh, g_wqh); cudaGetSymbolAddress((void**)&wql, g_wql);
    cudaGetSymbolAddress((void**)&wkh, g_wkh); cudaGetSymbolAddress((void**)&wkl, g_wkl);
    cudaGetSymbolAddress((void**)&wvh, g_wvh); cudaGetSymbolAddress((void**)&wvl, g_wvl);
    cudaGetSymbolAddress((void**)&woh, g_woh); cudaGetSymbolAddress((void**)&wol, g_wol);
    cudaGetSymbolAddress((void**)&wih, g_wih); cudaGetSymbolAddress((void**)&wil, g_wil);
    cudaGetSymbolAddress((void**)&wdh, g_wdh); cudaGetSymbolAddress((void**)&wdl, g_wdl);
    cudaGetSymbolAddress((void**)&xh,  g_xh);  cudaGetSymbolAddress((void**)&xl,  g_xl);
    cudaGetSymbolAddress((void**)&qh,  g_qh);  cudaGetSymbolAddress((void**)&ql,  g_ql);
    cudaGetSymbolAddress((void**)&kh,  g_kh);  cudaGetSymbolAddress((void**)&kl,  g_kl);
    cudaGetSymbolAddress((void**)&vh,  g_vh);  cudaGetSymbolAddress((void**)&vl,  g_vl);
    cudaGetSymbolAddress((void**)&ah,  g_ah);  cudaGetSymbolAddress((void**)&al,  g_al);
    cudaGetSymbolAddress((void**)&ffh, g_ffh); cudaGetSymbolAddress((void**)&ffl, g_ffl);
    cudaGetSymbolAddress((void**)&ph,  g_ph);  cudaGetSymbolAddress((void**)&pl,  g_pl);
    cudaGetSymbolAddress((void**)&pth, g_pth); cudaGetSymbolAddress((void**)&ptl, g_ptl);
    cudaGetSymbolAddress((void**)&tabh, g_tabh); cudaGetSymbolAddress((void**)&tabl, g_tabl);
    cudaGetSymbolAddress((void**)&tTh, g_tTh); cudaGetSymbolAddress((void**)&tTl, g_tTl);

    cudaFuncSetAttribute(gemm_mma_pipe, cudaFuncAttributeMaxDynamicSharedMemorySize, PIPE_SMEM);
    cudaFuncSetAttribute(gemm_mma_pipe_res, cudaFuncAttributeMaxDynamicSharedMemorySize, PIPE_SMEM);
    cudaFuncSetAttribute(qtab_mma, cudaFuncAttributeMaxDynamicSharedMemorySize, QT_SMEM);
    cudaFuncSetAttribute(ctx_rel_mma, cudaFuncAttributeMaxDynamicSharedMemorySize, CR_SMEM);
    cudaFuncSetAttribute(scores_mma, cudaFuncAttributeMaxDynamicSharedMemorySize, SC_SMEM);
    cudaFuncSetAttribute(ctx_pv_mma, cudaFuncAttributeMaxDynamicSharedMemorySize, PV_SMEM);

    build_tables<<<(160 * 64 + 255) / 256, 256>>>(rel, tabh, tabl, tTh, tTl);
    embed_ln<<<(int)BS, 256>>>(ids, tti, wemb, temb, elnw, elnb, x, xh, xl);

    {
        int n4 = (int)(WSZ / 4), g = (n4 + 255) / 256;
        split_bf16<<<g, 256>>>(qw, wqh, wql, n4);
        split_bf16<<<g, 256>>>(kw, wkh, wkl, n4);
        split_bf16<<<g, 256>>>(vw, wvh, wvl, n4);
        split_bf16<<<g, 256>>>(ow, woh, wol, n4);
        int n4f = (int)(WFF / 4), gf = (n4f + 255) / 256;
        split_bf16<<<gf, 256>>>(iw, wih, wil, n4f);
        split_bf16<<<gf, 256>>>(dw, wdh, wdl, n4f);
    }

    const dim3 gQKV(D / 128, (int)(BS / 128), 3);
    const dim3 gP(D / 128, (int)(BS / 128), 1);
    const dim3 gF1(FF / 128, (int)(BS / 128), 1);
    const dim3 gSC(S / 128, S / 128, B * H);
    const dim3 gPV(S / 128, 1, B * H);
    const int gRow = (int)(BS * H / 128);

    for (int l = 0; l < L; l++) {
        const size_t wo = (size_t)l * D * D;
        const size_t fo = (size_t)l * FF * D;

        GemmTargets tq = {};
        tq.wh[0] = wqh + wo; tq.wl[0] = wql + wo; tq.bias[0] = qb + l * D;
        tq.c[0] = nullptr; tq.ch[0] = qh; tq.cl[0] = ql;
        tq.wh[1] = wkh + wo; tq.wl[1] = wkl + wo; tq.bias[1] = kb + l * D;
        tq.c[1] = nullptr; tq.ch[1] = kh; tq.cl[1] = kl;
        tq.wh[2] = wvh + wo; tq.wl[2] = wvl + wo; tq.bias[2] = vb + l * D;
        tq.c[2] = nullptr; tq.ch[2] = vh; tq.cl[2] = vl;
        gemm_mma_pipe<<<gQKV, 256, PIPE_SMEM>>>(xh, xl, tq, (int)BS, D, D, 0);

        qtab_mma<<<gRow, 256, QT_SMEM>>>(qh, ql, tabh, tabl, qt);

        scores_mma<<<gSC, 256, SC_SMEM>>>(qh, ql, kh, kl, qt, amask, sc);
        softmax_warp<<<(int)(BHS / 8), 256>>>(sc, ph, pl, pth, ptl);

        ctx_rel_mma<<<gRow, 256, CR_SMEM>>>(pth, ptl, tTh, tTl, ctx);
        ctx_pv_mma<<<gPV, 256, PV_SMEM>>>(ph, pl, vh, vl, ctx, ah, al);

        gemm_mma_pipe_res<<<gP, 256, PIPE_SMEM>>>(ah, al, woh + wo, wol + wo,
                                                  ob + l * D, x, tmp, (int)BS, D, D);
        ln_kernel<<<(int)BS, 256>>>(tmp, alnw + l * D, alnb + l * D, attn, ah, al);

        GemmTargets tf = {};
        tf.wh[0] = wih + fo; tf.wl[0] = wil + fo; tf.bias[0] = ib + l * FF;
        tf.c[0] = nullptr; tf.ch[0] = ffh; tf.cl[0] = ffl;
        gemm_mma_pipe<<<gF1, 256, PIPE_SMEM>>>(ah, al, tf, (int)BS, FF, D, 1);

        gemm_mma_pipe_res<<<gP, 256, PIPE_SMEM>>>(ffh, ffl, wdh + fo, wdl + fo,
                                                  db + l * D, attn, tmp, (int)BS, D, FF);
        ln_kernel<<<(int)BS, 256>>>(tmp, olnw + l * D, olnb + l * D,
                                    (l == L - 1) ? out : x, xh, xl);
    }
}

// round 9
// speedup vs baseline: 2.3870x; 1.9975x over previous
#include <cuda_runtime.h>
#include <cuda_bf16.h>
#include <cuda_fp16.h>
#include <math.h>
#include <stdint.h>

// ---------------- problem constants ----------------
constexpr int B = 16, S = 512, D = 768, H = 12, FF = 3072, L = 4;
constexpr int DH = 64;
constexpr int NREL = 129;
constexpr int NRELP = 144;
constexpr float SCALE = 0.125f;
constexpr float LN_EPS = 1e-12f;

constexpr size_t BS   = (size_t)B * S;
constexpr size_t BSD  = BS * D;
constexpr size_t BHS  = (size_t)B * H * S;
constexpr size_t BHSS = BHS * S;

// ---------------- device scratch ----------------
__device__ float g_x[BSD];
__device__ float g_scores[BHSS];
__device__ float g_qtab[BHS * NREL];
__device__ float g_ctx[BSD];
__device__ float g_tmp[BSD];
__device__ float g_attn[BSD];

constexpr size_t WSZ = (size_t)L * D * D;
constexpr size_t WFF = (size_t)L * FF * D;
// fp16 weights for big GEMMs
__device__ __align__(256) __half g_wqf[WSZ], g_wkf[WSZ], g_wvf[WSZ], g_wof[WSZ];
__device__ __align__(256) __half g_wif[WFF], g_wdf[WFF];
// fp16 activations for big GEMMs
__device__ __align__(256) __half g_xf[BSD], g_ctxf[BSD], g_attnf[BSD];
__device__ __align__(256) __half g_fff[BS * FF];
// bf16 hi/lo for attention (3-term)
__device__ __align__(256) __nv_bfloat16 g_qh[BSD], g_ql[BSD];
__device__ __align__(256) __nv_bfloat16 g_kh[BSD], g_kl[BSD];
__device__ __align__(256) __nv_bfloat16 g_vh[BSD], g_vl[BSD];
__device__ __align__(256) __nv_bfloat16 g_ph[BHSS], g_pl[BHSS];
__device__ __align__(256) __nv_bfloat16 g_pth[BHS * NRELP], g_ptl[BHS * NRELP];
__device__ __align__(256) __nv_bfloat16 g_tabh[160 * 64], g_tabl[160 * 64];
__device__ __align__(256) __nv_bfloat16 g_tTh[64 * NRELP], g_tTl[64 * NRELP];

// ---------------- helpers ----------------
__device__ __forceinline__ float block_reduce_sum(float v, float* red) {
    int t = threadIdx.x;
    red[t] = v; __syncthreads();
    for (int o = 128; o > 0; o >>= 1) {
        if (t < o) red[t] += red[t + o];
        __syncthreads();
    }
    float r = red[0]; __syncthreads();
    return r;
}

__device__ __forceinline__ void split1(float v, __nv_bfloat16& h, __nv_bfloat16& l) {
    h = __float2bfloat16_rn(v);
    l = __float2bfloat16_rn(v - __bfloat162float(h));
}

__global__ void build_tables(const float* __restrict__ rel,
                             __nv_bfloat16* __restrict__ tabh, __nv_bfloat16* __restrict__ tabl,
                             __nv_bfloat16* __restrict__ tTh, __nv_bfloat16* __restrict__ tTl)
{
    int i = blockIdx.x * 256 + threadIdx.x;
    if (i >= 160 * 64) return;
    int j = i / 64, d = i % 64;
    float v = (j < NREL) ? rel[((size_t)128 * S + (64 + j)) * DH + d] : 0.f;
    __nv_bfloat16 h, l; split1(v, h, l);
    tabh[j * 64 + d] = h; tabl[j * 64 + d] = l;
    if (j < NRELP) { tTh[d * NRELP + j] = h; tTl[d * NRELP + j] = l; }
}

__global__ __launch_bounds__(256) void conv_f16(
    const float* __restrict__ in, __half* __restrict__ o, int n4)
{
    int i = blockIdx.x * 256 + threadIdx.x;
    if (i >= n4) return;
    float4 v = ((const float4*)in)[i];
    __half2* op = (__half2*)o;
    op[i * 2 + 0] = __floats2half2_rn(v.x, v.y);
    op[i * 2 + 1] = __floats2half2_rn(v.z, v.w);
}

// ---------------- mma primitives ----------------
__device__ __forceinline__ void mma16816(float* d, const uint32_t* a, const uint32_t* b) {
    asm volatile(
        "mma.sync.aligned.m16n8k16.row.col.f32.bf16.bf16.f32 "
        "{%0,%1,%2,%3}, {%4,%5,%6,%7}, {%8,%9}, {%0,%1,%2,%3};\n"
        : "+f"(d[0]), "+f"(d[1]), "+f"(d[2]), "+f"(d[3])
        : "r"(a[0]), "r"(a[1]), "r"(a[2]), "r"(a[3]), "r"(b[0]), "r"(b[1]));
}
__device__ __forceinline__ void mma16816h(float* d, const uint32_t* a, const uint32_t* b) {
    asm volatile(
        "mma.sync.aligned.m16n8k16.row.col.f32.f16.f16.f32 "
        "{%0,%1,%2,%3}, {%4,%5,%6,%7}, {%8,%9}, {%0,%1,%2,%3};\n"
        : "+f"(d[0]), "+f"(d[1]), "+f"(d[2]), "+f"(d[3])
        : "r"(a[0]), "r"(a[1]), "r"(a[2]), "r"(a[3]), "r"(b[0]), "r"(b[1]));
}
__device__ __forceinline__ void ldsm4(uint32_t* r, uint32_t addr) {
    asm volatile("ldmatrix.sync.aligned.m8n8.x4.shared.b16 {%0,%1,%2,%3}, [%4];\n"
        : "=r"(r[0]), "=r"(r[1]), "=r"(r[2]), "=r"(r[3]) : "r"(addr));
}
__device__ __forceinline__ void ldsm4t(uint32_t* r, uint32_t addr) {
    asm volatile("ldmatrix.sync.aligned.m8n8.x4.trans.shared.b16 {%0,%1,%2,%3}, [%4];\n"
        : "=r"(r[0]), "=r"(r[1]), "=r"(r[2]), "=r"(r[3]) : "r"(addr));
}
__device__ __forceinline__ void cp16(uint32_t dst, const void* src) {
    asm volatile("cp.async.cg.shared.global [%0], [%1], 16;\n" :: "r"(dst), "l"(src));
}
__device__ __forceinline__ void cp_commit() { asm volatile("cp.async.commit_group;\n"); }
__device__ __forceinline__ void cp_wait1() { asm volatile("cp.async.wait_group 1;\n" ::: "memory"); }
__device__ __forceinline__ void cp_wait0() { asm volatile("cp.async.wait_group 0;\n" ::: "memory"); }
__device__ __forceinline__ uint32_t smem_u32(const void* p) {
    return (uint32_t)__cvta_generic_to_shared(p);
}

// ======================================================================
// fp16 single-term pipelined MMA GEMM NT: C = A(h16) * W(h16)^T
// 128x128 tile, 8 warps (2m x 4n), k-tile 32, 3 stages (61.4KB smem).
// ======================================================================
constexpr int FSTR = 40;
constexpr int FARR = 128 * FSTR * 2;      // 10240 B per array
constexpr int FSTG = 2 * FARR;            // 20480 B per stage
constexpr int FNSTG = 3;
constexpr int F_SMEM = FNSTG * FSTG;      // 61440

struct F16Targets {
    const __half* w[3];
    const float* bias[3];
    const float* res[3];
    float* c[3];
    __half* cf[3];
    __nv_bfloat16* ch[3];
    __nv_bfloat16* cl[3];
};

__global__ __launch_bounds__(256, 2) void gemm_f16_pipe(
    const __half* __restrict__ A, F16Targets tg, int M, int N, int K, int act)
{
    extern __shared__ __align__(16) char dsm[];
    const uint32_t sbase = smem_u32(dsm);
    const int z = blockIdx.z;
    const __half* W = tg.w[z];

    const int bm = blockIdx.y * 128, bn = blockIdx.x * 128;
    const int t = threadIdx.x, lane = t & 31, w = t >> 5;
    const int wm = (w & 1) * 64, wn = (w >> 1) * 32;

    float acc[4][4][4];
    #pragma unroll
    for (int i = 0; i < 4; i++)
        #pragma unroll
        for (int j = 0; j < 4; j++)
            #pragma unroll
            for (int r = 0; r < 4; r++) acc[i][j][r] = 0.f;

    uint32_t aoff[4], boff[2];
    #pragma unroll
    for (int mi = 0; mi < 4; mi++)
        aoff[mi] = (uint32_t)(((wm + mi * 16 + (lane & 15)) * FSTR + ((lane >> 4) << 3)) * 2);
    #pragma unroll
    for (int ni2 = 0; ni2 < 2; ni2++)
        boff[ni2] = (uint32_t)(((wn + ni2 * 16 + (lane & 7) + ((lane >> 4) << 3)) * FSTR
                               + (((lane >> 3) & 1) << 3)) * 2);

    const int nk = K / 32;
    // load geometry: 512 segs (16B) per array; thread handles segs t and t+256
    const int r0 = t >> 2, c0 = t & 3;
    const int r1 = (t + 256) >> 2, c1 = (t + 256) & 3;
    const uint32_t d0 = (uint32_t)((r0 * FSTR + c0 * 8) * 2);
    const uint32_t d1 = (uint32_t)((r1 * FSTR + c1 * 8) * 2);

    auto issue = [&](int c) {
        if (c < nk) {
            const uint32_t base = sbase + (c % FNSTG) * FSTG;
            const size_t k0 = (size_t)c * 32;
            cp16(base + d0,        A + (size_t)(bm + r0) * K + k0 + c0 * 8);
            cp16(base + d1,        A + (size_t)(bm + r1) * K + k0 + c1 * 8);
            cp16(base + FARR + d0, W + (size_t)(bn + r0) * K + k0 + c0 * 8);
            cp16(base + FARR + d1, W + (size_t)(bn + r1) * K + k0 + c1 * 8);
        }
        cp_commit();
    };
    issue(0);
    issue(1);

    for (int kt = 0; kt < nk; kt++) {
        cp_wait1();
        __syncthreads();
        issue(kt + 2);

        const uint32_t sb = sbase + (kt % FNSTG) * FSTG;
        #pragma unroll
        for (int kk2 = 0; kk2 < 2; kk2++) {
            const uint32_t ko = kk2 * 32;
            uint32_t ah[4][4], bh[4][2];
            #pragma unroll
            for (int mi = 0; mi < 4; mi++)
                ldsm4(ah[mi], sb + aoff[mi] + ko);
            #pragma unroll
            for (int ni2 = 0; ni2 < 2; ni2++) {
                uint32_t t4[4];
                ldsm4(t4, sb + FARR + boff[ni2] + ko);
                bh[ni2 * 2][0] = t4[0]; bh[ni2 * 2][1] = t4[1];
                bh[ni2 * 2 + 1][0] = t4[2]; bh[ni2 * 2 + 1][1] = t4[3];
            }
            #pragma unroll
            for (int mi = 0; mi < 4; mi++)
                #pragma unroll
                for (int ni = 0; ni < 4; ni++)
                    mma16816h(acc[mi][ni], ah[mi], bh[ni]);
        }
        __syncthreads();
    }

    const float* bias = tg.bias[z];
    const float* res  = tg.res[z];
    float* Cp = tg.c[z];
    __half* Cf = tg.cf[z];
    __nv_bfloat16* Ch = tg.ch[z];
    __nv_bfloat16* Cl = tg.cl[z];

    #pragma unroll
    for (int mi = 0; mi < 4; mi++) {
        int m0 = bm + wm + mi * 16 + (lane >> 2);
        #pragma unroll
        for (int ni = 0; ni < 4; ni++) {
            int n = bn + wn + ni * 8 + (lane & 3) * 2;
            float2 v0 = make_float2(acc[mi][ni][0], acc[mi][ni][1]);
            float2 v1 = make_float2(acc[mi][ni][2], acc[mi][ni][3]);
            if (bias) {
                float2 bv = *(const float2*)&bias[n];
                v0.x += bv.x; v0.y += bv.y; v1.x += bv.x; v1.y += bv.y;
            }
            if (res) {
                float2 rr0 = *(const float2*)&res[(size_t)m0 * N + n];
                float2 rr1 = *(const float2*)&res[(size_t)(m0 + 8) * N + n];
                v0.x += rr0.x; v0.y += rr0.y; v1.x += rr1.x; v1.y += rr1.y;
            }
            if (act == 1) {
                v0.x = 0.5f * v0.x * (1.f + erff(v0.x * 0.70710678118654752f));
                v0.y = 0.5f * v0.y * (1.f + erff(v0.y * 0.70710678118654752f));
                v1.x = 0.5f * v1.x * (1.f + erff(v1.x * 0.70710678118654752f));
                v1.y = 0.5f * v1.y * (1.f + erff(v1.y * 0.70710678118654752f));
            }
            if (Cp) {
                *(float2*)&Cp[(size_t)m0 * N + n] = v0;
                *(float2*)&Cp[(size_t)(m0 + 8) * N + n] = v1;
            }
            if (Cf) {
                *(__half2*)&Cf[(size_t)m0 * N + n] = __floats2half2_rn(v0.x, v0.y);
                *(__half2*)&Cf[(size_t)(m0 + 8) * N + n] = __floats2half2_rn(v1.x, v1.y);
            }
            if (Ch) {
                __nv_bfloat16 h0, l0, h1, l1;
                split1(v0.x, h0, l0); split1(v0.y, h1, l1);
                *(__nv_bfloat162*)&Ch[(size_t)m0 * N + n] = __nv_bfloat162(h0, h1);
                *(__nv_bfloat162*)&Cl[(size_t)m0 * N + n] = __nv_bfloat162(l0, l1);
                split1(v1.x, h0, l0); split1(v1.y, h1, l1);
                *(__nv_bfloat162*)&Ch[(size_t)(m0 + 8) * N + n] = __nv_bfloat162(h0, h1);
                *(__nv_bfloat162*)&Cl[(size_t)(m0 + 8) * N + n] = __nv_bfloat162(l0, l1);
            }
        }
    }
}

// ======================================================================
// qtab via warp-MMA (bf16 3-term, unchanged)
// ======================================================================
constexpr int QT_STR = 72;
constexpr int QT_A = 128 * QT_STR * 2;
constexpr int QT_B = 160 * QT_STR * 2;
constexpr int QT_SMEM = 2 * QT_A + 2 * QT_B;

__global__ __launch_bounds__(256) void qtab_mma(
    const __nv_bfloat16* __restrict__ Qh, const __nv_bfloat16* __restrict__ Ql,
    const __nv_bfloat16* __restrict__ Th, const __nv_bfloat16* __restrict__ Tl,
    float* __restrict__ qt)
{
    extern __shared__ __align__(16) char dsm[];
    __nv_bfloat16* sAh = (__nv_bfloat16*)dsm;
    __nv_bfloat16* sAl = (__nv_bfloat16*)(dsm + QT_A);
    __nv_bfloat16* sBh = (__nv_bfloat16*)(dsm + 2 * QT_A);
    __nv_bfloat16* sBl = (__nv_bfloat16*)(dsm + 2 * QT_A + QT_B);
    const uint32_t bAh = smem_u32(sAh), bAl = smem_u32(sAl);
    const uint32_t bBh = smem_u32(sBh), bBl = smem_u32(sBl);

    const int bm = blockIdx.x * 128;
    const int t = threadIdx.x, lane = t & 31, w = t >> 5;
    const int wm = (w & 3) * 32, wn = (w >> 2) * 80;

    #pragma unroll
    for (int i = 0; i < 4; i++) {
        int s = t + i * 256;
        int row = s >> 3, c8 = s & 7;
        size_t src = (size_t)(bm + row) * 64 + c8 * 8;
        *(uint4*)&sAh[row * QT_STR + c8 * 8] = *(const uint4*)&Qh[src];
        *(uint4*)&sAl[row * QT_STR + c8 * 8] = *(const uint4*)&Ql[src];
    }
    #pragma unroll
    for (int i = 0; i < 5; i++) {
        int s = t + i * 256;
        int row = s >> 3, c8 = s & 7;
        *(uint4*)&sBh[row * QT_STR + c8 * 8] = *(const uint4*)&Th[row * 64 + c8 * 8];
        *(uint4*)&sBl[row * QT_STR + c8 * 8] = *(const uint4*)&Tl[row * 64 + c8 * 8];
    }
    __syncthreads();

    float acc[2][10][4];
    #pragma unroll
    for (int i = 0; i < 2; i++)
        #pragma unroll
        for (int j = 0; j < 10; j++)
            #pragma unroll
            for (int r = 0; r < 4; r++) acc[i][j][r] = 0.f;

    uint32_t aoff[2], boff[5];
    #pragma unroll
    for (int mi = 0; mi < 2; mi++)
        aoff[mi] = (uint32_t)(((wm + mi * 16 + (lane & 15)) * QT_STR + ((lane >> 4) << 3)) * 2);
    #pragma unroll
    for (int ni2 = 0; ni2 < 5; ni2++)
        boff[ni2] = (uint32_t)(((wn + ni2 * 16 + (lane & 7) + ((lane >> 4) << 3)) * QT_STR
                               + (((lane >> 3) & 1) << 3)) * 2);

    #pragma unroll
    for (int kc = 0; kc < 4; kc++) {
        uint32_t ko = kc * 32;
        uint32_t ah[2][4], al[2][4];
        #pragma unroll
        for (int mi = 0; mi < 2; mi++) {
            ldsm4(ah[mi], bAh + aoff[mi] + ko);
            ldsm4(al[mi], bAl + aoff[mi] + ko);
        }
        #pragma unroll
        for (int ni2 = 0; ni2 < 5; ni2++) {
            uint32_t th4[4], tl4[4];
            ldsm4(th4, bBh + boff[ni2] + ko);
            ldsm4(tl4, bBl + boff[ni2] + ko);
            uint32_t bh0[2] = {th4[0], th4[1]}, bh1[2] = {th4[2], th4[3]};
            uint32_t bl0[2] = {tl4[0], tl4[1]}, bl1[2] = {tl4[2], tl4[3]};
            #pragma unroll
            for (int mi = 0; mi < 2; mi++) {
                mma16816(acc[mi][ni2 * 2], ah[mi], bh0);
                mma16816(acc[mi][ni2 * 2], ah[mi], bl0);
                mma16816(acc[mi][ni2 * 2], al[mi], bh0);
                mma16816(acc[mi][ni2 * 2 + 1], ah[mi], bh1);
                mma16816(acc[mi][ni2 * 2 + 1], ah[mi], bl1);
                mma16816(acc[mi][ni2 * 2 + 1], al[mi], bh1);
            }
        }
    }

    #pragma unroll
    for (int mi = 0; mi < 2; mi++)
        #pragma unroll
        for (int rr = 0; rr < 2; rr++) {
            int m0 = bm + wm + mi * 16 + (lane >> 2) + rr * 8;
            #pragma unroll
            for (int ni = 0; ni < 10; ni++) {
                int n = wn + ni * 8 + (lane & 3) * 2;
                if (n < NREL)     qt[(size_t)m0 * NREL + n]     = acc[mi][ni][rr * 2 + 0];
                if (n + 1 < NREL) qt[(size_t)m0 * NREL + n + 1] = acc[mi][ni][rr * 2 + 1];
            }
        }
}

// ======================================================================
// ctx_rel via warp-MMA (unchanged)
// ======================================================================
constexpr int CR_ASTR = 56;
constexpr int CR_BSTR = 152;
constexpr int CR_A = 128 * CR_ASTR * 2;
constexpr int CR_B = 64 * CR_BSTR * 2;
constexpr int CR_SMEM = 2 * CR_A + 2 * CR_B;

__global__ __launch_bounds__(256) void ctx_rel_mma(
    const __nv_bfloat16* __restrict__ Ph, const __nv_bfloat16* __restrict__ Pl,
    const __nv_bfloat16* __restrict__ Th, const __nv_bfloat16* __restrict__ Tl,
    float* __restrict__ ctx)
{
    extern __shared__ __align__(16) char dsm[];
    __nv_bfloat16* sAh = (__nv_bfloat16*)dsm;
    __nv_bfloat16* sAl = (__nv_bfloat16*)(dsm + CR_A);
    __nv_bfloat16* sBh = (__nv_bfloat16*)(dsm + 2 * CR_A);
    __nv_bfloat16* sBl = (__nv_bfloat16*)(dsm + 2 * CR_A + CR_B);
    const uint32_t bAh = smem_u32(sAh), bAl = smem_u32(sAl);
    const uint32_t bBh = smem_u32(sBh), bBl = smem_u32(sBl);

    const int bm = blockIdx.x * 128;
    const int t = threadIdx.x, lane = t & 31, w = t >> 5;
    const int wm = (w & 3) * 32, wn = (w >> 2) * 32;

    for (int s = t; s < 1152; s += 256) {
        int row = s / 18, c8 = s % 18;
        *(uint4*)&sBh[row * CR_BSTR + c8 * 8] = *(const uint4*)&Th[row * NRELP + c8 * 8];
        *(uint4*)&sBl[row * CR_BSTR + c8 * 8] = *(const uint4*)&Tl[row * NRELP + c8 * 8];
    }

    float acc[2][4][4];
    #pragma unroll
    for (int i = 0; i < 2; i++)
        #pragma unroll
        for (int j = 0; j < 4; j++)
            #pragma unroll
            for (int r = 0; r < 4; r++) acc[i][j][r] = 0.f;

    uint32_t aoff[2], boff[2];
    #pragma unroll
    for (int mi = 0; mi < 2; mi++)
        aoff[mi] = (uint32_t)(((wm + mi * 16 + (lane & 15)) * CR_ASTR + ((lane >> 4) << 3)) * 2);
    #pragma unroll
    for (int ni2 = 0; ni2 < 2; ni2++)
        boff[ni2] = (uint32_t)(((wn + ni2 * 16 + (lane & 7) + ((lane >> 4) << 3)) * CR_BSTR
                               + (((lane >> 3) & 1) << 3)) * 2);

    for (int c = 0; c < 3; c++) {
        __syncthreads();
        #pragma unroll
        for (int i = 0; i < 3; i++) {
            int s = t + i * 256;
            int row = s / 6, c8 = s % 6;
            size_t src = (size_t)(bm + row) * NRELP + c * 48 + c8 * 8;
            *(uint4*)&sAh[row * CR_ASTR + c8 * 8] = *(const uint4*)&Ph[src];
            *(uint4*)&sAl[row * CR_ASTR + c8 * 8] = *(const uint4*)&Pl[src];
        }
        __syncthreads();
        #pragma unroll
        for (int kc = 0; kc < 3; kc++) {
            uint32_t kaoff = kc * 32;
            uint32_t kboff = (uint32_t)(c * 96 + kc * 32);
            uint32_t ah[2][4], al[2][4];
            #pragma unroll
            for (int mi = 0; mi < 2; mi++) {
                ldsm4(ah[mi], bAh + aoff[mi] + kaoff);
                ldsm4(al[mi], bAl + aoff[mi] + kaoff);
            }
            #pragma unroll
            for (int ni2 = 0; ni2 < 2; ni2++) {
                uint32_t th4[4], tl4[4];
                ldsm4(th4, bBh + boff[ni2] + kboff);
                ldsm4(tl4, bBl + boff[ni2] + kboff);
                uint32_t bh0[2] = {th4[0], th4[1]}, bh1[2] = {th4[2], th4[3]};
                uint32_t bl0[2] = {tl4[0], tl4[1]}, bl1[2] = {tl4[2], tl4[3]};
                #pragma unroll
                for (int mi = 0; mi < 2; mi++) {
                    mma16816(acc[mi][ni2 * 2], ah[mi], bh0);
                    mma16816(acc[mi][ni2 * 2], ah[mi], bl0);
                    mma16816(acc[mi][ni2 * 2], al[mi], bh0);
                    mma16816(acc[mi][ni2 * 2 + 1], ah[mi], bh1);
                    mma16816(acc[mi][ni2 * 2 + 1], ah[mi], bl1);
                    mma16816(acc[mi][ni2 * 2 + 1], al[mi], bh1);
                }
            }
        }
    }

    #pragma unroll
    for (int mi = 0; mi < 2; mi++)
        #pragma unroll
        for (int rr = 0; rr < 2; rr++) {
            int m0 = bm + wm + mi * 16 + (lane >> 2) + rr * 8;
            #pragma unroll
            for (int ni = 0; ni < 4; ni++) {
                int n = wn + ni * 8 + (lane & 3) * 2;
                float2 v = make_float2(acc[mi][ni][rr * 2 + 0], acc[mi][ni][rr * 2 + 1]);
                *(float2*)&ctx[(size_t)m0 * 64 + n] = v;
            }
        }
}

// ======================================================================
// Scores MMA (cp.async double buffer, unchanged from R8)
// ======================================================================
constexpr int QSTR = 40;
constexpr int SC_ARR = 128 * QSTR * 2;
constexpr int SC_STG = 4 * SC_ARR;
constexpr int SC_SMEM = 2 * SC_STG;

__global__ __launch_bounds__(256) void scores_mma(
    const __nv_bfloat16* __restrict__ Qh, const __nv_bfloat16* __restrict__ Ql,
    const __nv_bfloat16* __restrict__ Kh, const __nv_bfloat16* __restrict__ Kl,
    const float* __restrict__ qtab, const int* __restrict__ mask,
    float* __restrict__ scores)
{
    extern __shared__ __align__(16) char dsm[];
    const uint32_t sbase = smem_u32(dsm);
    const int bh = blockIdx.z, b = bh / H, h = bh % H;
    const int q0 = blockIdx.y * 128, k0b = blockIdx.x * 128;
    const int t = threadIdx.x, lane = t & 31, w = t >> 5;
    const int wm = (w & 1) * 64, wn = (w >> 1) * 32;

    float acc[4][4][4];
    #pragma unroll
    for (int i = 0; i < 4; i++)
        #pragma unroll
        for (int j = 0; j < 4; j++)
            #pragma unroll
            for (int r = 0; r < 4; r++) acc[i][j][r] = 0.f;

    uint32_t aoff[4], boff[2];
    #pragma unroll
    for (int mi = 0; mi < 4; mi++)
        aoff[mi] = (uint32_t)(((wm + mi * 16 + (lane & 15)) * QSTR + ((lane >> 4) << 3)) * 2);
    #pragma unroll
    for (int ni2 = 0; ni2 < 2; ni2++)
        boff[ni2] = (uint32_t)(((wn + ni2 * 16 + (lane & 7) + ((lane >> 4) << 3)) * QSTR
                               + (((lane >> 3) & 1) << 3)) * 2);

    auto issue = [&](int kt) {
        uint32_t base = sbase + kt * SC_STG;
        #pragma unroll
        for (int i = 0; i < 2; i++) {
            int idx = t * 2 + i;
            int row = idx >> 2, cseg = (idx & 3) * 8;
            size_t qsrc = ((size_t)(b * S) + q0 + row) * D + h * DH + kt * 32 + cseg;
            size_t ksrc = ((size_t)(b * S) + k0b + row) * D + h * DH + kt * 32 + cseg;
            uint32_t d = base + (uint32_t)((row * QSTR + cseg) * 2);
            cp16(d,              Qh + qsrc);
            cp16(d + SC_ARR,     Ql + qsrc);
            cp16(d + 2 * SC_ARR, Kh + ksrc);
            cp16(d + 3 * SC_ARR, Kl + ksrc);
        }
        cp_commit();
    };
    issue(0);
    issue(1);

    for (int kt = 0; kt < 2; kt++) {
        if (kt == 0) cp_wait1(); else cp_wait0();
        __syncthreads();
        const uint32_t sb = sbase + kt * SC_STG;
        #pragma unroll
        for (int kk2 = 0; kk2 < 2; kk2++) {
            uint32_t koffb = kk2 * 32;
            uint32_t ah[4][4], al[4][4], bhf[4][2], blf[4][2];
            #pragma unroll
            for (int mi = 0; mi < 4; mi++) {
                ldsm4(ah[mi], sb + aoff[mi] + koffb);
                ldsm4(al[mi], sb + SC_ARR + aoff[mi] + koffb);
            }
            #pragma unroll
            for (int ni2 = 0; ni2 < 2; ni2++) {
                uint32_t t4[4];
                ldsm4(t4, sb + 2 * SC_ARR + boff[ni2] + koffb);
                bhf[ni2 * 2][0] = t4[0]; bhf[ni2 * 2][1] = t4[1];
                bhf[ni2 * 2 + 1][0] = t4[2]; bhf[ni2 * 2 + 1][1] = t4[3];
                ldsm4(t4, sb + 3 * SC_ARR + boff[ni2] + koffb);
                blf[ni2 * 2][0] = t4[0]; blf[ni2 * 2][1] = t4[1];
                blf[ni2 * 2 + 1][0] = t4[2]; blf[ni2 * 2 + 1][1] = t4[3];
            }
            #pragma unroll
            for (int mi = 0; mi < 4; mi++)
                #pragma unroll
                for (int ni = 0; ni < 4; ni++) {
                    mma16816(acc[mi][ni], ah[mi], bhf[ni]);
                    mma16816(acc[mi][ni], ah[mi], blf[ni]);
                    mma16816(acc[mi][ni], al[mi], bhf[ni]);
                }
        }
    }

    #pragma unroll
    for (int mi = 0; mi < 4; mi++) {
        #pragma unroll
        for (int rr = 0; rr < 2; rr++) {
            int q = q0 + wm + mi * 16 + (lane >> 2) + rr * 8;
            const float* qtr = qtab + (((size_t)b * S + q) * H + h) * NREL;
            size_t rowb = ((size_t)bh * S + q) * S;
            #pragma unroll
            for (int ni = 0; ni < 4; ni++) {
                int k = k0b + wn + ni * 8 + (lane & 3) * 2;
                float vx = acc[mi][ni][rr * 2 + 0];
                float vy = acc[mi][ni][rr * 2 + 1];
                int r0 = k - q; r0 = r0 < -64 ? -64 : (r0 > 64 ? 64 : r0);
                int r1 = k + 1 - q; r1 = r1 < -64 ? -64 : (r1 > 64 ? 64 : r1);
                float mb0 = (1.f - (float)mask[b * S + k]) * -10000.f;
                float mb1 = (1.f - (float)mask[b * S + k + 1]) * -10000.f;
                float2 o;
                o.x = (vx + qtr[r0 + 64]) * SCALE + mb0;
                o.y = (vy + qtr[r1 + 64]) * SCALE + mb1;
                *(float2*)&scores[rowb + k] = o;
            }
        }
    }
}

// ======================================================================
// ctx_pv (cp.async 3-stage) -> fp16 ctx output
// ======================================================================
constexpr int VSTR = 72;
constexpr int PV_P = 128 * QSTR * 2;
constexpr int PV_V = 32 * VSTR * 2;
constexpr int PV_STG = 2 * PV_P + 2 * PV_V;
constexpr int PV_NSTG = 3;
constexpr int PV_SMEM = PV_NSTG * PV_STG;

__global__ __launch_bounds__(256) void ctx_pv_mma(
    const __nv_bfloat16* __restrict__ Ph, const __nv_bfloat16* __restrict__ Pl,
    const __nv_bfloat16* __restrict__ Vh, const __nv_bfloat16* __restrict__ Vl,
    const float* __restrict__ ctxin, __half* __restrict__ outf)
{
    extern __shared__ __align__(16) char dsm[];
    const uint32_t sbase = smem_u32(dsm);
    const int bh = blockIdx.z, b = bh / H, h = bh % H;
    const int q0 = blockIdx.x * 128;
    const int t = threadIdx.x, lane = t & 31, w = t >> 5;
    const int wm = (w & 3) * 32, wn = (w >> 2) * 32;

    float acc[2][4][4];
    #pragma unroll
    for (int i = 0; i < 2; i++)
        #pragma unroll
        for (int j = 0; j < 4; j++)
            #pragma unroll
            for (int r = 0; r < 4; r++) acc[i][j][r] = 0.f;

    uint32_t aoff[2];
    #pragma unroll
    for (int mi = 0; mi < 2; mi++)
        aoff[mi] = (uint32_t)(((wm + mi * 16 + (lane & 15)) * QSTR + ((lane >> 4) << 3)) * 2);

    const int nk = S / 32;

    auto issue = [&](int kt, int slot) {
        if (kt < nk) {
            uint32_t base = sbase + slot * PV_STG;
            #pragma unroll
            for (int i = 0; i < 2; i++) {
                int idx = t * 2 + i;
                int row = idx >> 2, cseg = (idx & 3) * 8;
                size_t psrc = ((size_t)bh * S + q0 + row) * S + kt * 32 + cseg;
                uint32_t d = base + (uint32_t)((row * QSTR + cseg) * 2);
                cp16(d,        Ph + psrc);
                cp16(d + PV_P, Pl + psrc);
            }
            {
                int row = t >> 3, cseg = (t & 7) * 8;
                size_t vsrc = ((size_t)(b * S) + kt * 32 + row) * D + h * DH + cseg;
                uint32_t d = base + 2 * PV_P + (uint32_t)((row * VSTR + cseg) * 2);
                cp16(d,        Vh + vsrc);
                cp16(d + PV_V, Vl + vsrc);
            }
        }
        cp_commit();
    };
    issue(0, 0);
    issue(1, 1);

    for (int kt = 0; kt < nk; kt++) {
        cp_wait1();
        __syncthreads();
        issue(kt + 2, (kt + 2) % PV_NSTG);

        const uint32_t sb = sbase + (kt % PV_NSTG) * PV_STG;
        #pragma unroll
        for (int kk2 = 0; kk2 < 2; kk2++) {
            uint32_t koffb = kk2 * 32;
            uint32_t ah[2][4], al[2][4], bhf[4][2], blf[4][2];
            #pragma unroll
            for (int mi = 0; mi < 2; mi++) {
                ldsm4(ah[mi], sb + aoff[mi] + koffb);
                ldsm4(al[mi], sb + PV_P + aoff[mi] + koffb);
            }
            #pragma unroll
            for (int ni2 = 0; ni2 < 2; ni2++) {
                uint32_t vaddr = (uint32_t)(((kk2 * 16 + (lane & 15)) * VSTR
                                 + wn + ni2 * 16 + (lane >> 4) * 8) * 2);
                uint32_t t4[4];
                ldsm4t(t4, sb + 2 * PV_P + vaddr);
                bhf[ni2 * 2][0] = t4[0]; bhf[ni2 * 2][1] = t4[1];
                bhf[ni2 * 2 + 1][0] = t4[2]; bhf[ni2 * 2 + 1][1] = t4[3];
                ldsm4t(t4, sb + 2 * PV_P + PV_V + vaddr);
                blf[ni2 * 2][0] = t4[0]; blf[ni2 * 2][1] = t4[1];
                blf[ni2 * 2 + 1][0] = t4[2]; blf[ni2 * 2 + 1][1] = t4[3];
            }
            #pragma unroll
            for (int mi = 0; mi < 2; mi++)
                #pragma unroll
                for (int ni = 0; ni < 4; ni++) {
                    mma16816(acc[mi][ni], ah[mi], bhf[ni]);
                    mma16816(acc[mi][ni], ah[mi], blf[ni]);
                    mma16816(acc[mi][ni], al[mi], bhf[ni]);
                }
        }
        __syncthreads();
    }

    #pragma unroll
    for (int mi = 0; mi < 2; mi++) {
        #pragma unroll
        for (int rr = 0; rr < 2; rr++) {
            int q = q0 + wm + mi * 16 + (lane >> 2) + rr * 8;
            size_t rb = ((size_t)(b * S) + q) * D + h * DH;
            #pragma unroll
            for (int ni = 0; ni < 4; ni++) {
                int d = wn + ni * 8 + (lane & 3) * 2;
                float2 cur = *(const float2*)&ctxin[rb + d];
                cur.x += acc[mi][ni][rr * 2 + 0];
                cur.y += acc[mi][ni][rr * 2 + 1];
                *(__half2*)&outf[rb + d] = __floats2half2_rn(cur.x, cur.y);
            }
        }
    }
}

// ---------------- embedding + LN (fp32 + fp16 out) ----------------
__global__ __launch_bounds__(256) void embed_ln(
    const int* __restrict__ ids, const int* __restrict__ tti,
    const float* __restrict__ we, const float* __restrict__ te,
    const float* __restrict__ w, const float* __restrict__ bb,
    float* __restrict__ out, __half* __restrict__ of)
{
    __shared__ float red[256];
    int m = blockIdx.x, t = threadIdx.x;
    int id = ids[m], t2 = tti[m];
    const float* wr = we + (size_t)id * D;
    const float* tr = te + (size_t)t2 * D;
    float vals[3]; float s = 0.f;
    #pragma unroll
    for (int i = 0; i < 3; i++) { int d = t + i * 256; vals[i] = wr[d] + tr[d]; s += vals[i]; }
    float mean = block_reduce_sum(s, red) * (1.f / D);
    float vs = 0.f;
    #pragma unroll
    for (int i = 0; i < 3; i++) { float dd = vals[i] - mean; vs += dd * dd; }
    float var = block_reduce_sum(vs, red) * (1.f / D);
    float rstd = rsqrtf(var + LN_EPS);
    #pragma unroll
    for (int i = 0; i < 3; i++) {
        int d = t + i * 256;
        float v = (vals[i] - mean) * rstd * w[d] + bb[d];
        out[(size_t)m * D + d] = v;
        of[(size_t)m * D + d] = __float2half_rn(v);
    }
}

__global__ __launch_bounds__(256) void ln_kernel(
    const float* __restrict__ x, const float* __restrict__ w,
    const float* __restrict__ bb, float* __restrict__ out,
    __half* __restrict__ of)
{
    __shared__ float red[256];
    int m = blockIdx.x, t = threadIdx.x;
    const float* xr = x + (size_t)m * D;
    float vals[3]; float s = 0.f;
    #pragma unroll
    for (int i = 0; i < 3; i++) { vals[i] = xr[t + i * 256]; s += vals[i]; }
    float mean = block_reduce_sum(s, red) * (1.f / D);
    float vs = 0.f;
    #pragma unroll
    for (int i = 0; i < 3; i++) { float dd = vals[i] - mean; vs += dd * dd; }
    float var = block_reduce_sum(vs, red) * (1.f / D);
    float rstd = rsqrtf(var + LN_EPS);
    #pragma unroll
    for (int i = 0; i < 3; i++) {
        int d = t + i * 256;
        float v = (vals[i] - mean) * rstd * w[d] + bb[d];
        out[(size_t)m * D + d] = v;
        of[(size_t)m * D + d] = __float2half_rn(v);
    }
}

// ---------------- warp-per-row softmax (unchanged) ----------------
__global__ __launch_bounds__(256) void softmax_warp(
    const float* __restrict__ scores,
    __nv_bfloat16* __restrict__ ph, __nv_bfloat16* __restrict__ pl,
    __nv_bfloat16* __restrict__ pth, __nv_bfloat16* __restrict__ ptl)
{
    __shared__ float srow[8][512];
    const int w = threadIdx.x >> 5, lane = threadIdx.x & 31;
    const int row = blockIdx.x * 8 + w;
    const int q = row % S, bh = row / S;
    const int b = bh / H, h = bh % H;
    const float* sr = scores + (size_t)row * S;

    float2 v[8];
    float m = -1e30f;
    #pragma unroll
    for (int i = 0; i < 8; i++) {
        v[i] = *(const float2*)&sr[lane * 2 + 64 * i];
        m = fmaxf(m, fmaxf(v[i].x, v[i].y));
    }
    #pragma unroll
    for (int o = 16; o > 0; o >>= 1) m = fmaxf(m, __shfl_xor_sync(0xffffffffu, m, o));

    float s = 0.f;
    #pragma unroll
    for (int i = 0; i < 8; i++) {
        v[i].x = expf(v[i].x - m); v[i].y = expf(v[i].y - m);
        s += v[i].x + v[i].y;
    }
    #pragma unroll
    for (int o = 16; o > 0; o >>= 1) s += __shfl_xor_sync(0xffffffffu, s, o);
    float inv = 1.f / s;

    size_t rb = (size_t)row * S;
    float left = 0.f, right = 0.f;
    #pragma unroll
    for (int i = 0; i < 8; i++) {
        int k = lane * 2 + 64 * i;
        float p0 = v[i].x * inv, p1 = v[i].y * inv;
        srow[w][k] = p0; srow[w][k + 1] = p1;
        __nv_bfloat16 h0, l0, h1, l1;
        split1(p0, h0, l0); split1(p1, h1, l1);
        *(__nv_bfloat162*)&ph[rb + k] = __nv_bfloat162(h0, h1);
        *(__nv_bfloat162*)&pl[rb + k] = __nv_bfloat162(l0, l1);
        if (k <= q - 64)     left += p0;
        if (k + 1 <= q - 64) left += p1;
        if (k >= q + 64)     right += p0;
        if (k + 1 >= q + 64) right += p1;
    }
    #pragma unroll
    for (int o = 16; o > 0; o >>= 1) {
        left  += __shfl_xor_sync(0xffffffffu, left, o);
        right += __shfl_xor_sync(0xffffffffu, right, o);
    }
    __syncwarp();

    size_t pbase = ((size_t)(b * S + q) * H + h) * NRELP;
    __nv_bfloat16 hh, ll;
    if (lane == 0) {
        split1(left, hh, ll);  pth[pbase] = hh;       ptl[pbase] = ll;
        split1(right, hh, ll); pth[pbase + 128] = hh; ptl[pbase + 128] = ll;
    }
    if (lane < 15) {
        pth[pbase + 129 + lane] = __float2bfloat16(0.f);
        ptl[pbase + 129 + lane] = __float2bfloat16(0.f);
    }
    #pragma unroll
    for (int jj = 0; jj < 4; jj++) {
        int j = 1 + lane + 32 * jj;
        if (j <= 127) {
            int k = q + j - 64;
            float p = (k >= 0 && k < S) ? srow[w][k] : 0.f;
            split1(p, hh, ll);
            pth[pbase + j] = hh; ptl[pbase + j] = ll;
        }
    }
}

// ---------------- launch ----------------
extern "C" void kernel_launch(void* const* d_in, const int* in_sizes, int n_in,
                              void* d_out, int out_size)
{
    const int*   ids     = (const int*)d_in[0];
    const int*   amask   = (const int*)d_in[1];
    const int*   tti     = (const int*)d_in[2];
    const float* wemb    = (const float*)d_in[3];
    const float* temb    = (const float*)d_in[4];
    const float* elnw    = (const float*)d_in[5];
    const float* elnb    = (const float*)d_in[6];
    const float* qw      = (const float*)d_in[7];
    const float* qb      = (const float*)d_in[8];
    const float* kw      = (const float*)d_in[9];
    const float* kb      = (const float*)d_in[10];
    const float* vw      = (const float*)d_in[11];
    const float* vb      = (const float*)d_in[12];
    const float* rel     = (const float*)d_in[13];
    const float* ow      = (const float*)d_in[14];
    const float* ob      = (const float*)d_in[15];
    const float* alnw    = (const float*)d_in[16];
    const float* alnb    = (const float*)d_in[17];
    const float* iw      = (const float*)d_in[18];
    const float* ib      = (const float*)d_in[19];
    const float* dw      = (const float*)d_in[20];
    const float* db      = (const float*)d_in[21];
    const float* olnw    = (const float*)d_in[22];
    const float* olnb    = (const float*)d_in[23];
    float* out = (float*)d_out;

    float *x, *sc, *qt, *ctx, *tmp, *attn;
    cudaGetSymbolAddress((void**)&x,    g_x);
    cudaGetSymbolAddress((void**)&sc,   g_scores);
    cudaGetSymbolAddress((void**)&qt,   g_qtab);
    cudaGetSymbolAddress((void**)&ctx,  g_ctx);
    cudaGetSymbolAddress((void**)&tmp,  g_tmp);
    cudaGetSymbolAddress((void**)&attn, g_attn);

    __half *wqf, *wkf, *wvf, *wof, *wif, *wdf, *xf, *ctxf, *attnf, *fff;
    __nv_bfloat16 *qh, *ql, *kh, *kl, *vh, *vl, *ph, *pl;
    __nv_bfloat16 *pth, *ptl, *tabh, *tabl, *tTh, *tTl;
    cudaGetSymbolAddress((void**)&wqf, g_wqf);
    cudaGetSymbolAddress((void**)&wkf, g_wkf);
    cudaGetSymbolAddress((void**)&wvf, g_wvf);
    cudaGetSymbolAddress((void**)&wof, g_wof);
    cudaGetSymbolAddress((void**)&wif, g_wif);
    cudaGetSymbolAddress((void**)&wdf, g_wdf);
    cudaGetSymbolAddress((void**)&xf,   g_xf);
    cudaGetSymbolAddress((void**)&ctxf, g_ctxf);
    cudaGetSymbolAddress((void**)&attnf, g_attnf);
    cudaGetSymbolAddress((void**)&fff,  g_fff);
    cudaGetSymbolAddress((void**)&qh,  g_qh);  cudaGetSymbolAddress((void**)&ql,  g_ql);
    cudaGetSymbolAddress((void**)&kh,  g_kh);  cudaGetSymbolAddress((void**)&kl,  g_kl);
    cudaGetSymbolAddress((void**)&vh,  g_vh);  cudaGetSymbolAddress((void**)&vl,  g_vl);
    cudaGetSymbolAddress((void**)&ph,  g_ph);  cudaGetSymbolAddress((void**)&pl,  g_pl);
    cudaGetSymbolAddress((void**)&pth, g_pth); cudaGetSymbolAddress((void**)&ptl, g_ptl);
    cudaGetSymbolAddress((void**)&tabh, g_tabh); cudaGetSymbolAddress((void**)&tabl, g_tabl);
    cudaGetSymbolAddress((void**)&tTh, g_tTh); cudaGetSymbolAddress((void**)&tTl, g_tTl);

    cudaFuncSetAttribute(gemm_f16_pipe, cudaFuncAttributeMaxDynamicSharedMemorySize, F_SMEM);
    cudaFuncSetAttribute(qtab_mma, cudaFuncAttributeMaxDynamicSharedMemorySize, QT_SMEM);
    cudaFuncSetAttribute(ctx_rel_mma, cudaFuncAttributeMaxDynamicSharedMemorySize, CR_SMEM);
    cudaFuncSetAttribute(scores_mma, cudaFuncAttributeMaxDynamicSharedMemorySize, SC_SMEM);
    cudaFuncSetAttribute(ctx_pv_mma, cudaFuncAttributeMaxDynamicSharedMemorySize, PV_SMEM);

    build_tables<<<(160 * 64 + 255) / 256, 256>>>(rel, tabh, tabl, tTh, tTl);
    embed_ln<<<(int)BS, 256>>>(ids, tti, wemb, temb, elnw, elnb, x, xf);

    {
        int n4 = (int)(WSZ / 4), g = (n4 + 255) / 256;
        conv_f16<<<g, 256>>>(qw, wqf, n4);
        conv_f16<<<g, 256>>>(kw, wkf, n4);
        conv_f16<<<g, 256>>>(vw, wvf, n4);
        conv_f16<<<g, 256>>>(ow, wof, n4);
        int n4f = (int)(WFF / 4), gf = (n4f + 255) / 256;
        conv_f16<<<gf, 256>>>(iw, wif, n4f);
        conv_f16<<<gf, 256>>>(dw, wdf, n4f);
    }

    const dim3 gQKV(D / 128, (int)(BS / 128), 3);
    const dim3 gP(D / 128, (int)(BS / 128), 1);
    const dim3 gF1(FF / 128, (int)(BS / 128), 1);
    const dim3 gSC(S / 128, S / 128, B * H);
    const dim3 gPV(S / 128, 1, B * H);
    const int gRow = (int)(BS * H / 128);

    for (int l = 0; l < L; l++) {
        const size_t wo = (size_t)l * D * D;
        const size_t fo = (size_t)l * FF * D;

        // QKV fused, fp16 1-term; outputs bf16 hi/lo pairs for attention
        F16Targets tq = {};
        tq.w[0] = wqf + wo; tq.bias[0] = qb + l * D; tq.ch[0] = qh; tq.cl[0] = ql;
        tq.w[1] = wkf + wo; tq.bias[1] = kb + l * D; tq.ch[1] = kh; tq.cl[1] = kl;
        tq.w[2] = wvf + wo; tq.bias[2] = vb + l * D; tq.ch[2] = vh; tq.cl[2] = vl;
        gemm_f16_pipe<<<gQKV, 256, F_SMEM>>>(xf, tq, (int)BS, D, D, 0);

        qtab_mma<<<gRow, 256, QT_SMEM>>>(qh, ql, tabh, tabl, qt);

        scores_mma<<<gSC, 256, SC_SMEM>>>(qh, ql, kh, kl, qt, amask, sc);
        softmax_warp<<<(int)(BHS / 8), 256>>>(sc, ph, pl, pth, ptl);

        ctx_rel_mma<<<gRow, 256, CR_SMEM>>>(pth, ptl, tTh, tTl, ctx);
        ctx_pv_mma<<<gPV, 256, PV_SMEM>>>(ph, pl, vh, vl, ctx, ctxf);

        // O-proj fp16 1-term (+bias +residual, fp32 out)
        F16Targets to = {};
        to.w[0] = wof + wo; to.bias[0] = ob + l * D; to.res[0] = x; to.c[0] = tmp;
        gemm_f16_pipe<<<gP, 256, F_SMEM>>>(ctxf, to, (int)BS, D, D, 0);
        ln_kernel<<<(int)BS, 256>>>(tmp, alnw + l * D, alnb + l * D, attn, attnf);

        // FFN1 fp16 1-term + gelu, fp16 out
        F16Targets tf = {};
        tf.w[0] = wif + fo; tf.bias[0] = ib + l * FF; tf.cf[0] = fff;
        gemm_f16_pipe<<<gF1, 256, F_SMEM>>>(attnf, tf, (int)BS, FF, D, 1);

        // FFN2 fp16 1-term (+bias +residual, fp32 out)
        F16Targets td = {};
        td.w[0] = wdf + fo; td.bias[0] = db + l * D; td.res[0] = attn; td.c[0] = tmp;
        gemm_f16_pipe<<<gP, 256, F_SMEM>>>(fff, td, (int)BS, D, FF, 0);
        ln_kernel<<<(int)BS, 256>>>(tmp, olnw + l * D, olnb + l * D,
                                    (l == L - 1) ? out : x, xf);
    }
}

// round 10
// speedup vs baseline: 2.7674x; 1.1594x over previous
#include <cuda_runtime.h>
#include <cuda_bf16.h>
#include <cuda_fp16.h>
#include <math.h>
#include <stdint.h>

// ---------------- problem constants ----------------
constexpr int B = 16, S = 512, D = 768, H = 12, FF = 3072, L = 4;
constexpr int DH = 64;
constexpr int NREL = 129;
constexpr int NRELP = 144;
constexpr float SCALE = 0.125f;
constexpr float LN_EPS = 1e-12f;

constexpr size_t BS   = (size_t)B * S;
constexpr size_t BSD  = BS * D;
constexpr size_t BHS  = (size_t)B * H * S;
constexpr size_t BHSS = BHS * S;

// ---------------- device scratch ----------------
__device__ float g_x[BSD];
__device__ float g_scores[BHSS];
__device__ float g_qtab[BHS * NREL];
__device__ float g_ctx[BSD];
__device__ float g_tmp[BSD];
__device__ float g_attn[BSD];

constexpr size_t WSZ = (size_t)L * D * D;
constexpr size_t WFF = (size_t)L * FF * D;
__device__ __align__(256) __half g_wqf[WSZ], g_wkf[WSZ], g_wvf[WSZ], g_wof[WSZ];
__device__ __align__(256) __half g_wif[WFF], g_wdf[WFF];
__device__ __align__(256) __half g_xf[BSD], g_ctxf[BSD], g_attnf[BSD];
__device__ __align__(256) __half g_fff[BS * FF];
// fp16 attention operands
__device__ __align__(256) __half g_qf[BSD], g_kf[BSD], g_vf[BSD];
__device__ __align__(256) __half g_pf[BHSS];
__device__ __align__(256) __half g_ptf[BHS * NRELP];
__device__ __align__(256) __half g_tabf[160 * 64];
__device__ __align__(256) __half g_tTf[64 * NRELP];

// ---------------- helpers ----------------
__device__ __forceinline__ float block_reduce_sum(float v, float* red) {
    int t = threadIdx.x;
    red[t] = v; __syncthreads();
    for (int o = 128; o > 0; o >>= 1) {
        if (t < o) red[t] += red[t + o];
        __syncthreads();
    }
    float r = red[0]; __syncthreads();
    return r;
}

__global__ void build_tables(const float* __restrict__ rel,
                             __half* __restrict__ tabf, __half* __restrict__ tTf)
{
    int i = blockIdx.x * 256 + threadIdx.x;
    if (i >= 160 * 64) return;
    int j = i / 64, d = i % 64;
    float v = (j < NREL) ? rel[((size_t)128 * S + (64 + j)) * DH + d] : 0.f;
    __half h = __float2half_rn(v);
    tabf[j * 64 + d] = h;
    if (j < NRELP) tTf[d * NRELP + j] = h;
}

__global__ __launch_bounds__(256) void conv_f16(
    const float* __restrict__ in, __half* __restrict__ o, int n4)
{
    int i = blockIdx.x * 256 + threadIdx.x;
    if (i >= n4) return;
    float4 v = ((const float4*)in)[i];
    __half2* op = (__half2*)o;
    op[i * 2 + 0] = __floats2half2_rn(v.x, v.y);
    op[i * 2 + 1] = __floats2half2_rn(v.z, v.w);
}

// ---------------- mma primitives ----------------
__device__ __forceinline__ void mma16816h(float* d, const uint32_t* a, const uint32_t* b) {
    asm volatile(
        "mma.sync.aligned.m16n8k16.row.col.f32.f16.f16.f32 "
        "{%0,%1,%2,%3}, {%4,%5,%6,%7}, {%8,%9}, {%0,%1,%2,%3};\n"
        : "+f"(d[0]), "+f"(d[1]), "+f"(d[2]), "+f"(d[3])
        : "r"(a[0]), "r"(a[1]), "r"(a[2]), "r"(a[3]), "r"(b[0]), "r"(b[1]));
}
__device__ __forceinline__ void ldsm4(uint32_t* r, uint32_t addr) {
    asm volatile("ldmatrix.sync.aligned.m8n8.x4.shared.b16 {%0,%1,%2,%3}, [%4];\n"
        : "=r"(r[0]), "=r"(r[1]), "=r"(r[2]), "=r"(r[3]) : "r"(addr));
}
__device__ __forceinline__ void ldsm4t(uint32_t* r, uint32_t addr) {
    asm volatile("ldmatrix.sync.aligned.m8n8.x4.trans.shared.b16 {%0,%1,%2,%3}, [%4];\n"
        : "=r"(r[0]), "=r"(r[1]), "=r"(r[2]), "=r"(r[3]) : "r"(addr));
}
__device__ __forceinline__ void cp16(uint32_t dst, const void* src) {
    asm volatile("cp.async.cg.shared.global [%0], [%1], 16;\n" :: "r"(dst), "l"(src));
}
__device__ __forceinline__ void cp_commit() { asm volatile("cp.async.commit_group;\n"); }
__device__ __forceinline__ void cp_wait1() { asm volatile("cp.async.wait_group 1;\n" ::: "memory"); }
__device__ __forceinline__ void cp_wait0() { asm volatile("cp.async.wait_group 0;\n" ::: "memory"); }
__device__ __forceinline__ uint32_t smem_u32(const void* p) {
    return (uint32_t)__cvta_generic_to_shared(p);
}

// ======================================================================
// fp16 single-term pipelined MMA GEMM NT (unchanged from R9)
// ======================================================================
constexpr int FSTR = 40;
constexpr int FARR = 128 * FSTR * 2;
constexpr int FSTG = 2 * FARR;
constexpr int FNSTG = 3;
constexpr int F_SMEM = FNSTG * FSTG;      // 61440

struct F16Targets {
    const __half* w[3];
    const float* bias[3];
    const float* res[3];
    float* c[3];
    __half* cf[3];
};

__global__ __launch_bounds__(256, 2) void gemm_f16_pipe(
    const __half* __restrict__ A, F16Targets tg, int M, int N, int K, int act)
{
    extern __shared__ __align__(16) char dsm[];
    const uint32_t sbase = smem_u32(dsm);
    const int z = blockIdx.z;
    const __half* W = tg.w[z];

    const int bm = blockIdx.y * 128, bn = blockIdx.x * 128;
    const int t = threadIdx.x, lane = t & 31, w = t >> 5;
    const int wm = (w & 1) * 64, wn = (w >> 1) * 32;

    float acc[4][4][4];
    #pragma unroll
    for (int i = 0; i < 4; i++)
        #pragma unroll
        for (int j = 0; j < 4; j++)
            #pragma unroll
            for (int r = 0; r < 4; r++) acc[i][j][r] = 0.f;

    uint32_t aoff[4], boff[2];
    #pragma unroll
    for (int mi = 0; mi < 4; mi++)
        aoff[mi] = (uint32_t)(((wm + mi * 16 + (lane & 15)) * FSTR + ((lane >> 4) << 3)) * 2);
    #pragma unroll
    for (int ni2 = 0; ni2 < 2; ni2++)
        boff[ni2] = (uint32_t)(((wn + ni2 * 16 + (lane & 7) + ((lane >> 4) << 3)) * FSTR
                               + (((lane >> 3) & 1) << 3)) * 2);

    const int nk = K / 32;
    const int r0 = t >> 2, c0 = t & 3;
    const int r1 = (t + 256) >> 2, c1 = (t + 256) & 3;
    const uint32_t d0 = (uint32_t)((r0 * FSTR + c0 * 8) * 2);
    const uint32_t d1 = (uint32_t)((r1 * FSTR + c1 * 8) * 2);

    auto issue = [&](int c) {
        if (c < nk) {
            const uint32_t base = sbase + (c % FNSTG) * FSTG;
            const size_t k0 = (size_t)c * 32;
            cp16(base + d0,        A + (size_t)(bm + r0) * K + k0 + c0 * 8);
            cp16(base + d1,        A + (size_t)(bm + r1) * K + k0 + c1 * 8);
            cp16(base + FARR + d0, W + (size_t)(bn + r0) * K + k0 + c0 * 8);
            cp16(base + FARR + d1, W + (size_t)(bn + r1) * K + k0 + c1 * 8);
        }
        cp_commit();
    };
    issue(0);
    issue(1);

    for (int kt = 0; kt < nk; kt++) {
        cp_wait1();
        __syncthreads();
        issue(kt + 2);

        const uint32_t sb = sbase + (kt % FNSTG) * FSTG;
        #pragma unroll
        for (int kk2 = 0; kk2 < 2; kk2++) {
            const uint32_t ko = kk2 * 32;
            uint32_t ah[4][4], bh[4][2];
            #pragma unroll
            for (int mi = 0; mi < 4; mi++)
                ldsm4(ah[mi], sb + aoff[mi] + ko);
            #pragma unroll
            for (int ni2 = 0; ni2 < 2; ni2++) {
                uint32_t t4[4];
                ldsm4(t4, sb + FARR + boff[ni2] + ko);
                bh[ni2 * 2][0] = t4[0]; bh[ni2 * 2][1] = t4[1];
                bh[ni2 * 2 + 1][0] = t4[2]; bh[ni2 * 2 + 1][1] = t4[3];
            }
            #pragma unroll
            for (int mi = 0; mi < 4; mi++)
                #pragma unroll
                for (int ni = 0; ni < 4; ni++)
                    mma16816h(acc[mi][ni], ah[mi], bh[ni]);
        }
        __syncthreads();
    }

    const float* bias = tg.bias[z];
    const float* res  = tg.res[z];
    float* Cp = tg.c[z];
    __half* Cf = tg.cf[z];

    #pragma unroll
    for (int mi = 0; mi < 4; mi++) {
        int m0 = bm + wm + mi * 16 + (lane >> 2);
        #pragma unroll
        for (int ni = 0; ni < 4; ni++) {
            int n = bn + wn + ni * 8 + (lane & 3) * 2;
            float2 v0 = make_float2(acc[mi][ni][0], acc[mi][ni][1]);
            float2 v1 = make_float2(acc[mi][ni][2], acc[mi][ni][3]);
            if (bias) {
                float2 bv = *(const float2*)&bias[n];
                v0.x += bv.x; v0.y += bv.y; v1.x += bv.x; v1.y += bv.y;
            }
            if (res) {
                float2 rr0 = *(const float2*)&res[(size_t)m0 * N + n];
                float2 rr1 = *(const float2*)&res[(size_t)(m0 + 8) * N + n];
                v0.x += rr0.x; v0.y += rr0.y; v1.x += rr1.x; v1.y += rr1.y;
            }
            if (act == 1) {
                v0.x = 0.5f * v0.x * (1.f + erff(v0.x * 0.70710678118654752f));
                v0.y = 0.5f * v0.y * (1.f + erff(v0.y * 0.70710678118654752f));
                v1.x = 0.5f * v1.x * (1.f + erff(v1.x * 0.70710678118654752f));
                v1.y = 0.5f * v1.y * (1.f + erff(v1.y * 0.70710678118654752f));
            }
            if (Cp) {
                *(float2*)&Cp[(size_t)m0 * N + n] = v0;
                *(float2*)&Cp[(size_t)(m0 + 8) * N + n] = v1;
            }
            if (Cf) {
                *(__half2*)&Cf[(size_t)m0 * N + n] = __floats2half2_rn(v0.x, v0.y);
                *(__half2*)&Cf[(size_t)(m0 + 8) * N + n] = __floats2half2_rn(v1.x, v1.y);
            }
        }
    }
}

// ======================================================================
// qtab fp16: qtab[m, j] = Q[m,:]·table[j,:]; tile 128 x 160
// ======================================================================
constexpr int QT_STR = 72;
constexpr int QT_A = 128 * QT_STR * 2;
constexpr int QT_B = 160 * QT_STR * 2;
constexpr int QT_SMEM = QT_A + QT_B;      // 41472

__global__ __launch_bounds__(256) void qtab_f16(
    const __half* __restrict__ Qf, const __half* __restrict__ Tf,
    float* __restrict__ qt)
{
    extern __shared__ __align__(16) char dsm[];
    __half* sA = (__half*)dsm;
    __half* sB = (__half*)(dsm + QT_A);
    const uint32_t bA = smem_u32(sA), bB = smem_u32(sB);

    const int bm = blockIdx.x * 128;
    const int t = threadIdx.x, lane = t & 31, w = t >> 5;
    const int wm = (w & 3) * 32, wn = (w >> 2) * 80;

    #pragma unroll
    for (int i = 0; i < 4; i++) {
        int s = t + i * 256;
        int row = s >> 3, c8 = s & 7;
        *(uint4*)&sA[row * QT_STR + c8 * 8] = *(const uint4*)&Qf[(size_t)(bm + row) * 64 + c8 * 8];
    }
    #pragma unroll
    for (int i = 0; i < 5; i++) {
        int s = t + i * 256;
        int row = s >> 3, c8 = s & 7;
        *(uint4*)&sB[row * QT_STR + c8 * 8] = *(const uint4*)&Tf[row * 64 + c8 * 8];
    }
    __syncthreads();

    float acc[2][10][4];
    #pragma unroll
    for (int i = 0; i < 2; i++)
        #pragma unroll
        for (int j = 0; j < 10; j++)
            #pragma unroll
            for (int r = 0; r < 4; r++) acc[i][j][r] = 0.f;

    uint32_t aoff[2], boff[5];
    #pragma unroll
    for (int mi = 0; mi < 2; mi++)
        aoff[mi] = (uint32_t)(((wm + mi * 16 + (lane & 15)) * QT_STR + ((lane >> 4) << 3)) * 2);
    #pragma unroll
    for (int ni2 = 0; ni2 < 5; ni2++)
        boff[ni2] = (uint32_t)(((wn + ni2 * 16 + (lane & 7) + ((lane >> 4) << 3)) * QT_STR
                               + (((lane >> 3) & 1) << 3)) * 2);

    #pragma unroll
    for (int kc = 0; kc < 4; kc++) {
        uint32_t ko = kc * 32;
        uint32_t ah[2][4];
        #pragma unroll
        for (int mi = 0; mi < 2; mi++)
            ldsm4(ah[mi], bA + aoff[mi] + ko);
        #pragma unroll
        for (int ni2 = 0; ni2 < 5; ni2++) {
            uint32_t t4[4];
            ldsm4(t4, bB + boff[ni2] + ko);
            uint32_t b0[2] = {t4[0], t4[1]}, b1[2] = {t4[2], t4[3]};
            #pragma unroll
            for (int mi = 0; mi < 2; mi++) {
                mma16816h(acc[mi][ni2 * 2], ah[mi], b0);
                mma16816h(acc[mi][ni2 * 2 + 1], ah[mi], b1);
            }
        }
    }

    #pragma unroll
    for (int mi = 0; mi < 2; mi++)
        #pragma unroll
        for (int rr = 0; rr < 2; rr++) {
            int m0 = bm + wm + mi * 16 + (lane >> 2) + rr * 8;
            #pragma unroll
            for (int ni = 0; ni < 10; ni++) {
                int n = wn + ni * 8 + (lane & 3) * 2;
                if (n < NREL)     qt[(size_t)m0 * NREL + n]     = acc[mi][ni][rr * 2 + 0];
                if (n + 1 < NREL) qt[(size_t)m0 * NREL + n + 1] = acc[mi][ni][rr * 2 + 1];
            }
        }
}

// ======================================================================
// ctx_rel fp16: ctx[m, d] = ptab[m,:]·tabT[d,:], K=144
// ======================================================================
constexpr int CR_ASTR = 56;
constexpr int CR_BSTR = 152;
constexpr int CR_A = 128 * CR_ASTR * 2;   // 14336
constexpr int CR_B = 64 * CR_BSTR * 2;    // 19456
constexpr int CR_SMEM = CR_A + CR_B;      // 33792

__global__ __launch_bounds__(256) void ctx_rel_f16(
    const __half* __restrict__ Pf, const __half* __restrict__ Tf,
    float* __restrict__ ctx)
{
    extern __shared__ __align__(16) char dsm[];
    __half* sA = (__half*)dsm;
    __half* sB = (__half*)(dsm + CR_A);
    const uint32_t bA = smem_u32(sA), bB = smem_u32(sB);

    const int bm = blockIdx.x * 128;
    const int t = threadIdx.x, lane = t & 31, w = t >> 5;
    const int wm = (w & 3) * 32, wn = (w >> 2) * 32;

    for (int s = t; s < 1152; s += 256) {
        int row = s / 18, c8 = s % 18;
        *(uint4*)&sB[row * CR_BSTR + c8 * 8] = *(const uint4*)&Tf[row * NRELP + c8 * 8];
    }

    float acc[2][4][4];
    #pragma unroll
    for (int i = 0; i < 2; i++)
        #pragma unroll
        for (int j = 0; j < 4; j++)
            #pragma unroll
            for (int r = 0; r < 4; r++) acc[i][j][r] = 0.f;

    uint32_t aoff[2], boff[2];
    #pragma unroll
    for (int mi = 0; mi < 2; mi++)
        aoff[mi] = (uint32_t)(((wm + mi * 16 + (lane & 15)) * CR_ASTR + ((lane >> 4) << 3)) * 2);
    #pragma unroll
    for (int ni2 = 0; ni2 < 2; ni2++)
        boff[ni2] = (uint32_t)(((wn + ni2 * 16 + (lane & 7) + ((lane >> 4) << 3)) * CR_BSTR
                               + (((lane >> 3) & 1) << 3)) * 2);

    for (int c = 0; c < 3; c++) {
        __syncthreads();
        #pragma unroll
        for (int i = 0; i < 3; i++) {
            int s = t + i * 256;
            int row = s / 6, c8 = s % 6;
            size_t src = (size_t)(bm + row) * NRELP + c * 48 + c8 * 8;
            *(uint4*)&sA[row * CR_ASTR + c8 * 8] = *(const uint4*)&Pf[src];
        }
        __syncthreads();
        #pragma unroll
        for (int kc = 0; kc < 3; kc++) {
            uint32_t kaoff = kc * 32;
            uint32_t kboff = (uint32_t)(c * 96 + kc * 32);
            uint32_t ah[2][4];
            #pragma unroll
            for (int mi = 0; mi < 2; mi++)
                ldsm4(ah[mi], bA + aoff[mi] + kaoff);
            #pragma unroll
            for (int ni2 = 0; ni2 < 2; ni2++) {
                uint32_t t4[4];
                ldsm4(t4, bB + boff[ni2] + kboff);
                uint32_t b0[2] = {t4[0], t4[1]}, b1[2] = {t4[2], t4[3]};
                #pragma unroll
                for (int mi = 0; mi < 2; mi++) {
                    mma16816h(acc[mi][ni2 * 2], ah[mi], b0);
                    mma16816h(acc[mi][ni2 * 2 + 1], ah[mi], b1);
                }
            }
        }
    }

    #pragma unroll
    for (int mi = 0; mi < 2; mi++)
        #pragma unroll
        for (int rr = 0; rr < 2; rr++) {
            int m0 = bm + wm + mi * 16 + (lane >> 2) + rr * 8;
            #pragma unroll
            for (int ni = 0; ni < 4; ni++) {
                int n = wn + ni * 8 + (lane & 3) * 2;
                float2 v = make_float2(acc[mi][ni][rr * 2 + 0], acc[mi][ni][rr * 2 + 1]);
                *(float2*)&ctx[(size_t)m0 * 64 + n] = v;
            }
        }
}

// ======================================================================
// Scores fp16: 128x128 q,k tile; K=64, cp.async double buffer
// ======================================================================
constexpr int QSTR = 40;
constexpr int SC_ARR = 128 * QSTR * 2;    // 10240
constexpr int SC_STG = 2 * SC_ARR;        // 20480
constexpr int SC_SMEM = 2 * SC_STG;       // 40960

__global__ __launch_bounds__(256) void scores_f16(
    const __half* __restrict__ Qf, const __half* __restrict__ Kf,
    const float* __restrict__ qtab, const int* __restrict__ mask,
    float* __restrict__ scores)
{
    extern __shared__ __align__(16) char dsm[];
    const uint32_t sbase = smem_u32(dsm);
    const int bh = blockIdx.z, b = bh / H, h = bh % H;
    const int q0 = blockIdx.y * 128, k0b = blockIdx.x * 128;
    const int t = threadIdx.x, lane = t & 31, w = t >> 5;
    const int wm = (w & 1) * 64, wn = (w >> 1) * 32;

    float acc[4][4][4];
    #pragma unroll
    for (int i = 0; i < 4; i++)
        #pragma unroll
        for (int j = 0; j < 4; j++)
            #pragma unroll
            for (int r = 0; r < 4; r++) acc[i][j][r] = 0.f;

    uint32_t aoff[4], boff[2];
    #pragma unroll
    for (int mi = 0; mi < 4; mi++)
        aoff[mi] = (uint32_t)(((wm + mi * 16 + (lane & 15)) * QSTR + ((lane >> 4) << 3)) * 2);
    #pragma unroll
    for (int ni2 = 0; ni2 < 2; ni2++)
        boff[ni2] = (uint32_t)(((wn + ni2 * 16 + (lane & 7) + ((lane >> 4) << 3)) * QSTR
                               + (((lane >> 3) & 1) << 3)) * 2);

    auto issue = [&](int kt) {
        uint32_t base = sbase + kt * SC_STG;
        #pragma unroll
        for (int i = 0; i < 2; i++) {
            int idx = t * 2 + i;
            int row = idx >> 2, cseg = (idx & 3) * 8;
            size_t qsrc = ((size_t)(b * S) + q0 + row) * D + h * DH + kt * 32 + cseg;
            size_t ksrc = ((size_t)(b * S) + k0b + row) * D + h * DH + kt * 32 + cseg;
            uint32_t d = base + (uint32_t)((row * QSTR + cseg) * 2);
            cp16(d,          Qf + qsrc);
            cp16(d + SC_ARR, Kf + ksrc);
        }
        cp_commit();
    };
    issue(0);
    issue(1);

    for (int kt = 0; kt < 2; kt++) {
        if (kt == 0) cp_wait1(); else cp_wait0();
        __syncthreads();
        const uint32_t sb = sbase + kt * SC_STG;
        #pragma unroll
        for (int kk2 = 0; kk2 < 2; kk2++) {
            uint32_t koffb = kk2 * 32;
            uint32_t ah[4][4], bh2[4][2];
            #pragma unroll
            for (int mi = 0; mi < 4; mi++)
                ldsm4(ah[mi], sb + aoff[mi] + koffb);
            #pragma unroll
            for (int ni2 = 0; ni2 < 2; ni2++) {
                uint32_t t4[4];
                ldsm4(t4, sb + SC_ARR + boff[ni2] + koffb);
                bh2[ni2 * 2][0] = t4[0]; bh2[ni2 * 2][1] = t4[1];
                bh2[ni2 * 2 + 1][0] = t4[2]; bh2[ni2 * 2 + 1][1] = t4[3];
            }
            #pragma unroll
            for (int mi = 0; mi < 4; mi++)
                #pragma unroll
                for (int ni = 0; ni < 4; ni++)
                    mma16816h(acc[mi][ni], ah[mi], bh2[ni]);
        }
    }

    #pragma unroll
    for (int mi = 0; mi < 4; mi++) {
        #pragma unroll
        for (int rr = 0; rr < 2; rr++) {
            int q = q0 + wm + mi * 16 + (lane >> 2) + rr * 8;
            const float* qtr = qtab + (((size_t)b * S + q) * H + h) * NREL;
            size_t rowb = ((size_t)bh * S + q) * S;
            #pragma unroll
            for (int ni = 0; ni < 4; ni++) {
                int k = k0b + wn + ni * 8 + (lane & 3) * 2;
                float vx = acc[mi][ni][rr * 2 + 0];
                float vy = acc[mi][ni][rr * 2 + 1];
                int r0 = k - q; r0 = r0 < -64 ? -64 : (r0 > 64 ? 64 : r0);
                int r1 = k + 1 - q; r1 = r1 < -64 ? -64 : (r1 > 64 ? 64 : r1);
                float mb0 = (1.f - (float)mask[b * S + k]) * -10000.f;
                float mb1 = (1.f - (float)mask[b * S + k + 1]) * -10000.f;
                float2 o;
                o.x = (vx + qtr[r0 + 64]) * SCALE + mb0;
                o.y = (vy + qtr[r1 + 64]) * SCALE + mb1;
                *(float2*)&scores[rowb + k] = o;
            }
        }
    }
}

// ======================================================================
// ctx_pv fp16: (probs@V + ctx_rel) -> fp16 out; cp.async 3-stage
// ======================================================================
constexpr int VSTR = 72;
constexpr int PV_P = 128 * QSTR * 2;      // 10240
constexpr int PV_V = 32 * VSTR * 2;       // 4608
constexpr int PV_STG = PV_P + PV_V;       // 14848
constexpr int PV_NSTG = 3;
constexpr int PV_SMEM = PV_NSTG * PV_STG; // 44544

__global__ __launch_bounds__(256) void ctx_pv_f16(
    const __half* __restrict__ Pf, const __half* __restrict__ Vf,
    const float* __restrict__ ctxin, __half* __restrict__ outf)
{
    extern __shared__ __align__(16) char dsm[];
    const uint32_t sbase = smem_u32(dsm);
    const int bh = blockIdx.z, b = bh / H, h = bh % H;
    const int q0 = blockIdx.x * 128;
    const int t = threadIdx.x, lane = t & 31, w = t >> 5;
    const int wm = (w & 3) * 32, wn = (w >> 2) * 32;

    float acc[2][4][4];
    #pragma unroll
    for (int i = 0; i < 2; i++)
        #pragma unroll
        for (int j = 0; j < 4; j++)
            #pragma unroll
            for (int r = 0; r < 4; r++) acc[i][j][r] = 0.f;

    uint32_t aoff[2];
    #pragma unroll
    for (int mi = 0; mi < 2; mi++)
        aoff[mi] = (uint32_t)(((wm + mi * 16 + (lane & 15)) * QSTR + ((lane >> 4) << 3)) * 2);

    const int nk = S / 32;

    auto issue = [&](int kt, int slot) {
        if (kt < nk) {
            uint32_t base = sbase + slot * PV_STG;
            #pragma unroll
            for (int i = 0; i < 2; i++) {
                int idx = t * 2 + i;
                int row = idx >> 2, cseg = (idx & 3) * 8;
                size_t psrc = ((size_t)bh * S + q0 + row) * S + kt * 32 + cseg;
                cp16(base + (uint32_t)((row * QSTR + cseg) * 2), Pf + psrc);
            }
            {
                int row = t >> 3, cseg = (t & 7) * 8;
                size_t vsrc = ((size_t)(b * S) + kt * 32 + row) * D + h * DH + cseg;
                cp16(base + PV_P + (uint32_t)((row * VSTR + cseg) * 2), Vf + vsrc);
            }
        }
        cp_commit();
    };
    issue(0, 0);
    issue(1, 1);

    for (int kt = 0; kt < nk; kt++) {
        cp_wait1();
        __syncthreads();
        issue(kt + 2, (kt + 2) % PV_NSTG);

        const uint32_t sb = sbase + (kt % PV_NSTG) * PV_STG;
        #pragma unroll
        for (int kk2 = 0; kk2 < 2; kk2++) {
            uint32_t koffb = kk2 * 32;
            uint32_t ah[2][4], bh2[4][2];
            #pragma unroll
            for (int mi = 0; mi < 2; mi++)
                ldsm4(ah[mi], sb + aoff[mi] + koffb);
            #pragma unroll
            for (int ni2 = 0; ni2 < 2; ni2++) {
                uint32_t vaddr = (uint32_t)(((kk2 * 16 + (lane & 15)) * VSTR
                                 + wn + ni2 * 16 + (lane >> 4) * 8) * 2);
                uint32_t t4[4];
                ldsm4t(t4, sb + PV_P + vaddr);
                bh2[ni2 * 2][0] = t4[0]; bh2[ni2 * 2][1] = t4[1];
                bh2[ni2 * 2 + 1][0] = t4[2]; bh2[ni2 * 2 + 1][1] = t4[3];
            }
            #pragma unroll
            for (int mi = 0; mi < 2; mi++)
                #pragma unroll
                for (int ni = 0; ni < 4; ni++)
                    mma16816h(acc[mi][ni], ah[mi], bh2[ni]);
        }
        __syncthreads();
    }

    #pragma unroll
    for (int mi = 0; mi < 2; mi++) {
        #pragma unroll
        for (int rr = 0; rr < 2; rr++) {
            int q = q0 + wm + mi * 16 + (lane >> 2) + rr * 8;
            size_t rb = ((size_t)(b * S) + q) * D + h * DH;
            #pragma unroll
            for (int ni = 0; ni < 4; ni++) {
                int d = wn + ni * 8 + (lane & 3) * 2;
                float2 cur = *(const float2*)&ctxin[rb + d];
                cur.x += acc[mi][ni][rr * 2 + 0];
                cur.y += acc[mi][ni][rr * 2 + 1];
                *(__half2*)&outf[rb + d] = __floats2half2_rn(cur.x, cur.y);
            }
        }
    }
}

// ---------------- embedding + LN ----------------
__global__ __launch_bounds__(256) void embed_ln(
    const int* __restrict__ ids, const int* __restrict__ tti,
    const float* __restrict__ we, const float* __restrict__ te,
    const float* __restrict__ w, const float* __restrict__ bb,
    float* __restrict__ out, __half* __restrict__ of)
{
    __shared__ float red[256];
    int m = blockIdx.x, t = threadIdx.x;
    int id = ids[m], t2 = tti[m];
    const float* wr = we + (size_t)id * D;
    const float* tr = te + (size_t)t2 * D;
    float vals[3]; float s = 0.f;
    #pragma unroll
    for (int i = 0; i < 3; i++) { int d = t + i * 256; vals[i] = wr[d] + tr[d]; s += vals[i]; }
    float mean = block_reduce_sum(s, red) * (1.f / D);
    float vs = 0.f;
    #pragma unroll
    for (int i = 0; i < 3; i++) { float dd = vals[i] - mean; vs += dd * dd; }
    float var = block_reduce_sum(vs, red) * (1.f / D);
    float rstd = rsqrtf(var + LN_EPS);
    #pragma unroll
    for (int i = 0; i < 3; i++) {
        int d = t + i * 256;
        float v = (vals[i] - mean) * rstd * w[d] + bb[d];
        out[(size_t)m * D + d] = v;
        of[(size_t)m * D + d] = __float2half_rn(v);
    }
}

__global__ __launch_bounds__(256) void ln_kernel(
    const float* __restrict__ x, const float* __restrict__ w,
    const float* __restrict__ bb, float* __restrict__ out,
    __half* __restrict__ of)
{
    __shared__ float red[256];
    int m = blockIdx.x, t = threadIdx.x;
    const float* xr = x + (size_t)m * D;
    float vals[3]; float s = 0.f;
    #pragma unroll
    for (int i = 0; i < 3; i++) { vals[i] = xr[t + i * 256]; s += vals[i]; }
    float mean = block_reduce_sum(s, red) * (1.f / D);
    float vs = 0.f;
    #pragma unroll
    for (int i = 0; i < 3; i++) { float dd = vals[i] - mean; vs += dd * dd; }
    float var = block_reduce_sum(vs, red) * (1.f / D);
    float rstd = rsqrtf(var + LN_EPS);
    #pragma unroll
    for (int i = 0; i < 3; i++) {
        int d = t + i * 256;
        float v = (vals[i] - mean) * rstd * w[d] + bb[d];
        out[(size_t)m * D + d] = v;
        of[(size_t)m * D + d] = __float2half_rn(v);
    }
}

// ---------------- warp-per-row softmax -> fp16 probs + fp16 padded ptab ----------------
__global__ __launch_bounds__(256) void softmax_warp(
    const float* __restrict__ scores,
    __half* __restrict__ pf, __half* __restrict__ ptf)
{
    __shared__ float srow[8][512];
    const int w = threadIdx.x >> 5, lane = threadIdx.x & 31;
    const int row = blockIdx.x * 8 + w;
    const int q = row % S, bh = row / S;
    const int b = bh / H, h = bh % H;
    const float* sr = scores + (size_t)row * S;

    float2 v[8];
    float m = -1e30f;
    #pragma unroll
    for (int i = 0; i < 8; i++) {
        v[i] = *(const float2*)&sr[lane * 2 + 64 * i];
        m = fmaxf(m, fmaxf(v[i].x, v[i].y));
    }
    #pragma unroll
    for (int o = 16; o > 0; o >>= 1) m = fmaxf(m, __shfl_xor_sync(0xffffffffu, m, o));

    float s = 0.f;
    #pragma unroll
    for (int i = 0; i < 8; i++) {
        v[i].x = expf(v[i].x - m); v[i].y = expf(v[i].y - m);
        s += v[i].x + v[i].y;
    }
    #pragma unroll
    for (int o = 16; o > 0; o >>= 1) s += __shfl_xor_sync(0xffffffffu, s, o);
    float inv = 1.f / s;

    size_t rb = (size_t)row * S;
    float left = 0.f, right = 0.f;
    #pragma unroll
    for (int i = 0; i < 8; i++) {
        int k = lane * 2 + 64 * i;
        float p0 = v[i].x * inv, p1 = v[i].y * inv;
        srow[w][k] = p0; srow[w][k + 1] = p1;
        *(__half2*)&pf[rb + k] = __floats2half2_rn(p0, p1);
        if (k <= q - 64)     left += p0;
        if (k + 1 <= q - 64) left += p1;
        if (k >= q + 64)     right += p0;
        if (k + 1 >= q + 64) right += p1;
    }
    #pragma unroll
    for (int o = 16; o > 0; o >>= 1) {
        left  += __shfl_xor_sync(0xffffffffu, left, o);
        right += __shfl_xor_sync(0xffffffffu, right, o);
    }
    __syncwarp();

    size_t pbase = ((size_t)(b * S + q) * H + h) * NRELP;
    if (lane == 0) {
        ptf[pbase]       = __float2half_rn(left);
        ptf[pbase + 128] = __float2half_rn(right);
    }
    if (lane < 15) ptf[pbase + 129 + lane] = __float2half_rn(0.f);
    #pragma unroll
    for (int jj = 0; jj < 4; jj++) {
        int j = 1 + lane + 32 * jj;
        if (j <= 127) {
            int k = q + j - 64;
            float p = (k >= 0 && k < S) ? srow[w][k] : 0.f;
            ptf[pbase + j] = __float2half_rn(p);
        }
    }
}

// ---------------- launch ----------------
extern "C" void kernel_launch(void* const* d_in, const int* in_sizes, int n_in,
                              void* d_out, int out_size)
{
    const int*   ids     = (const int*)d_in[0];
    const int*   amask   = (const int*)d_in[1];
    const int*   tti     = (const int*)d_in[2];
    const float* wemb    = (const float*)d_in[3];
    const float* temb    = (const float*)d_in[4];
    const float* elnw    = (const float*)d_in[5];
    const float* elnb    = (const float*)d_in[6];
    const float* qw      = (const float*)d_in[7];
    const float* qb      = (const float*)d_in[8];
    const float* kw      = (const float*)d_in[9];
    const float* kb      = (const float*)d_in[10];
    const float* vw      = (const float*)d_in[11];
    const float* vb      = (const float*)d_in[12];
    const float* rel     = (const float*)d_in[13];
    const float* ow      = (const float*)d_in[14];
    const float* ob      = (const float*)d_in[15];
    const float* alnw    = (const float*)d_in[16];
    const float* alnb    = (const float*)d_in[17];
    const float* iw      = (const float*)d_in[18];
    const float* ib      = (const float*)d_in[19];
    const float* dw      = (const float*)d_in[20];
    const float* db      = (const float*)d_in[21];
    const float* olnw    = (const float*)d_in[22];
    const float* olnb    = (const float*)d_in[23];
    float* out = (float*)d_out;

    float *x, *sc, *qt, *ctx, *tmp, *attn;
    cudaGetSymbolAddress((void**)&x,    g_x);
    cudaGetSymbolAddress((void**)&sc,   g_scores);
    cudaGetSymbolAddress((void**)&qt,   g_qtab);
    cudaGetSymbolAddress((void**)&ctx,  g_ctx);
    cudaGetSymbolAddress((void**)&tmp,  g_tmp);
    cudaGetSymbolAddress((void**)&attn, g_attn);

    __half *wqf, *wkf, *wvf, *wof, *wif, *wdf, *xf, *ctxf, *attnf, *fff;
    __half *qf, *kf, *vf, *pf, *ptf, *tabf, *tTf;
    cudaGetSymbolAddress((void**)&wqf, g_wqf);
    cudaGetSymbolAddress((void**)&wkf, g_wkf);
    cudaGetSymbolAddress((void**)&wvf, g_wvf);
    cudaGetSymbolAddress((void**)&wof, g_wof);
    cudaGetSymbolAddress((void**)&wif, g_wif);
    cudaGetSymbolAddress((void**)&wdf, g_wdf);
    cudaGetSymbolAddress((void**)&xf,   g_xf);
    cudaGetSymbolAddress((void**)&ctxf, g_ctxf);
    cudaGetSymbolAddress((void**)&attnf, g_attnf);
    cudaGetSymbolAddress((void**)&fff,  g_fff);
    cudaGetSymbolAddress((void**)&qf,  g_qf);
    cudaGetSymbolAddress((void**)&kf,  g_kf);
    cudaGetSymbolAddress((void**)&vf,  g_vf);
    cudaGetSymbolAddress((void**)&pf,  g_pf);
    cudaGetSymbolAddress((void**)&ptf, g_ptf);
    cudaGetSymbolAddress((void**)&tabf, g_tabf);
    cudaGetSymbolAddress((void**)&tTf,  g_tTf);

    cudaFuncSetAttribute(gemm_f16_pipe, cudaFuncAttributeMaxDynamicSharedMemorySize, F_SMEM);
    cudaFuncSetAttribute(qtab_f16, cudaFuncAttributeMaxDynamicSharedMemorySize, QT_SMEM);
    cudaFuncSetAttribute(ctx_rel_f16, cudaFuncAttributeMaxDynamicSharedMemorySize, CR_SMEM);
    cudaFuncSetAttribute(scores_f16, cudaFuncAttributeMaxDynamicSharedMemorySize, SC_SMEM);
    cudaFuncSetAttribute(ctx_pv_f16, cudaFuncAttributeMaxDynamicSharedMemorySize, PV_SMEM);

    build_tables<<<(160 * 64 + 255) / 256, 256>>>(rel, tabf, tTf);
    embed_ln<<<(int)BS, 256>>>(ids, tti, wemb, temb, elnw, elnb, x, xf);

    {
        int n4 = (int)(WSZ / 4), g = (n4 + 255) / 256;
        conv_f16<<<g, 256>>>(qw, wqf, n4);
        conv_f16<<<g, 256>>>(kw, wkf, n4);
        conv_f16<<<g, 256>>>(vw, wvf, n4);
        conv_f16<<<g, 256>>>(ow, wof, n4);
        int n4f = (int)(WFF / 4), gf = (n4f + 255) / 256;
        conv_f16<<<gf, 256>>>(iw, wif, n4f);
        conv_f16<<<gf, 256>>>(dw, wdf, n4f);
    }

    const dim3 gQKV(D / 128, (int)(BS / 128), 3);
    const dim3 gP(D / 128, (int)(BS / 128), 1);
    const dim3 gF1(FF / 128, (int)(BS / 128), 1);
    const dim3 gSC(S / 128, S / 128, B * H);
    const dim3 gPV(S / 128, 1, B * H);
    const int gRow = (int)(BS * H / 128);

    for (int l = 0; l < L; l++) {
        const size_t wo = (size_t)l * D * D;
        const size_t fo = (size_t)l * FF * D;

        F16Targets tq = {};
        tq.w[0] = wqf + wo; tq.bias[0] = qb + l * D; tq.cf[0] = qf;
        tq.w[1] = wkf + wo; tq.bias[1] = kb + l * D; tq.cf[1] = kf;
        tq.w[2] = wvf + wo; tq.bias[2] = vb + l * D; tq.cf[2] = vf;
        gemm_f16_pipe<<<gQKV, 256, F_SMEM>>>(xf, tq, (int)BS, D, D, 0);

        qtab_f16<<<gRow, 256, QT_SMEM>>>(qf, tabf, qt);

        scores_f16<<<gSC, 256, SC_SMEM>>>(qf, kf, qt, amask, sc);
        softmax_warp<<<(int)(BHS / 8), 256>>>(sc, pf, ptf);

        ctx_rel_f16<<<gRow, 256, CR_SMEM>>>(ptf, tTf, ctx);
        ctx_pv_f16<<<gPV, 256, PV_SMEM>>>(pf, vf, ctx, ctxf);

        F16Targets to = {};
        to.w[0] = wof + wo; to.bias[0] = ob + l * D; to.res[0] = x; to.c[0] = tmp;
        gemm_f16_pipe<<<gP, 256, F_SMEM>>>(ctxf, to, (int)BS, D, D, 0);
        ln_kernel<<<(int)BS, 256>>>(tmp, alnw + l * D, alnb + l * D, attn, attnf);

        F16Targets tf = {};
        tf.w[0] = wif + fo; tf.bias[0] = ib + l * FF; tf.cf[0] = fff;
        gemm_f16_pipe<<<gF1, 256, F_SMEM>>>(attnf, tf, (int)BS, FF, D, 1);

        F16Targets td = {};
        td.w[0] = wdf + fo; td.bias[0] = db + l * D; td.res[0] = attn; td.c[0] = tmp;
        gemm_f16_pipe<<<gP, 256, F_SMEM>>>(fff, td, (int)BS, D, FF, 0);
        ln_kernel<<<(int)BS, 256>>>(tmp, olnw + l * D, olnb + l * D,
                                    (l == L - 1) ? out : x, xf);
    }
}